// round 2
// baseline (speedup 1.0000x reference)
#include <cuda_runtime.h>
#include <math.h>

// Problem constants
#define NB 8
#define NT 512
#define NTOK 4096   // NB*NT tokens

// Scratch buffers (static device globals — no runtime allocation allowed)
__device__ float g_x   [NTOK * 1024];   // x = lnsilu(act@W_pre)+emb@W_emb   [T,B,HID]
__device__ float g_xz  [NTOK * 2048];   // xz = x@W_in+b  (ssm | gate)
__device__ float g_dt  [NTOK * 1024];   // softplus(x_ssm@W_dt+b_dt)
__device__ float g_bc  [NTOK * 32];     // Bp (16) | Cp (16)
__device__ float g_y   [NTOK * 1024];   // scan output (gated)
__device__ float g_det [NTOK * 1024];   // deter
__device__ float g_tmp [NTOK * 1024];   // pre-LN GEMM outputs / post logits
__device__ float g_h1  [NTOK * 1024];   // hidden after lnsilu

// ---------------------------------------------------------------------------
// Generic fp32 GEMM: C[M=4096, N] = act( A[M,K] @ W[K,N] + bias ) (+ addend)
// A is split: cols [0,K0) from A0 (row p, stride lda0),
//             cols [K0,K) from A1 with token gather row (p%8)*512 + p/8
// BM=128, BN=64, BK=16, 256 threads, 8x4 per-thread microtile.
// ---------------------------------------------------------------------------
__global__ __launch_bounds__(256, 2) void gemm_kernel(
    const float* __restrict__ A0, int lda0, int K0,
    const float* __restrict__ A1, int lda1,
    const float* __restrict__ W,
    const float* __restrict__ bias,
    const float* __restrict__ addend, int ldadd,
    float* __restrict__ C, int ldc,
    int N, int K, int act)
{
    __shared__ float As[16][128];
    __shared__ float Bs[16][68];   // padded row to de-conflict stores

    const int tid = threadIdx.x;
    const int tx  = tid & 15;       // N direction (16 * 4 = 64)
    const int ty  = tid >> 4;       // M direction (16 * 8 = 128)
    const int bm  = blockIdx.y * 128;
    const int bn  = blockIdx.x * 64;

    // A tile load mapping: thread -> (row, 8-wide K chunk)
    const int arow = tid >> 1;            // 0..127
    const int akk  = (tid & 1) * 8;       // 0 or 8
    // B tile load mapping: thread -> (k row, 4-wide N chunk)
    const int brow = tid >> 4;            // 0..15
    const int bcol = (tid & 15) * 4;      // 0..60

    const int grow = bm + arow;           // global token row for A loads
    const int gt = grow >> 3;             // t
    const int gb = grow & 7;              // b

    float acc[8][4];
    #pragma unroll
    for (int i = 0; i < 8; i++)
        #pragma unroll
        for (int j = 0; j < 4; j++) acc[i][j] = 0.f;

    for (int k0 = 0; k0 < K; k0 += 16) {
        // ---- load A tile (transposed into smem) ----
        const float* asrc;
        if (k0 < K0) asrc = A0 + (size_t)grow * lda0 + (k0 + akk);
        else         asrc = A1 + (size_t)(gb * NT + gt) * lda1 + (k0 - K0 + akk);
        float4 av0 = *(const float4*)asrc;
        float4 av1 = *(const float4*)(asrc + 4);

        // ---- load B tile ----
        const float* wsrc = W + (size_t)(k0 + brow) * N + (bn + bcol);
        float4 wv;
        if (bn + bcol + 3 < N) {
            wv = *(const float4*)wsrc;
        } else {
            wv.x = (bn + bcol + 0 < N) ? wsrc[0] : 0.f;
            wv.y = (bn + bcol + 1 < N) ? wsrc[1] : 0.f;
            wv.z = (bn + bcol + 2 < N) ? wsrc[2] : 0.f;
            wv.w = (bn + bcol + 3 < N) ? wsrc[3] : 0.f;
        }

        As[akk + 0][arow] = av0.x; As[akk + 1][arow] = av0.y;
        As[akk + 2][arow] = av0.z; As[akk + 3][arow] = av0.w;
        As[akk + 4][arow] = av1.x; As[akk + 5][arow] = av1.y;
        As[akk + 6][arow] = av1.z; As[akk + 7][arow] = av1.w;
        *(float4*)&Bs[brow][bcol] = wv;

        __syncthreads();

        #pragma unroll
        for (int kk = 0; kk < 16; kk++) {
            float4 a0 = *(const float4*)&As[kk][ty * 8];
            float4 a1 = *(const float4*)&As[kk][ty * 8 + 4];
            float4 b4 = *(const float4*)&Bs[kk][tx * 4];
            float ar[8] = {a0.x, a0.y, a0.z, a0.w, a1.x, a1.y, a1.z, a1.w};
            float br[4] = {b4.x, b4.y, b4.z, b4.w};
            #pragma unroll
            for (int i = 0; i < 8; i++)
                #pragma unroll
                for (int j = 0; j < 4; j++)
                    acc[i][j] = fmaf(ar[i], br[j], acc[i][j]);
        }
        __syncthreads();
    }

    // ---- epilogue ----
    float bv[4];
    #pragma unroll
    for (int j = 0; j < 4; j++) {
        int col = bn + tx * 4 + j;
        bv[j] = (bias != nullptr && col < N) ? bias[col] : 0.f;
    }
    #pragma unroll
    for (int i = 0; i < 8; i++) {
        int row = bm + ty * 8 + i;
        #pragma unroll
        for (int j = 0; j < 4; j++) {
            int col = bn + tx * 4 + j;
            if (col < N) {
                float v = acc[i][j] + bv[j];
                if (addend) v += addend[(size_t)row * ldadd + col];
                if (act == 1)  // softplus (stable)
                    v = fmaxf(v, 0.f) + log1pf(__expf(-fabsf(v)));
                C[(size_t)row * ldc + col] = v;
            }
        }
    }
}

// ---------------------------------------------------------------------------
// Stage 0: per-token  lnsilu(actions @ W_pre + b_pre)  -> g_x
// One block per token (in [T,B] order), 256 threads, 4 cols each.
// ---------------------------------------------------------------------------
__global__ __launch_bounds__(256) void pre_kernel(
    const float* __restrict__ actions, const float* __restrict__ W_pre,
    const float* __restrict__ b_pre, const float* __restrict__ g_pre,
    const float* __restrict__ bb_pre, float* __restrict__ xout)
{
    int p = blockIdx.x;
    int t = p >> 3, b = p & 7;
    __shared__ float sa[32];
    __shared__ float red[2][8];
    int tid = threadIdx.x;
    if (tid < 32) sa[tid] = actions[(size_t)(b * NT + t) * 32 + tid];
    __syncthreads();

    int c0 = tid * 4;
    float4 acc = *(const float4*)(b_pre + c0);
    #pragma unroll 8
    for (int k = 0; k < 32; k++) {
        float a = sa[k];
        float4 w = *(const float4*)(W_pre + (size_t)k * 1024 + c0);
        acc.x = fmaf(a, w.x, acc.x); acc.y = fmaf(a, w.y, acc.y);
        acc.z = fmaf(a, w.z, acc.z); acc.w = fmaf(a, w.w, acc.w);
    }
    float s  = acc.x + acc.y + acc.z + acc.w;
    float s2 = acc.x*acc.x + acc.y*acc.y + acc.z*acc.z + acc.w*acc.w;
    #pragma unroll
    for (int o = 16; o; o >>= 1) {
        s  += __shfl_xor_sync(0xffffffffu, s, o);
        s2 += __shfl_xor_sync(0xffffffffu, s2, o);
    }
    if ((tid & 31) == 0) { red[0][tid >> 5] = s; red[1][tid >> 5] = s2; }
    __syncthreads();
    if (tid == 0) {
        float a = 0.f, c = 0.f;
        for (int i = 0; i < 8; i++) { a += red[0][i]; c += red[1][i]; }
        red[0][0] = a; red[1][0] = c;
    }
    __syncthreads();
    float mean = red[0][0] * (1.f / 1024.f);
    float var  = red[1][0] * (1.f / 1024.f) - mean * mean;
    float inv  = rsqrtf(var + 1e-5f);
    float vv[4] = {acc.x, acc.y, acc.z, acc.w};
    #pragma unroll
    for (int j = 0; j < 4; j++) {
        int c = c0 + j;
        float xn = (vv[j] - mean) * inv * g_pre[c] + bb_pre[c];
        xn = xn * (1.f / (1.f + __expf(-xn)));   // silu
        xout[(size_t)p * 1024 + c] = xn;
    }
}

// ---------------------------------------------------------------------------
// Per-token LayerNorm (+optional silu), row width 1024.
// Writes Y (and optionally Y2 with its own stride — used for deter -> output).
// ---------------------------------------------------------------------------
__global__ __launch_bounds__(256) void ln_kernel(
    const float* __restrict__ X,
    const float* __restrict__ gma, const float* __restrict__ bta,
    float* __restrict__ Y, int ldy,
    float* __restrict__ Y2, int ldy2,
    int dosilu)
{
    int p = blockIdx.x;
    int tid = threadIdx.x;
    int c0 = tid * 4;
    __shared__ float red[2][8];
    float4 v = *(const float4*)(X + (size_t)p * 1024 + c0);
    float s  = v.x + v.y + v.z + v.w;
    float s2 = v.x*v.x + v.y*v.y + v.z*v.z + v.w*v.w;
    #pragma unroll
    for (int o = 16; o; o >>= 1) {
        s  += __shfl_xor_sync(0xffffffffu, s, o);
        s2 += __shfl_xor_sync(0xffffffffu, s2, o);
    }
    if ((tid & 31) == 0) { red[0][tid >> 5] = s; red[1][tid >> 5] = s2; }
    __syncthreads();
    if (tid == 0) {
        float a = 0.f, c = 0.f;
        for (int i = 0; i < 8; i++) { a += red[0][i]; c += red[1][i]; }
        red[0][0] = a; red[1][0] = c;
    }
    __syncthreads();
    float mean = red[0][0] * (1.f / 1024.f);
    float var  = red[1][0] * (1.f / 1024.f) - mean * mean;
    float inv  = rsqrtf(var + 1e-5f);
    float vv[4] = {v.x, v.y, v.z, v.w};
    #pragma unroll
    for (int j = 0; j < 4; j++) {
        int c = c0 + j;
        float xn = (vv[j] - mean) * inv * gma[c] + bta[c];
        if (dosilu) xn = xn * (1.f / (1.f + __expf(-xn)));
        Y[(size_t)p * ldy + c] = xn;
        if (Y2) Y2[(size_t)p * ldy2 + c] = xn;
    }
}

// ---------------------------------------------------------------------------
// SSM scan: channel (b,d) handled by a 16-lane group (lane = state n).
// h_t = exp(dt*A)*h_{t-1} + dt*x_ssm*Bp ;  y = <h,Cp> + Dp*x_ssm ; gated silu.
// 131072 threads total (4096 warps) -> plenty of latency hiding.
// ---------------------------------------------------------------------------
__global__ __launch_bounds__(256) void scan_kernel(
    const float* __restrict__ xz, const float* __restrict__ dt,
    const float* __restrict__ bc, const float* __restrict__ A_log,
    const float* __restrict__ Dp, float* __restrict__ y)
{
    int pair = blockIdx.x * 16 + (threadIdx.x >> 4);   // (b,d): pair = b*1024 + d
    int n = threadIdx.x & 15;
    int b = pair >> 10;
    int d = pair & 1023;
    float A  = -__expf(A_log[d * 16 + n]);
    float Dd = Dp[d];
    float h = 0.f;
    for (int t = 0; t < NT; t++) {
        int p = t * NB + b;
        float dtv = dt[(size_t)p * 1024 + d];
        float xs  = xz[(size_t)p * 2048 + d];
        float g   = __expf(dtv * A);
        h = fmaf(g, h, dtv * xs * bc[(size_t)p * 32 + n]);
        float c = h * bc[(size_t)p * 32 + 16 + n];
        c += __shfl_xor_sync(0xffffffffu, c, 8, 16);
        c += __shfl_xor_sync(0xffffffffu, c, 4, 16);
        c += __shfl_xor_sync(0xffffffffu, c, 2, 16);
        c += __shfl_xor_sync(0xffffffffu, c, 1, 16);
        if (n == 0) {
            float gate = xz[(size_t)p * 2048 + 1024 + d];
            y[(size_t)p * 1024 + d] =
                (c + Dd * xs) * gate * (1.f / (1.f + __expf(-gate)));
        }
    }
}

// ---------------------------------------------------------------------------
// softmax over CLS=32 chunks + unimix + log -> out[:, 2048:3072]
// One warp per (token, stochastic slot).
// ---------------------------------------------------------------------------
__global__ __launch_bounds__(256) void softmax_kernel(
    const float* __restrict__ post, float* __restrict__ out)
{
    int idx  = blockIdx.x * 8 + (threadIdx.x >> 5);
    int lane = threadIdx.x & 31;
    int p = idx >> 5, s = idx & 31;
    float v = post[(size_t)p * 1024 + s * 32 + lane];
    float m = v;
    #pragma unroll
    for (int o = 16; o; o >>= 1) m = fmaxf(m, __shfl_xor_sync(0xffffffffu, m, o));
    float e = __expf(v - m);
    float sum = e;
    #pragma unroll
    for (int o = 16; o; o >>= 1) sum += __shfl_xor_sync(0xffffffffu, sum, o);
    float prob = e / sum;
    out[(size_t)p * 3072 + 2048 + s * 32 + lane] =
        logf(0.99f * prob + 0.01f / 32.f + 1e-8f);
}

// ---------------------------------------------------------------------------
extern "C" void kernel_launch(void* const* d_in, const int* in_sizes, int n_in,
                              void* d_out, int out_size)
{
    const float* actions = (const float*)d_in[0];
    const float* embeds  = (const float*)d_in[1];
    const float* W_pre   = (const float*)d_in[2];
    const float* b_pre   = (const float*)d_in[3];
    const float* g_pre   = (const float*)d_in[4];
    const float* bb_pre  = (const float*)d_in[5];
    const float* W_emb   = (const float*)d_in[6];
    const float* W_in    = (const float*)d_in[7];
    const float* b_in    = (const float*)d_in[8];
    const float* W_dt    = (const float*)d_in[9];
    const float* b_dt    = (const float*)d_in[10];
    const float* W_B     = (const float*)d_in[11];
    const float* W_C     = (const float*)d_in[12];
    const float* A_log   = (const float*)d_in[13];
    const float* Dp      = (const float*)d_in[14];
    const float* g_out   = (const float*)d_in[15];
    const float* b_out   = (const float*)d_in[16];
    const float* W_pr1   = (const float*)d_in[17];
    const float* b_pr1   = (const float*)d_in[18];
    const float* g_pr    = (const float*)d_in[19];
    const float* bb_pr   = (const float*)d_in[20];
    const float* W_pr2   = (const float*)d_in[21];
    const float* b_pr2   = (const float*)d_in[22];
    const float* W_po1   = (const float*)d_in[23];
    const float* b_po1   = (const float*)d_in[24];
    const float* g_po    = (const float*)d_in[25];
    const float* bb_po   = (const float*)d_in[26];
    const float* W_po2   = (const float*)d_in[27];
    const float* b_po2   = (const float*)d_in[28];
    float* out = (float*)d_out;

    float *px, *pxz, *pdt, *pbc, *py, *pdet, *ptmp, *ph;
    cudaGetSymbolAddress((void**)&px,   g_x);
    cudaGetSymbolAddress((void**)&pxz,  g_xz);
    cudaGetSymbolAddress((void**)&pdt,  g_dt);
    cudaGetSymbolAddress((void**)&pbc,  g_bc);
    cudaGetSymbolAddress((void**)&py,   g_y);
    cudaGetSymbolAddress((void**)&pdet, g_det);
    cudaGetSymbolAddress((void**)&ptmp, g_tmp);
    cudaGetSymbolAddress((void**)&ph,   g_h1);

    dim3 blk(256);
    dim3 gN1(1024 / 64, NTOK / 128);   // N=1024
    dim3 gN2(2048 / 64, NTOK / 128);   // N=2048
    dim3 gNs(1,         NTOK / 128);   // N<=64

    // 0: lnsilu(actions @ W_pre + b_pre) -> g_x
    pre_kernel<<<NTOK, blk>>>(actions, W_pre, b_pre, g_pre, bb_pre, px);

    // 1: g_x += embeds(gathered) @ W_emb
    gemm_kernel<<<gN1, blk>>>(nullptr, 0, 0, embeds, 1024, W_emb,
                              nullptr, px, 1024, px, 1024, 1024, 1024, 0);

    // 2: xz = x @ W_in + b_in
    gemm_kernel<<<gN2, blk>>>(px, 1024, 1024, nullptr, 0, W_in,
                              b_in, nullptr, 0, pxz, 2048, 2048, 1024, 0);

    // 3: dt = softplus(x_ssm @ W_dt + b_dt)
    gemm_kernel<<<gN1, blk>>>(pxz, 2048, 1024, nullptr, 0, W_dt,
                              b_dt, nullptr, 0, pdt, 1024, 1024, 1024, 1);

    // 4: Bp, Cp
    gemm_kernel<<<gNs, blk>>>(pxz, 2048, 1024, nullptr, 0, W_B,
                              nullptr, nullptr, 0, pbc, 32, 16, 1024, 0);
    gemm_kernel<<<gNs, blk>>>(pxz, 2048, 1024, nullptr, 0, W_C,
                              nullptr, nullptr, 0, pbc + 16, 32, 16, 1024, 0);

    // 5: SSM scan + gate -> g_y
    scan_kernel<<<512, blk>>>(pxz, pdt, pbc, A_log, Dp, py);

    // 6: deter = LN(y); write g_det and out[:, 0:1024]
    ln_kernel<<<NTOK, blk>>>(py, g_out, b_out, pdet, 1024, out, 3072, 0);

    // 7: prior head
    gemm_kernel<<<gN1, blk>>>(pdet, 1024, 1024, nullptr, 0, W_pr1,
                              b_pr1, nullptr, 0, ptmp, 1024, 1024, 1024, 0);
    ln_kernel<<<NTOK, blk>>>(ptmp, g_pr, bb_pr, ph, 1024, nullptr, 0, 1);
    gemm_kernel<<<gN1, blk>>>(ph, 1024, 1024, nullptr, 0, W_pr2,
                              b_pr2, nullptr, 0, out + 1024, 3072, 1024, 1024, 0);

    // 8: post head (post_in = [deter | emb_t], K=2048)
    gemm_kernel<<<gN1, blk>>>(pdet, 1024, 1024, embeds, 1024, W_po1,
                              b_po1, nullptr, 0, ptmp, 1024, 1024, 2048, 0);
    ln_kernel<<<NTOK, blk>>>(ptmp, g_po, bb_po, ph, 1024, nullptr, 0, 1);
    gemm_kernel<<<gN1, blk>>>(ph, 1024, 1024, nullptr, 0, W_po2,
                              b_po2, nullptr, 0, ptmp, 1024, 1024, 1024, 0);

    // 9: softmax + unimix + log -> out[:, 2048:3072]
    softmax_kernel<<<NTOK * 32 / 8, blk>>>(ptmp, out);
}

// round 5
// speedup vs baseline: 1.2442x; 1.2442x over previous
#include <cuda_runtime.h>
#include <cuda_bf16.h>
#include <math.h>
#include <stdint.h>

#define NB 8
#define NT 512
#define NTOK 4096

// ===================== helpers =============================================
__device__ __forceinline__ uint32_t smem_to_u32(const void* p) {
    uint32_t a;
    asm("{ .reg .u64 t; cvta.to.shared.u64 t, %1; cvt.u32.u64 %0, t; }" : "=r"(a) : "l"(p));
    return a;
}
__device__ __forceinline__ void cp16(uint32_t s, const void* g) {
    asm volatile("cp.async.cg.shared.global [%0], [%1], 16;" :: "r"(s), "l"(g));
}
#define CP_COMMIT() asm volatile("cp.async.commit_group;" ::: "memory")
#define CP_WAIT(n)  asm volatile("cp.async.wait_group %0;" :: "n"(n) : "memory")

__device__ __forceinline__ void ldm4(uint32_t* r, uint32_t addr) {
    asm volatile("ldmatrix.sync.aligned.m8n8.x4.shared.b16 {%0,%1,%2,%3}, [%4];"
        : "=r"(r[0]), "=r"(r[1]), "=r"(r[2]), "=r"(r[3]) : "r"(addr));
}
__device__ __forceinline__ void mma16816(float* c, const uint32_t* a, const uint32_t* b) {
    asm volatile("mma.sync.aligned.m16n8k16.row.col.f32.bf16.bf16.f32 "
        "{%0,%1,%2,%3}, {%4,%5,%6,%7}, {%8,%9}, {%0,%1,%2,%3};"
        : "+f"(c[0]), "+f"(c[1]), "+f"(c[2]), "+f"(c[3])
        : "r"(a[0]), "r"(a[1]), "r"(a[2]), "r"(a[3]), "r"(b[0]), "r"(b[1]));
}

// ===================== device scratch ======================================
__device__ float g_tmp[NTOK * 1024];
__device__ float g_xz [NTOK * 2048];
__device__ float g_dt [NTOK * 1024];
__device__ float g_bc [NTOK * 32];
__device__ float g_y  [NTOK * 1024];

__device__ __nv_bfloat16 a_emb_h[NTOK*1024], a_emb_l[NTOK*1024];
__device__ __nv_bfloat16 a_x_h  [NTOK*1024], a_x_l  [NTOK*1024];
__device__ __nv_bfloat16 a_ssm_h[NTOK*1024], a_ssm_l[NTOK*1024];
__device__ __nv_bfloat16 a_det_h[NTOK*1024], a_det_l[NTOK*1024];
__device__ __nv_bfloat16 a_h_h  [NTOK*1024], a_h_l  [NTOK*1024];

__device__ __nv_bfloat16 wt_emb_h[1024*1024], wt_emb_l[1024*1024];
__device__ __nv_bfloat16 wt_in_h [2048*1024], wt_in_l [2048*1024];
__device__ __nv_bfloat16 wt_dt_h [1024*1024], wt_dt_l [1024*1024];
__device__ __nv_bfloat16 wt_pr1_h[1024*1024], wt_pr1_l[1024*1024];
__device__ __nv_bfloat16 wt_pr2_h[1024*1024], wt_pr2_l[1024*1024];
__device__ __nv_bfloat16 wt_po1_h[1024*2048], wt_po1_l[1024*2048];
__device__ __nv_bfloat16 wt_po2_h[1024*1024], wt_po2_l[1024*1024];

// ===================== HMMA GEMM ===========================================
// C[4096,N] = act( [A0|A1] @ Wt^T + bias ) (+addend), 3-term bf16 split.
// A hi/lo: [4096,1024] bf16 (K=2048 -> two buffers, split at K0).
// Wt hi/lo: [N,K] bf16. Tile 128x128, BK=32, 8 warps (warp 32x64), 4 stages.
#define STG_BYTES 40960            // 4 operands * 128 rows * 80B
#define GEMM_SMEM (4*STG_BYTES + 512)

__global__ __launch_bounds__(256, 1) void gemm_tc(
    const __nv_bfloat16* __restrict__ A0h, const __nv_bfloat16* __restrict__ A0l, int K0,
    const __nv_bfloat16* __restrict__ A1h, const __nv_bfloat16* __restrict__ A1l,
    const __nv_bfloat16* __restrict__ Bh,  const __nv_bfloat16* __restrict__ Bl,
    const float* __restrict__ bias,
    const float* __restrict__ addend, int ldadd,
    float* __restrict__ C, int ldc,
    __nv_bfloat16* __restrict__ Chi, __nv_bfloat16* __restrict__ Clo, int ldhl,
    int K, int act)
{
    extern __shared__ char smem[];
    const uint32_t sb = smem_to_u32(smem);
    const int tid = threadIdx.x;
    const int lane = tid & 31, w = tid >> 5;
    const int bm = blockIdx.y * 128;
    const int bn = blockIdx.x * 128;
    const int wm = (w & 3) * 32;
    const int wn = (w >> 2) * 64;
    float* sbias = (float*)(smem + 4 * STG_BYTES);
    if (tid < 128) sbias[tid] = bias ? bias[bn + tid] : 0.f;

    const int nst = K >> 5;

    auto load_stage = [&](int s) {
        const uint32_t dst = sb + (uint32_t)(s & 3) * STG_BYTES;
        const int kglob = s << 5;
        #pragma unroll
        for (int j = 0; j < 8; j++) {
            int q = tid + (j << 8);
            int op = q >> 9;             // 0:Ah 1:Al 2:Bh 3:Bl
            int row = (q >> 2) & 127;
            int kc = q & 3;              // 16B chunk within 64B row-slice
            uint32_t d = dst + (uint32_t)op * 10240u + (uint32_t)row * 80u + (uint32_t)kc * 16u;
            const __nv_bfloat16* src;
            if (op < 2) {
                int col = kglob + kc * 8;
                const __nv_bfloat16* base;
                if (col < K0) base = op ? A0l : A0h;
                else { base = op ? A1l : A1h; col -= K0; }
                src = base + (size_t)(bm + row) * 1024 + col;
            } else {
                src = ((op == 2) ? Bh : Bl) + (size_t)(bn + row) * K + kglob + kc * 8;
            }
            cp16(d, src);
        }
        CP_COMMIT();
    };

    load_stage(0); load_stage(1); load_stage(2);

    float acc[2][8][4] = {};

    for (int s = 0; s < nst; s++) {
        CP_WAIT(2);            // stage s resident (s+1, s+2 may be pending)
        __syncthreads();
        const uint32_t sA = sb + (uint32_t)(s & 3) * STG_BYTES;
        #pragma unroll
        for (int kk = 0; kk < 2; kk++) {
            const int kloc = kk * 16;
            uint32_t ah[2][4], al[2][4], bh[4][4], bl[4][4];
            #pragma unroll
            for (int mi = 0; mi < 2; mi++) {
                uint32_t ad = sA
                    + (uint32_t)((wm + mi * 16 + (lane & 15)) * 80)
                    + (uint32_t)((kloc + ((lane >> 4) << 3)) * 2);
                ldm4(ah[mi], ad);
                ldm4(al[mi], ad + 10240u);
            }
            #pragma unroll
            for (int nj = 0; nj < 4; nj++) {
                uint32_t bd = sA + 20480u
                    + (uint32_t)((wn + nj * 16 + ((lane >> 4) << 3) + (lane & 7)) * 80)
                    + (uint32_t)((kloc + ((lane >> 3) & 1) * 8) * 2);
                ldm4(bh[nj], bd);
                ldm4(bl[nj], bd + 10240u);
            }
            #pragma unroll
            for (int mi = 0; mi < 2; mi++)
                #pragma unroll
                for (int nj = 0; nj < 8; nj++) {
                    const uint32_t* bhp = &bh[nj >> 1][(nj & 1) * 2];
                    const uint32_t* blp = &bl[nj >> 1][(nj & 1) * 2];
                    mma16816(acc[mi][nj], ah[mi], bhp);
                    mma16816(acc[mi][nj], ah[mi], blp);
                    mma16816(acc[mi][nj], al[mi], bhp);
                }
        }
        // issue loads for stage s+3 AFTER compute: barrier above guarantees all
        // warps finished compute(s-1), which last read buffer (s+3)&3.
        if (s + 3 < nst) load_stage(s + 3); else CP_COMMIT();
    }

    // ---- epilogue ----
    const int g = lane >> 2, cc = (lane & 3) * 2;
    const bool dohl = (Chi != nullptr) && (bn < ldhl);
    #pragma unroll
    for (int mi = 0; mi < 2; mi++) {
        #pragma unroll
        for (int r = 0; r < 2; r++) {
            const int m = bm + wm + mi * 16 + g + r * 8;
            #pragma unroll
            for (int nj = 0; nj < 8; nj++) {
                const int ncol = wn + nj * 8 + cc;
                const int n = bn + ncol;
                float v0 = acc[mi][nj][r * 2 + 0] + sbias[ncol];
                float v1 = acc[mi][nj][r * 2 + 1] + sbias[ncol + 1];
                if (addend) {
                    float2 a = *(const float2*)(addend + (size_t)m * ldadd + n);
                    v0 += a.x; v1 += a.y;
                }
                if (act == 1) {
                    v0 = fmaxf(v0, 0.f) + log1pf(__expf(-fabsf(v0)));
                    v1 = fmaxf(v1, 0.f) + log1pf(__expf(-fabsf(v1)));
                }
                if (C) *(float2*)(C + (size_t)m * ldc + n) = make_float2(v0, v1);
                if (dohl) {
                    __nv_bfloat16 h0 = __float2bfloat16_rn(v0);
                    __nv_bfloat16 h1 = __float2bfloat16_rn(v1);
                    __nv_bfloat162 hh; hh.x = h0; hh.y = h1;
                    *(__nv_bfloat162*)(Chi + (size_t)m * ldhl + n) = hh;
                    __nv_bfloat162 ll;
                    ll.x = __float2bfloat16_rn(v0 - __bfloat162float(h0));
                    ll.y = __float2bfloat16_rn(v1 - __bfloat162float(h1));
                    *(__nv_bfloat162*)(Clo + (size_t)m * ldhl + n) = ll;
                }
            }
        }
    }
}

// ===================== weight transpose + split ============================
__global__ __launch_bounds__(256) void wconv_kernel(
    const float* __restrict__ W, __nv_bfloat16* __restrict__ H,
    __nv_bfloat16* __restrict__ L, int K, int N)
{
    __shared__ float s[32][33];
    const int tx = threadIdx.x, ty = threadIdx.y;
    const int n0 = blockIdx.x * 32, k0 = blockIdx.y * 32;
    #pragma unroll
    for (int j = 0; j < 4; j++)
        s[ty + j * 8][tx] = W[(size_t)(k0 + ty + j * 8) * N + n0 + tx];
    __syncthreads();
    #pragma unroll
    for (int j = 0; j < 4; j++) {
        float v = s[tx][ty + j * 8];
        __nv_bfloat16 h = __float2bfloat16_rn(v);
        size_t o = (size_t)(n0 + ty + j * 8) * K + k0 + tx;
        H[o] = h;
        L[o] = __float2bfloat16_rn(v - __bfloat162float(h));
    }
}

// ===================== activation split ([B,T]->[T,B] gather) ==============
__global__ __launch_bounds__(256) void aconv_kernel(
    const float* __restrict__ X,
    __nv_bfloat16* __restrict__ H, __nv_bfloat16* __restrict__ L)
{
    const int p = blockIdx.x;
    const int src = (p & 7) * NT + (p >> 3);
    const int c = threadIdx.x * 4;
    float4 v = *(const float4*)(X + (size_t)src * 1024 + c);
    float vv[4] = {v.x, v.y, v.z, v.w};
    #pragma unroll
    for (int k = 0; k < 2; k++) {
        __nv_bfloat16 h0 = __float2bfloat16_rn(vv[2*k]);
        __nv_bfloat16 h1 = __float2bfloat16_rn(vv[2*k+1]);
        __nv_bfloat162 hh; hh.x = h0; hh.y = h1;
        ((__nv_bfloat162*)(H + (size_t)p * 1024 + c))[k] = hh;
        __nv_bfloat162 ll;
        ll.x = __float2bfloat16_rn(vv[2*k]   - __bfloat162float(h0));
        ll.y = __float2bfloat16_rn(vv[2*k+1] - __bfloat162float(h1));
        ((__nv_bfloat162*)(L + (size_t)p * 1024 + c))[k] = ll;
    }
}

// ===================== stage 0: lnsilu(actions @ W_pre + b) ================
__global__ __launch_bounds__(256) void pre_kernel(
    const float* __restrict__ actions, const float* __restrict__ W_pre,
    const float* __restrict__ b_pre, const float* __restrict__ g_pre,
    const float* __restrict__ bb_pre, float* __restrict__ xout)
{
    int p = blockIdx.x;
    int t = p >> 3, b = p & 7;
    __shared__ float sa[32];
    __shared__ float red[2][8];
    int tid = threadIdx.x;
    if (tid < 32) sa[tid] = actions[(size_t)(b * NT + t) * 32 + tid];
    __syncthreads();
    int c0 = tid * 4;
    float4 acc = *(const float4*)(b_pre + c0);
    #pragma unroll 8
    for (int k = 0; k < 32; k++) {
        float a = sa[k];
        float4 w = *(const float4*)(W_pre + (size_t)k * 1024 + c0);
        acc.x = fmaf(a, w.x, acc.x); acc.y = fmaf(a, w.y, acc.y);
        acc.z = fmaf(a, w.z, acc.z); acc.w = fmaf(a, w.w, acc.w);
    }
    float s  = acc.x + acc.y + acc.z + acc.w;
    float s2 = acc.x*acc.x + acc.y*acc.y + acc.z*acc.z + acc.w*acc.w;
    #pragma unroll
    for (int o = 16; o; o >>= 1) {
        s  += __shfl_xor_sync(0xffffffffu, s, o);
        s2 += __shfl_xor_sync(0xffffffffu, s2, o);
    }
    if ((tid & 31) == 0) { red[0][tid >> 5] = s; red[1][tid >> 5] = s2; }
    __syncthreads();
    if (tid == 0) {
        float a = 0.f, c = 0.f;
        for (int i = 0; i < 8; i++) { a += red[0][i]; c += red[1][i]; }
        red[0][0] = a; red[1][0] = c;
    }
    __syncthreads();
    float mean = red[0][0] * (1.f / 1024.f);
    float var  = red[1][0] * (1.f / 1024.f) - mean * mean;
    float inv  = rsqrtf(var + 1e-5f);
    float vv[4] = {acc.x, acc.y, acc.z, acc.w};
    #pragma unroll
    for (int j = 0; j < 4; j++) {
        int c = c0 + j;
        float xn = (vv[j] - mean) * inv * g_pre[c] + bb_pre[c];
        xn = xn * (1.f / (1.f + __expf(-xn)));
        xout[(size_t)p * 1024 + c] = xn;
    }
}

// ===================== LayerNorm (+opt silu) -> fp32 and/or bf16 hi/lo =====
__global__ __launch_bounds__(256) void ln_kernel(
    const float* __restrict__ X,
    const float* __restrict__ gma, const float* __restrict__ bta,
    float* __restrict__ Y, int ldy,
    __nv_bfloat16* __restrict__ H, __nv_bfloat16* __restrict__ L,
    int dosilu)
{
    int p = blockIdx.x;
    int tid = threadIdx.x;
    int c0 = tid * 4;
    __shared__ float red[2][8];
    float4 v = *(const float4*)(X + (size_t)p * 1024 + c0);
    float s  = v.x + v.y + v.z + v.w;
    float s2 = v.x*v.x + v.y*v.y + v.z*v.z + v.w*v.w;
    #pragma unroll
    for (int o = 16; o; o >>= 1) {
        s  += __shfl_xor_sync(0xffffffffu, s, o);
        s2 += __shfl_xor_sync(0xffffffffu, s2, o);
    }
    if ((tid & 31) == 0) { red[0][tid >> 5] = s; red[1][tid >> 5] = s2; }
    __syncthreads();
    if (tid == 0) {
        float a = 0.f, c = 0.f;
        for (int i = 0; i < 8; i++) { a += red[0][i]; c += red[1][i]; }
        red[0][0] = a; red[1][0] = c;
    }
    __syncthreads();
    float mean = red[0][0] * (1.f / 1024.f);
    float var  = red[1][0] * (1.f / 1024.f) - mean * mean;
    float inv  = rsqrtf(var + 1e-5f);
    float vv[4] = {v.x, v.y, v.z, v.w};
    float xn[4];
    #pragma unroll
    for (int j = 0; j < 4; j++) {
        int c = c0 + j;
        float x = (vv[j] - mean) * inv * gma[c] + bta[c];
        if (dosilu) x = x * (1.f / (1.f + __expf(-x)));
        xn[j] = x;
    }
    if (Y) {
        #pragma unroll
        for (int j = 0; j < 4; j++) Y[(size_t)p * ldy + c0 + j] = xn[j];
    }
    if (H) {
        #pragma unroll
        for (int k = 0; k < 2; k++) {
            __nv_bfloat16 h0 = __float2bfloat16_rn(xn[2*k]);
            __nv_bfloat16 h1 = __float2bfloat16_rn(xn[2*k+1]);
            __nv_bfloat162 hh; hh.x = h0; hh.y = h1;
            ((__nv_bfloat162*)(H + (size_t)p * 1024 + c0))[k] = hh;
            __nv_bfloat162 ll;
            ll.x = __float2bfloat16_rn(xn[2*k]   - __bfloat162float(h0));
            ll.y = __float2bfloat16_rn(xn[2*k+1] - __bfloat162float(h1));
            ((__nv_bfloat162*)(L + (size_t)p * 1024 + c0))[k] = ll;
        }
    }
}

// ===================== small SIMT GEMM for B/C (N=16) ======================
__global__ __launch_bounds__(256, 2) void gemm_small(
    const float* __restrict__ A, int lda,
    const float* __restrict__ W,
    float* __restrict__ C, int ldc, int N, int K)
{
    __shared__ float As[16][128];
    __shared__ float Bs[16][68];
    const int tid = threadIdx.x;
    const int tx  = tid & 15;
    const int ty  = tid >> 4;
    const int bm  = blockIdx.y * 128;
    const int arow = tid >> 1;
    const int akk  = (tid & 1) * 8;
    const int brow = tid >> 4;
    const int bcol = (tid & 15) * 4;

    float acc[8][4];
    #pragma unroll
    for (int i = 0; i < 8; i++)
        #pragma unroll
        for (int j = 0; j < 4; j++) acc[i][j] = 0.f;

    for (int k0 = 0; k0 < K; k0 += 16) {
        const float* asrc = A + (size_t)(bm + arow) * lda + k0 + akk;
        float4 av0 = *(const float4*)asrc;
        float4 av1 = *(const float4*)(asrc + 4);
        const float* wsrc = W + (size_t)(k0 + brow) * N + bcol;
        float4 wv;
        wv.x = (bcol + 0 < N) ? wsrc[0] : 0.f;
        wv.y = (bcol + 1 < N) ? wsrc[1] : 0.f;
        wv.z = (bcol + 2 < N) ? wsrc[2] : 0.f;
        wv.w = (bcol + 3 < N) ? wsrc[3] : 0.f;
        As[akk + 0][arow] = av0.x; As[akk + 1][arow] = av0.y;
        As[akk + 2][arow] = av0.z; As[akk + 3][arow] = av0.w;
        As[akk + 4][arow] = av1.x; As[akk + 5][arow] = av1.y;
        As[akk + 6][arow] = av1.z; As[akk + 7][arow] = av1.w;
        *(float4*)&Bs[brow][bcol] = wv;
        __syncthreads();
        #pragma unroll
        for (int kk = 0; kk < 16; kk++) {
            float4 a0 = *(const float4*)&As[kk][ty * 8];
            float4 a1 = *(const float4*)&As[kk][ty * 8 + 4];
            float4 b4 = *(const float4*)&Bs[kk][tx * 4];
            float ar[8] = {a0.x, a0.y, a0.z, a0.w, a1.x, a1.y, a1.z, a1.w};
            float br[4] = {b4.x, b4.y, b4.z, b4.w};
            #pragma unroll
            for (int i = 0; i < 8; i++)
                #pragma unroll
                for (int j = 0; j < 4; j++)
                    acc[i][j] = fmaf(ar[i], br[j], acc[i][j]);
        }
        __syncthreads();
    }
    #pragma unroll
    for (int i = 0; i < 8; i++) {
        int row = bm + ty * 8 + i;
        #pragma unroll
        for (int j = 0; j < 4; j++) {
            int col = tx * 4 + j;
            if (col < N) C[(size_t)row * ldc + col] = acc[i][j];
        }
    }
}

// ===================== SSM scan ============================================
__global__ __launch_bounds__(256) void scan_kernel(
    const float* __restrict__ xz, const float* __restrict__ dt,
    const float* __restrict__ bc, const float* __restrict__ A_log,
    const float* __restrict__ Dp, float* __restrict__ y)
{
    int pair = blockIdx.x * 16 + (threadIdx.x >> 4);
    int n = threadIdx.x & 15;
    int b = pair >> 10;
    int d = pair & 1023;
    float A  = -__expf(A_log[d * 16 + n]);
    float Dd = Dp[d];
    float h = 0.f;
    for (int t = 0; t < NT; t++) {
        int p = t * NB + b;
        float dtv = dt[(size_t)p * 1024 + d];
        float xs  = xz[(size_t)p * 2048 + d];
        float g   = __expf(dtv * A);
        h = fmaf(g, h, dtv * xs * bc[(size_t)p * 32 + n]);
        float c = h * bc[(size_t)p * 32 + 16 + n];
        c += __shfl_xor_sync(0xffffffffu, c, 8, 16);
        c += __shfl_xor_sync(0xffffffffu, c, 4, 16);
        c += __shfl_xor_sync(0xffffffffu, c, 2, 16);
        c += __shfl_xor_sync(0xffffffffu, c, 1, 16);
        if (n == 0) {
            float gate = xz[(size_t)p * 2048 + 1024 + d];
            y[(size_t)p * 1024 + d] =
                (c + Dd * xs) * gate * (1.f / (1.f + __expf(-gate)));
        }
    }
}

// ===================== softmax + unimix + log ==============================
__global__ __launch_bounds__(256) void softmax_kernel(
    const float* __restrict__ post, float* __restrict__ out)
{
    int idx  = blockIdx.x * 8 + (threadIdx.x >> 5);
    int lane = threadIdx.x & 31;
    int p = idx >> 5, s = idx & 31;
    float v = post[(size_t)p * 1024 + s * 32 + lane];
    float m = v;
    #pragma unroll
    for (int o = 16; o; o >>= 1) m = fmaxf(m, __shfl_xor_sync(0xffffffffu, m, o));
    float e = __expf(v - m);
    float sum = e;
    #pragma unroll
    for (int o = 16; o; o >>= 1) sum += __shfl_xor_sync(0xffffffffu, sum, o);
    float prob = e / sum;
    out[(size_t)p * 3072 + 2048 + s * 32 + lane] =
        logf(0.99f * prob + 0.01f / 32.f + 1e-8f);
}

// ===========================================================================
extern "C" void kernel_launch(void* const* d_in, const int* in_sizes, int n_in,
                              void* d_out, int out_size)
{
    const float* actions = (const float*)d_in[0];
    const float* embeds  = (const float*)d_in[1];
    const float* W_pre   = (const float*)d_in[2];
    const float* b_pre   = (const float*)d_in[3];
    const float* g_pre   = (const float*)d_in[4];
    const float* bb_pre  = (const float*)d_in[5];
    const float* W_emb   = (const float*)d_in[6];
    const float* W_in    = (const float*)d_in[7];
    const float* b_in    = (const float*)d_in[8];
    const float* W_dt    = (const float*)d_in[9];
    const float* b_dt    = (const float*)d_in[10];
    const float* W_B     = (const float*)d_in[11];
    const float* W_C     = (const float*)d_in[12];
    const float* A_log   = (const float*)d_in[13];
    const float* Dp      = (const float*)d_in[14];
    const float* g_out   = (const float*)d_in[15];
    const float* b_out   = (const float*)d_in[16];
    const float* W_pr1   = (const float*)d_in[17];
    const float* b_pr1   = (const float*)d_in[18];
    const float* g_pr    = (const float*)d_in[19];
    const float* bb_pr   = (const float*)d_in[20];
    const float* W_pr2   = (const float*)d_in[21];
    const float* b_pr2   = (const float*)d_in[22];
    const float* W_po1   = (const float*)d_in[23];
    const float* b_po1   = (const float*)d_in[24];
    const float* g_po    = (const float*)d_in[25];
    const float* bb_po   = (const float*)d_in[26];
    const float* W_po2   = (const float*)d_in[27];
    const float* b_po2   = (const float*)d_in[28];
    float* out = (float*)d_out;

    float *ptmp, *pxz, *pdt, *pbc, *py;
    cudaGetSymbolAddress((void**)&ptmp, g_tmp);
    cudaGetSymbolAddress((void**)&pxz,  g_xz);
    cudaGetSymbolAddress((void**)&pdt,  g_dt);
    cudaGetSymbolAddress((void**)&pbc,  g_bc);
    cudaGetSymbolAddress((void**)&py,   g_y);
    __nv_bfloat16 *pembh, *pembl, *pxh, *pxl, *pssh, *pssl, *pdeh, *pdel, *phh, *phl;
    cudaGetSymbolAddress((void**)&pembh, a_emb_h); cudaGetSymbolAddress((void**)&pembl, a_emb_l);
    cudaGetSymbolAddress((void**)&pxh, a_x_h);     cudaGetSymbolAddress((void**)&pxl, a_x_l);
    cudaGetSymbolAddress((void**)&pssh, a_ssm_h);  cudaGetSymbolAddress((void**)&pssl, a_ssm_l);
    cudaGetSymbolAddress((void**)&pdeh, a_det_h);  cudaGetSymbolAddress((void**)&pdel, a_det_l);
    cudaGetSymbolAddress((void**)&phh, a_h_h);     cudaGetSymbolAddress((void**)&phl, a_h_l);
    __nv_bfloat16 *wEh,*wEl,*wIh,*wIl,*wDh,*wDl,*wP1h,*wP1l,*wP2h,*wP2l,*wO1h,*wO1l,*wO2h,*wO2l;
    cudaGetSymbolAddress((void**)&wEh, wt_emb_h);  cudaGetSymbolAddress((void**)&wEl, wt_emb_l);
    cudaGetSymbolAddress((void**)&wIh, wt_in_h);   cudaGetSymbolAddress((void**)&wIl, wt_in_l);
    cudaGetSymbolAddress((void**)&wDh, wt_dt_h);   cudaGetSymbolAddress((void**)&wDl, wt_dt_l);
    cudaGetSymbolAddress((void**)&wP1h, wt_pr1_h); cudaGetSymbolAddress((void**)&wP1l, wt_pr1_l);
    cudaGetSymbolAddress((void**)&wP2h, wt_pr2_h); cudaGetSymbolAddress((void**)&wP2l, wt_pr2_l);
    cudaGetSymbolAddress((void**)&wO1h, wt_po1_h); cudaGetSymbolAddress((void**)&wO1l, wt_po1_l);
    cudaGetSymbolAddress((void**)&wO2h, wt_po2_h); cudaGetSymbolAddress((void**)&wO2l, wt_po2_l);

    cudaFuncSetAttribute(gemm_tc, cudaFuncAttributeMaxDynamicSharedMemorySize, GEMM_SMEM);

    dim3 blk(256);
    dim3 wb(32, 8);

    // weight conversions (transpose [K,N] fp32 -> [N,K] bf16 hi/lo)
    wconv_kernel<<<dim3(32, 32), wb>>>(W_emb, wEh, wEl, 1024, 1024);
    wconv_kernel<<<dim3(64, 32), wb>>>(W_in,  wIh, wIl, 1024, 2048);
    wconv_kernel<<<dim3(32, 32), wb>>>(W_dt,  wDh, wDl, 1024, 1024);
    wconv_kernel<<<dim3(32, 32), wb>>>(W_pr1, wP1h, wP1l, 1024, 1024);
    wconv_kernel<<<dim3(32, 32), wb>>>(W_pr2, wP2h, wP2l, 1024, 1024);
    wconv_kernel<<<dim3(32, 64), wb>>>(W_po1, wO1h, wO1l, 2048, 1024);
    wconv_kernel<<<dim3(32, 32), wb>>>(W_po2, wO2h, wO2l, 1024, 1024);

    // stage 0: x_pre (fp32) and gathered embeds (bf16 split)
    pre_kernel<<<NTOK, blk>>>(actions, W_pre, b_pre, g_pre, bb_pre, ptmp);
    aconv_kernel<<<NTOK, blk>>>(embeds, pembh, pembl);

    // x = emb @ W_emb + x_pre  -> bf16 split only
    gemm_tc<<<dim3(8, 32), blk, GEMM_SMEM>>>(pembh, pembl, 1024, pembh, pembl,
        wEh, wEl, nullptr, ptmp, 1024, nullptr, 0, pxh, pxl, 1024, 1024, 0);

    // xz = x @ W_in + b_in  -> fp32 g_xz + bf16 split of first 1024 cols
    gemm_tc<<<dim3(16, 32), blk, GEMM_SMEM>>>(pxh, pxl, 1024, pxh, pxl,
        wIh, wIl, b_in, nullptr, 0, pxz, 2048, pssh, pssl, 1024, 1024, 0);

    // dt = softplus(x_ssm @ W_dt + b_dt)
    gemm_tc<<<dim3(8, 32), blk, GEMM_SMEM>>>(pssh, pssl, 1024, pssh, pssl,
        wDh, wDl, b_dt, nullptr, 0, pdt, 1024, nullptr, nullptr, 0, 1024, 1);

    // Bp, Cp (fp32 SIMT, N=16)
    gemm_small<<<dim3(1, 32), blk>>>(pxz, 2048, W_B, pbc, 32, 16, 1024);
    gemm_small<<<dim3(1, 32), blk>>>(pxz, 2048, W_C, pbc + 16, 32, 16, 1024);

    // scan
    scan_kernel<<<512, blk>>>(pxz, pdt, pbc, A_log, Dp, py);

    // deter = LN(y) -> out[:,0:1024] fp32 + bf16 split
    ln_kernel<<<NTOK, blk>>>(py, g_out, b_out, out, 3072, pdeh, pdel, 0);

    // prior head
    gemm_tc<<<dim3(8, 32), blk, GEMM_SMEM>>>(pdeh, pdel, 1024, pdeh, pdel,
        wP1h, wP1l, b_pr1, nullptr, 0, ptmp, 1024, nullptr, nullptr, 0, 1024, 0);
    ln_kernel<<<NTOK, blk>>>(ptmp, g_pr, bb_pr, nullptr, 0, phh, phl, 1);
    gemm_tc<<<dim3(8, 32), blk, GEMM_SMEM>>>(phh, phl, 1024, phh, phl,
        wP2h, wP2l, b_pr2, nullptr, 0, out + 1024, 3072, nullptr, nullptr, 0, 1024, 0);

    // post head (K=2048: [deter | emb_t])
    gemm_tc<<<dim3(8, 32), blk, GEMM_SMEM>>>(pdeh, pdel, 1024, pembh, pembl,
        wO1h, wO1l, b_po1, nullptr, 0, ptmp, 1024, nullptr, nullptr, 0, 2048, 0);
    ln_kernel<<<NTOK, blk>>>(ptmp, g_po, bb_po, nullptr, 0, phh, phl, 1);
    gemm_tc<<<dim3(8, 32), blk, GEMM_SMEM>>>(phh, phl, 1024, phh, phl,
        wO2h, wO2l, b_po2, nullptr, 0, ptmp, 1024, nullptr, nullptr, 0, 1024, 0);

    // softmax -> out[:, 2048:3072]
    softmax_kernel<<<NTOK * 32 / 8, blk>>>(ptmp, out);
}

// round 6
// speedup vs baseline: 2.3366x; 1.8779x over previous
#include <cuda_runtime.h>
#include <cuda_fp16.h>
#include <math.h>
#include <stdint.h>

#define NB 8
#define NT 512
#define NTOK 4096

// ===================== helpers =============================================
__device__ __forceinline__ uint32_t smem_to_u32(const void* p) {
    uint32_t a;
    asm("{ .reg .u64 t; cvta.to.shared.u64 t, %1; cvt.u32.u64 %0, t; }" : "=r"(a) : "l"(p));
    return a;
}
__device__ __forceinline__ void cp16(uint32_t s, const void* g) {
    asm volatile("cp.async.cg.shared.global [%0], [%1], 16;" :: "r"(s), "l"(g));
}
#define CP_COMMIT() asm volatile("cp.async.commit_group;" ::: "memory")
#define CP_WAIT(n)  asm volatile("cp.async.wait_group %0;" :: "n"(n) : "memory")

__device__ __forceinline__ void ldm4(uint32_t* r, uint32_t addr) {
    asm volatile("ldmatrix.sync.aligned.m8n8.x4.shared.b16 {%0,%1,%2,%3}, [%4];"
        : "=r"(r[0]), "=r"(r[1]), "=r"(r[2]), "=r"(r[3]) : "r"(addr));
}
__device__ __forceinline__ void mma16816(float* c, const uint32_t* a, const uint32_t* b) {
    asm volatile("mma.sync.aligned.m16n8k16.row.col.f32.f16.f16.f32 "
        "{%0,%1,%2,%3}, {%4,%5,%6,%7}, {%8,%9}, {%0,%1,%2,%3};"
        : "+f"(c[0]), "+f"(c[1]), "+f"(c[2]), "+f"(c[3])
        : "r"(a[0]), "r"(a[1]), "r"(a[2]), "r"(a[3]), "r"(b[0]), "r"(b[1]));
}

// ===================== device scratch ======================================
__device__ float g_tmp[NTOK * 1024];
__device__ float g_xz [NTOK * 2048];
__device__ float g_dt [NTOK * 1024];
__device__ float g_bc [NTOK * 32];
__device__ float g_y  [NTOK * 1024];

// Activations: single fp16
__device__ __half a_emb[NTOK*1024];
__device__ __half a_x  [NTOK*1024];
__device__ __half a_ssm[NTOK*1024];
__device__ __half a_det[NTOK*1024];
__device__ __half a_h1 [NTOK*1024];

// Weights: fp16 hi/lo, transposed [N,K]
__device__ __half wt_emb_h[1024*1024], wt_emb_l[1024*1024];
__device__ __half wt_in_h [2048*1024], wt_in_l [2048*1024];
__device__ __half wt_dt_h [1024*1024], wt_dt_l [1024*1024];
__device__ __half wt_pr1_h[1024*1024], wt_pr1_l[1024*1024];
__device__ __half wt_pr2_h[1024*1024], wt_pr2_l[1024*1024];
__device__ __half wt_po1_h[1024*2048], wt_po1_l[1024*2048];
__device__ __half wt_po2_h[1024*1024], wt_po2_l[1024*1024];

// ===================== HMMA GEMM ===========================================
// C[4096,N] = act( [A0|A1] @ Wt^T + bias ) (+addend), 2-pass fp16 W-split.
// A: fp16 [4096,1024] (K=2048 -> two buffers split at K0). Wt hi/lo [N,K].
// Tile 128(M)x64(N), BK=32, 4 warps, 3 stages, 3 CTAs/SM.
// Stage layout (80B-padded rows, 16B-aligned, ldmatrix conflict-free):
//   A: 128 rows x 80B at +0 (10240), Bh: 64 x 80B at +10240, Bl at +15360.
#define STG_BYTES 20480
#define GEMM_SMEM (3*STG_BYTES + 256)

__global__ __launch_bounds__(128, 3) void gemm_tc(
    const __half* __restrict__ A0, int K0,
    const __half* __restrict__ A1,
    const __half* __restrict__ Bh, const __half* __restrict__ Bl,
    const float* __restrict__ bias,
    const float* __restrict__ addend, int ldadd,
    float* __restrict__ C, int ldc,
    __half* __restrict__ Chi, int ldhl,
    int K, int act)
{
    extern __shared__ char smem[];
    const uint32_t sb = smem_to_u32(smem);
    const int tid = threadIdx.x;
    const int lane = tid & 31, w = tid >> 5;
    const int bm = blockIdx.y * 128;
    const int bn = blockIdx.x * 64;
    const int wm = w * 32;
    float* sbias = (float*)(smem + 3 * STG_BYTES);
    if (tid < 64) sbias[tid] = bias ? bias[bn + tid] : 0.f;

    const int nst = K >> 5;

    auto load_stage = [&](int s) {
        const uint32_t dst = sb + (uint32_t)(s % 3) * STG_BYTES;
        const int kglob = s << 5;
        #pragma unroll
        for (int j = 0; j < 8; j++) {
            int q = tid + (j << 7);
            uint32_t d;
            const __half* src;
            if (q < 512) {               // A: 128 rows x 4 chunks
                int row = q >> 2, kc = q & 3;
                int col = kglob + kc * 8;
                const __half* base = A0;
                if (col >= K0) { base = A1; col -= K0; }
                d = dst + (uint32_t)(row * 80 + kc * 16);
                src = base + (size_t)(bm + row) * 1024 + col;
            } else {                     // B hi (512..767) / lo (768..1023)
                int q2 = q - 512;
                int hi = q2 < 256 ? 1 : 0;
                q2 &= 255;
                int row = q2 >> 2, kc = q2 & 3;
                d = dst + (uint32_t)(hi ? 10240 : 15360) + (uint32_t)(row * 80 + kc * 16);
                src = (hi ? Bh : Bl) + (size_t)(bn + row) * K + kglob + kc * 8;
            }
            cp16(d, src);
        }
        CP_COMMIT();
    };

    load_stage(0); load_stage(1);

    float acc[2][8][4] = {};

    for (int s = 0; s < nst; s++) {
        CP_WAIT(1);
        __syncthreads();
        const uint32_t sA = sb + (uint32_t)(s % 3) * STG_BYTES;
        #pragma unroll
        for (int kk = 0; kk < 2; kk++) {
            const int kloc = kk * 16;
            uint32_t ah[2][4], bh[4][4], bl[4][4];
            #pragma unroll
            for (int mi = 0; mi < 2; mi++) {
                uint32_t ad = sA
                    + (uint32_t)((wm + mi * 16 + (lane & 15)) * 80)
                    + (uint32_t)((kloc + ((lane >> 4) << 3)) * 2);
                ldm4(ah[mi], ad);
            }
            #pragma unroll
            for (int nj = 0; nj < 4; nj++) {
                uint32_t bd = sA + 10240u
                    + (uint32_t)((nj * 16 + ((lane >> 4) << 3) + (lane & 7)) * 80)
                    + (uint32_t)((kloc + ((lane >> 3) & 1) * 8) * 2);
                ldm4(bh[nj], bd);
                ldm4(bl[nj], bd + 5120u);
            }
            #pragma unroll
            for (int mi = 0; mi < 2; mi++)
                #pragma unroll
                for (int nj = 0; nj < 8; nj++) {
                    const uint32_t* bhp = &bh[nj >> 1][(nj & 1) * 2];
                    const uint32_t* blp = &bl[nj >> 1][(nj & 1) * 2];
                    mma16816(acc[mi][nj], ah[mi], bhp);
                    mma16816(acc[mi][nj], ah[mi], blp);
                }
        }
        // prefetch s+2 AFTER compute(s): buffer (s+2)%3 == (s-1)%3, whose last
        // readers (compute(s-1)) all finished before this iteration's barrier.
        if (s + 2 < nst) load_stage(s + 2); else CP_COMMIT();
    }

    // ---- epilogue ----
    const int g = lane >> 2, cc = (lane & 3) * 2;
    const bool dohl = (Chi != nullptr) && (bn < ldhl);
    #pragma unroll
    for (int mi = 0; mi < 2; mi++) {
        #pragma unroll
        for (int r = 0; r < 2; r++) {
            const int m = bm + wm + mi * 16 + g + r * 8;
            #pragma unroll
            for (int nj = 0; nj < 8; nj++) {
                const int ncol = nj * 8 + cc;
                const int n = bn + ncol;
                float v0 = acc[mi][nj][r * 2 + 0] + sbias[ncol];
                float v1 = acc[mi][nj][r * 2 + 1] + sbias[ncol + 1];
                if (addend) {
                    float2 a = *(const float2*)(addend + (size_t)m * ldadd + n);
                    v0 += a.x; v1 += a.y;
                }
                if (act == 1) {
                    v0 = fmaxf(v0, 0.f) + log1pf(__expf(-fabsf(v0)));
                    v1 = fmaxf(v1, 0.f) + log1pf(__expf(-fabsf(v1)));
                }
                if (C) *(float2*)(C + (size_t)m * ldc + n) = make_float2(v0, v1);
                if (dohl) {
                    *(__half2*)(Chi + (size_t)m * ldhl + n) =
                        __halves2half2(__float2half_rn(v0), __float2half_rn(v1));
                }
            }
        }
    }
}

// ===================== weight transpose + fp16 hi/lo split =================
__global__ __launch_bounds__(256) void wconv_kernel(
    const float* __restrict__ W, __half* __restrict__ H,
    __half* __restrict__ L, int K, int N)
{
    __shared__ float s[32][33];
    const int tx = threadIdx.x, ty = threadIdx.y;
    const int n0 = blockIdx.x * 32, k0 = blockIdx.y * 32;
    #pragma unroll
    for (int j = 0; j < 4; j++)
        s[ty + j * 8][tx] = W[(size_t)(k0 + ty + j * 8) * N + n0 + tx];
    __syncthreads();
    #pragma unroll
    for (int j = 0; j < 4; j++) {
        float v = s[tx][ty + j * 8];
        __half h = __float2half_rn(v);
        size_t o = (size_t)(n0 + ty + j * 8) * K + k0 + tx;
        H[o] = h;
        L[o] = __float2half_rn(v - __half2float(h));
    }
}

// ===================== embeds: [B,T]->[T,B] gather + fp16 ==================
__global__ __launch_bounds__(256) void aconv_kernel(
    const float* __restrict__ X, __half* __restrict__ H)
{
    const int p = blockIdx.x;
    const int src = (p & 7) * NT + (p >> 3);
    const int c = threadIdx.x * 4;
    float4 v = *(const float4*)(X + (size_t)src * 1024 + c);
    __half2 h0 = __halves2half2(__float2half_rn(v.x), __float2half_rn(v.y));
    __half2 h1 = __halves2half2(__float2half_rn(v.z), __float2half_rn(v.w));
    ((__half2*)(H + (size_t)p * 1024 + c))[0] = h0;
    ((__half2*)(H + (size_t)p * 1024 + c))[1] = h1;
}

// ===================== stage 0: lnsilu(actions @ W_pre + b) -> fp32 ========
__global__ __launch_bounds__(256) void pre_kernel(
    const float* __restrict__ actions, const float* __restrict__ W_pre,
    const float* __restrict__ b_pre, const float* __restrict__ g_pre,
    const float* __restrict__ bb_pre, float* __restrict__ xout)
{
    int p = blockIdx.x;
    int t = p >> 3, b = p & 7;
    __shared__ float sa[32];
    __shared__ float red[2][8];
    int tid = threadIdx.x;
    if (tid < 32) sa[tid] = actions[(size_t)(b * NT + t) * 32 + tid];
    __syncthreads();
    int c0 = tid * 4;
    float4 acc = *(const float4*)(b_pre + c0);
    #pragma unroll 8
    for (int k = 0; k < 32; k++) {
        float a = sa[k];
        float4 wv = *(const float4*)(W_pre + (size_t)k * 1024 + c0);
        acc.x = fmaf(a, wv.x, acc.x); acc.y = fmaf(a, wv.y, acc.y);
        acc.z = fmaf(a, wv.z, acc.z); acc.w = fmaf(a, wv.w, acc.w);
    }
    float s  = acc.x + acc.y + acc.z + acc.w;
    float s2 = acc.x*acc.x + acc.y*acc.y + acc.z*acc.z + acc.w*acc.w;
    #pragma unroll
    for (int o = 16; o; o >>= 1) {
        s  += __shfl_xor_sync(0xffffffffu, s, o);
        s2 += __shfl_xor_sync(0xffffffffu, s2, o);
    }
    if ((tid & 31) == 0) { red[0][tid >> 5] = s; red[1][tid >> 5] = s2; }
    __syncthreads();
    if (tid == 0) {
        float a = 0.f, c = 0.f;
        for (int i = 0; i < 8; i++) { a += red[0][i]; c += red[1][i]; }
        red[0][0] = a; red[1][0] = c;
    }
    __syncthreads();
    float mean = red[0][0] * (1.f / 1024.f);
    float var  = red[1][0] * (1.f / 1024.f) - mean * mean;
    float inv  = rsqrtf(var + 1e-5f);
    float vv[4] = {acc.x, acc.y, acc.z, acc.w};
    #pragma unroll
    for (int j = 0; j < 4; j++) {
        int c = c0 + j;
        float xn = (vv[j] - mean) * inv * g_pre[c] + bb_pre[c];
        xn = xn * (1.f / (1.f + __expf(-xn)));
        xout[(size_t)p * 1024 + c] = xn;
    }
}

// ===================== LayerNorm (+opt silu) -> fp32 and/or fp16 ===========
__global__ __launch_bounds__(256) void ln_kernel(
    const float* __restrict__ X,
    const float* __restrict__ gma, const float* __restrict__ bta,
    float* __restrict__ Y, int ldy,
    __half* __restrict__ H, int dosilu)
{
    int p = blockIdx.x;
    int tid = threadIdx.x;
    int c0 = tid * 4;
    __shared__ float red[2][8];
    float4 v = *(const float4*)(X + (size_t)p * 1024 + c0);
    float s  = v.x + v.y + v.z + v.w;
    float s2 = v.x*v.x + v.y*v.y + v.z*v.z + v.w*v.w;
    #pragma unroll
    for (int o = 16; o; o >>= 1) {
        s  += __shfl_xor_sync(0xffffffffu, s, o);
        s2 += __shfl_xor_sync(0xffffffffu, s2, o);
    }
    if ((tid & 31) == 0) { red[0][tid >> 5] = s; red[1][tid >> 5] = s2; }
    __syncthreads();
    if (tid == 0) {
        float a = 0.f, c = 0.f;
        for (int i = 0; i < 8; i++) { a += red[0][i]; c += red[1][i]; }
        red[0][0] = a; red[1][0] = c;
    }
    __syncthreads();
    float mean = red[0][0] * (1.f / 1024.f);
    float var  = red[1][0] * (1.f / 1024.f) - mean * mean;
    float inv  = rsqrtf(var + 1e-5f);
    float vv[4] = {v.x, v.y, v.z, v.w};
    float xn[4];
    #pragma unroll
    for (int j = 0; j < 4; j++) {
        int c = c0 + j;
        float x = (vv[j] - mean) * inv * gma[c] + bta[c];
        if (dosilu) x = x * (1.f / (1.f + __expf(-x)));
        xn[j] = x;
    }
    if (Y) {
        #pragma unroll
        for (int j = 0; j < 4; j++) Y[(size_t)p * ldy + c0 + j] = xn[j];
    }
    if (H) {
        ((__half2*)(H + (size_t)p * 1024 + c0))[0] =
            __halves2half2(__float2half_rn(xn[0]), __float2half_rn(xn[1]));
        ((__half2*)(H + (size_t)p * 1024 + c0))[1] =
            __halves2half2(__float2half_rn(xn[2]), __float2half_rn(xn[3]));
    }
}

// ===================== fused B/C projection (N=32) =========================
__global__ __launch_bounds__(256, 2) void gemm_small2(
    const float* __restrict__ A, int lda,
    const float* __restrict__ WB, const float* __restrict__ WC,
    float* __restrict__ Cout, int K)
{
    __shared__ float As[16][128];
    __shared__ float Bs[16][36];
    const int tid = threadIdx.x;
    const int tx  = tid & 15;
    const int ty  = tid >> 4;
    const int bm  = blockIdx.y * 128;
    const int arow = tid >> 1;
    const int akk  = (tid & 1) * 8;
    const int brow = tid >> 4;
    const int bcol = (tid & 15) * 4;

    float acc[8][2];
    #pragma unroll
    for (int i = 0; i < 8; i++) { acc[i][0] = 0.f; acc[i][1] = 0.f; }

    for (int k0 = 0; k0 < K; k0 += 16) {
        const float* asrc = A + (size_t)(bm + arow) * lda + k0 + akk;
        float4 av0 = *(const float4*)asrc;
        float4 av1 = *(const float4*)(asrc + 4);
        if (bcol < 32) {
            #pragma unroll
            for (int j = 0; j < 4; j++) {
                int c = bcol + j;
                Bs[brow][c] = (c < 16) ? WB[(size_t)(k0 + brow) * 16 + c]
                                       : WC[(size_t)(k0 + brow) * 16 + c - 16];
            }
        }
        As[akk + 0][arow] = av0.x; As[akk + 1][arow] = av0.y;
        As[akk + 2][arow] = av0.z; As[akk + 3][arow] = av0.w;
        As[akk + 4][arow] = av1.x; As[akk + 5][arow] = av1.y;
        As[akk + 6][arow] = av1.z; As[akk + 7][arow] = av1.w;
        __syncthreads();
        #pragma unroll
        for (int kk = 0; kk < 16; kk++) {
            float4 a0 = *(const float4*)&As[kk][ty * 8];
            float4 a1 = *(const float4*)&As[kk][ty * 8 + 4];
            float b0 = Bs[kk][tx * 2], b1 = Bs[kk][tx * 2 + 1];
            float ar[8] = {a0.x, a0.y, a0.z, a0.w, a1.x, a1.y, a1.z, a1.w};
            #pragma unroll
            for (int i = 0; i < 8; i++) {
                acc[i][0] = fmaf(ar[i], b0, acc[i][0]);
                acc[i][1] = fmaf(ar[i], b1, acc[i][1]);
            }
        }
        __syncthreads();
    }
    #pragma unroll
    for (int i = 0; i < 8; i++) {
        int row = bm + ty * 8 + i;
        *(float2*)(Cout + (size_t)row * 32 + tx * 2) = make_float2(acc[i][0], acc[i][1]);
    }
}

// ===================== SSM scan ============================================
__global__ __launch_bounds__(256) void scan_kernel(
    const float* __restrict__ xz, const float* __restrict__ dt,
    const float* __restrict__ bc, const float* __restrict__ A_log,
    const float* __restrict__ Dp, float* __restrict__ y)
{
    int pair = blockIdx.x * 16 + (threadIdx.x >> 4);
    int n = threadIdx.x & 15;
    int b = pair >> 10;
    int d = pair & 1023;
    float A  = -__expf(A_log[d * 16 + n]);
    float Dd = Dp[d];
    float h = 0.f;
    for (int t = 0; t < NT; t++) {
        int p = t * NB + b;
        float dtv = dt[(size_t)p * 1024 + d];
        float xs  = xz[(size_t)p * 2048 + d];
        float g   = __expf(dtv * A);
        h = fmaf(g, h, dtv * xs * bc[(size_t)p * 32 + n]);
        float c = h * bc[(size_t)p * 32 + 16 + n];
        c += __shfl_xor_sync(0xffffffffu, c, 8, 16);
        c += __shfl_xor_sync(0xffffffffu, c, 4, 16);
        c += __shfl_xor_sync(0xffffffffu, c, 2, 16);
        c += __shfl_xor_sync(0xffffffffu, c, 1, 16);
        if (n == 0) {
            float gate = xz[(size_t)p * 2048 + 1024 + d];
            y[(size_t)p * 1024 + d] =
                (c + Dd * xs) * gate * (1.f / (1.f + __expf(-gate)));
        }
    }
}

// ===================== softmax + unimix + log ==============================
__global__ __launch_bounds__(256) void softmax_kernel(
    const float* __restrict__ post, float* __restrict__ out)
{
    int idx  = blockIdx.x * 8 + (threadIdx.x >> 5);
    int lane = threadIdx.x & 31;
    int p = idx >> 5, s = idx & 31;
    float v = post[(size_t)p * 1024 + s * 32 + lane];
    float m = v;
    #pragma unroll
    for (int o = 16; o; o >>= 1) m = fmaxf(m, __shfl_xor_sync(0xffffffffu, m, o));
    float e = __expf(v - m);
    float sum = e;
    #pragma unroll
    for (int o = 16; o; o >>= 1) sum += __shfl_xor_sync(0xffffffffu, sum, o);
    float prob = e / sum;
    out[(size_t)p * 3072 + 2048 + s * 32 + lane] =
        logf(0.99f * prob + 0.01f / 32.f + 1e-8f);
}

// ===========================================================================
extern "C" void kernel_launch(void* const* d_in, const int* in_sizes, int n_in,
                              void* d_out, int out_size)
{
    const float* actions = (const float*)d_in[0];
    const float* embeds  = (const float*)d_in[1];
    const float* W_pre   = (const float*)d_in[2];
    const float* b_pre   = (const float*)d_in[3];
    const float* g_pre   = (const float*)d_in[4];
    const float* bb_pre  = (const float*)d_in[5];
    const float* W_emb   = (const float*)d_in[6];
    const float* W_in    = (const float*)d_in[7];
    const float* b_in    = (const float*)d_in[8];
    const float* W_dt    = (const float*)d_in[9];
    const float* b_dt    = (const float*)d_in[10];
    const float* W_B     = (const float*)d_in[11];
    const float* W_C     = (const float*)d_in[12];
    const float* A_log   = (const float*)d_in[13];
    const float* Dp      = (const float*)d_in[14];
    const float* g_out   = (const float*)d_in[15];
    const float* b_out   = (const float*)d_in[16];
    const float* W_pr1   = (const float*)d_in[17];
    const float* b_pr1   = (const float*)d_in[18];
    const float* g_pr    = (const float*)d_in[19];
    const float* bb_pr   = (const float*)d_in[20];
    const float* W_pr2   = (const float*)d_in[21];
    const float* b_pr2   = (const float*)d_in[22];
    const float* W_po1   = (const float*)d_in[23];
    const float* b_po1   = (const float*)d_in[24];
    const float* g_po    = (const float*)d_in[25];
    const float* bb_po   = (const float*)d_in[26];
    const float* W_po2   = (const float*)d_in[27];
    const float* b_po2   = (const float*)d_in[28];
    float* out = (float*)d_out;

    float *ptmp, *pxz, *pdt, *pbc, *py;
    cudaGetSymbolAddress((void**)&ptmp, g_tmp);
    cudaGetSymbolAddress((void**)&pxz,  g_xz);
    cudaGetSymbolAddress((void**)&pdt,  g_dt);
    cudaGetSymbolAddress((void**)&pbc,  g_bc);
    cudaGetSymbolAddress((void**)&py,   g_y);
    __half *pemb, *px, *pss, *pde, *ph1;
    cudaGetSymbolAddress((void**)&pemb, a_emb);
    cudaGetSymbolAddress((void**)&px,  a_x);
    cudaGetSymbolAddress((void**)&pss, a_ssm);
    cudaGetSymbolAddress((void**)&pde, a_det);
    cudaGetSymbolAddress((void**)&ph1, a_h1);
    __half *wEh,*wEl,*wIh,*wIl,*wDh,*wDl,*wP1h,*wP1l,*wP2h,*wP2l,*wO1h,*wO1l,*wO2h,*wO2l;
    cudaGetSymbolAddress((void**)&wEh, wt_emb_h);  cudaGetSymbolAddress((void**)&wEl, wt_emb_l);
    cudaGetSymbolAddress((void**)&wIh, wt_in_h);   cudaGetSymbolAddress((void**)&wIl, wt_in_l);
    cudaGetSymbolAddress((void**)&wDh, wt_dt_h);   cudaGetSymbolAddress((void**)&wDl, wt_dt_l);
    cudaGetSymbolAddress((void**)&wP1h, wt_pr1_h); cudaGetSymbolAddress((void**)&wP1l, wt_pr1_l);
    cudaGetSymbolAddress((void**)&wP2h, wt_pr2_h); cudaGetSymbolAddress((void**)&wP2l, wt_pr2_l);
    cudaGetSymbolAddress((void**)&wO1h, wt_po1_h); cudaGetSymbolAddress((void**)&wO1l, wt_po1_l);
    cudaGetSymbolAddress((void**)&wO2h, wt_po2_h); cudaGetSymbolAddress((void**)&wO2l, wt_po2_l);

    cudaFuncSetAttribute(gemm_tc, cudaFuncAttributeMaxDynamicSharedMemorySize, GEMM_SMEM);

    dim3 blk(256);
    dim3 gblk(128);
    dim3 wb(32, 8);
    dim3 gN1(16, 32);   // N=1024
    dim3 gN2(32, 32);   // N=2048

    // launches 0-4 cheap, so ncu (-s 5 -c 1) captures the first gemm_tc
    pre_kernel<<<NTOK, blk>>>(actions, W_pre, b_pre, g_pre, bb_pre, ptmp);  // 0
    aconv_kernel<<<NTOK, blk>>>(embeds, pemb);                              // 1
    wconv_kernel<<<dim3(32, 32), wb>>>(W_emb, wEh, wEl, 1024, 1024);        // 2
    wconv_kernel<<<dim3(64, 32), wb>>>(W_in,  wIh, wIl, 1024, 2048);        // 3
    wconv_kernel<<<dim3(32, 32), wb>>>(W_dt,  wDh, wDl, 1024, 1024);        // 4

    // 5: x = emb @ W_emb + x_pre -> fp16
    gemm_tc<<<gN1, gblk, GEMM_SMEM>>>(pemb, 1024, pemb, wEh, wEl,
        nullptr, ptmp, 1024, nullptr, 0, px, 1024, 1024, 0);
    // 6: xz = x @ W_in + b_in -> fp32 + fp16 of first 1024 cols
    gemm_tc<<<gN2, gblk, GEMM_SMEM>>>(px, 1024, px, wIh, wIl,
        b_in, nullptr, 0, pxz, 2048, pss, 1024, 1024, 0);
    // 7: dt = softplus(x_ssm @ W_dt + b_dt)
    gemm_tc<<<gN1, gblk, GEMM_SMEM>>>(pss, 1024, pss, wDh, wDl,
        b_dt, nullptr, 0, pdt, 1024, nullptr, 0, 1024, 1);

    wconv_kernel<<<dim3(32, 32), wb>>>(W_pr1, wP1h, wP1l, 1024, 1024);      // 8
    wconv_kernel<<<dim3(32, 32), wb>>>(W_pr2, wP2h, wP2l, 1024, 1024);      // 9
    wconv_kernel<<<dim3(32, 64), wb>>>(W_po1, wO1h, wO1l, 2048, 1024);      // 10
    wconv_kernel<<<dim3(32, 32), wb>>>(W_po2, wO2h, wO2l, 1024, 1024);      // 11

    // 12: Bp|Cp
    gemm_small2<<<dim3(1, 32), blk>>>(pxz, 2048, W_B, W_C, pbc, 1024);
    // 13: scan
    scan_kernel<<<512, blk>>>(pxz, pdt, pbc, A_log, Dp, py);
    // 14: deter = LN(y) -> out[:,0:1024] + fp16
    ln_kernel<<<NTOK, blk>>>(py, g_out, b_out, out, 3072, pde, 0);

    // prior head
    gemm_tc<<<gN1, gblk, GEMM_SMEM>>>(pde, 1024, pde, wP1h, wP1l,
        b_pr1, nullptr, 0, ptmp, 1024, nullptr, 0, 1024, 0);
    ln_kernel<<<NTOK, blk>>>(ptmp, g_pr, bb_pr, nullptr, 0, ph1, 1);
    gemm_tc<<<gN1, gblk, GEMM_SMEM>>>(ph1, 1024, ph1, wP2h, wP2l,
        b_pr2, nullptr, 0, out + 1024, 3072, nullptr, 0, 1024, 0);

    // post head (K=2048: [deter | emb_t])
    gemm_tc<<<gN1, gblk, GEMM_SMEM>>>(pde, 1024, pemb, wO1h, wO1l,
        b_po1, nullptr, 0, ptmp, 1024, nullptr, 0, 2048, 0);
    ln_kernel<<<NTOK, blk>>>(ptmp, g_po, bb_po, nullptr, 0, ph1, 1);
    gemm_tc<<<gN1, gblk, GEMM_SMEM>>>(ph1, 1024, ph1, wO2h, wO2l,
        b_po2, nullptr, 0, ptmp, 1024, nullptr, 0, 1024, 0);

    // softmax -> out[:, 2048:3072]
    softmax_kernel<<<NTOK * 32 / 8, blk>>>(ptmp, out);
}

// round 7
// speedup vs baseline: 2.6231x; 1.1226x over previous
#include <cuda_runtime.h>
#include <cuda_fp16.h>
#include <math.h>
#include <stdint.h>

#define NB 8
#define NT 512
#define NTOK 4096

// ===================== helpers =============================================
__device__ __forceinline__ uint32_t smem_to_u32(const void* p) {
    uint32_t a;
    asm("{ .reg .u64 t; cvta.to.shared.u64 t, %1; cvt.u32.u64 %0, t; }" : "=r"(a) : "l"(p));
    return a;
}
__device__ __forceinline__ void cp16(uint32_t s, const void* g) {
    asm volatile("cp.async.cg.shared.global [%0], [%1], 16;" :: "r"(s), "l"(g));
}
#define CP_COMMIT() asm volatile("cp.async.commit_group;" ::: "memory")
#define CP_WAIT(n)  asm volatile("cp.async.wait_group %0;" :: "n"(n) : "memory")

__device__ __forceinline__ void ldm4(uint32_t* r, uint32_t addr) {
    asm volatile("ldmatrix.sync.aligned.m8n8.x4.shared.b16 {%0,%1,%2,%3}, [%4];"
        : "=r"(r[0]), "=r"(r[1]), "=r"(r[2]), "=r"(r[3]) : "r"(addr));
}
__device__ __forceinline__ void mma16816(float* c, const uint32_t* a, const uint32_t* b) {
    asm volatile("mma.sync.aligned.m16n8k16.row.col.f32.f16.f16.f32 "
        "{%0,%1,%2,%3}, {%4,%5,%6,%7}, {%8,%9}, {%0,%1,%2,%3};"
        : "+f"(c[0]), "+f"(c[1]), "+f"(c[2]), "+f"(c[3])
        : "r"(a[0]), "r"(a[1]), "r"(a[2]), "r"(a[3]), "r"(b[0]), "r"(b[1]));
}

// ===================== device scratch ======================================
__device__ float g_tmp[NTOK * 1024];
__device__ float g_xz [NTOK * 2048];
__device__ float g_dt [NTOK * 1024];
__device__ float g_bc [NTOK * 32];
__device__ float g_y  [NTOK * 1024];

// Activations: single fp16
__device__ __half a_emb[NTOK*1024];
__device__ __half a_x  [NTOK*1024];
__device__ __half a_ssm[NTOK*1024];
__device__ __half a_det[NTOK*1024];
__device__ __half a_h1 [NTOK*1024];

// Weights: fp16 hi/lo, transposed [N,K]
__device__ __half wt_emb_h[1024*1024], wt_emb_l[1024*1024];
__device__ __half wt_in_h [2048*1024], wt_in_l [2048*1024];
__device__ __half wt_dt_h [1024*1024], wt_dt_l [1024*1024];
__device__ __half wt_pr1_h[1024*1024], wt_pr1_l[1024*1024];
__device__ __half wt_pr2_h[1024*1024], wt_pr2_l[1024*1024];
__device__ __half wt_po1_h[1024*2048], wt_po1_l[1024*2048];
__device__ __half wt_po2_h[1024*1024], wt_po2_l[1024*1024];
// B|C packed [128,1024]; rows 32-127 stay zero (static zero-init)
__device__ __half wt_bc_h[128*1024], wt_bc_l[128*1024];

// ===================== HMMA GEMM ===========================================
// C[4096,N] = act( [A0|A1] @ Wt^T + bias ) (+addend), 2-pass fp16 W-split.
// Tile 128(M)x128(N), 4 warps (warp tile 64x64), BK=32, 3 stages, 2 CTAs/SM.
// Stage layout (80B-padded rows): A 128x80 @ +0, Bh 128x80 @ +10240,
// Bl 128x80 @ +20480. STG=30720.
#define STG_BYTES 30720
#define GEMM_SMEM (3*STG_BYTES + 512)

__global__ __launch_bounds__(128, 2) void gemm_tc(
    const __half* __restrict__ A0, int K0,
    const __half* __restrict__ A1,
    const __half* __restrict__ Bh, const __half* __restrict__ Bl,
    const float* __restrict__ bias,
    const float* __restrict__ addend, int ldadd,
    float* __restrict__ C, int ldc, int nvalid,
    __half* __restrict__ Chi, int ldhl,
    int K, int act)
{
    extern __shared__ char smem[];
    const uint32_t sb = smem_to_u32(smem);
    const int tid = threadIdx.x;
    const int lane = tid & 31, w = tid >> 5;
    const int bm = blockIdx.y * 128;
    const int bn = blockIdx.x * 128;
    const int wm = (w & 1) * 64;
    const int wn = (w >> 1) * 64;
    float* sbias = (float*)(smem + 3 * STG_BYTES);
    if (tid < 128) sbias[tid] = bias ? bias[bn + tid] : 0.f;

    const int nst = K >> 5;

    auto load_stage = [&](int s) {
        const uint32_t dst = sb + (uint32_t)(s % 3) * STG_BYTES;
        const int kglob = s << 5;
        #pragma unroll
        for (int j = 0; j < 12; j++) {
            int q = tid + (j << 7);
            int op = q >> 9;                 // 0:A 1:Bh 2:Bl
            int row = (q >> 2) & 127;
            int kc = q & 3;
            uint32_t d = dst + (uint32_t)op * 10240u + (uint32_t)(row * 80 + kc * 16);
            const __half* src;
            if (op == 0) {
                int col = kglob + kc * 8;
                const __half* base = A0;
                if (col >= K0) { base = A1; col -= K0; }
                src = base + (size_t)(bm + row) * 1024 + col;
            } else {
                src = ((op == 1) ? Bh : Bl) + (size_t)(bn + row) * K + kglob + kc * 8;
            }
            cp16(d, src);
        }
        CP_COMMIT();
    };

    load_stage(0); load_stage(1);

    float acc[4][8][4] = {};

    for (int s = 0; s < nst; s++) {
        CP_WAIT(1);
        __syncthreads();
        const uint32_t sA = sb + (uint32_t)(s % 3) * STG_BYTES;
        #pragma unroll
        for (int kk = 0; kk < 2; kk++) {
            const int kloc = kk * 16;
            uint32_t ah[4][4], bh[4][4], bl[4][4];
            #pragma unroll
            for (int mi = 0; mi < 4; mi++) {
                uint32_t ad = sA
                    + (uint32_t)((wm + mi * 16 + (lane & 15)) * 80)
                    + (uint32_t)((kloc + ((lane >> 4) << 3)) * 2);
                ldm4(ah[mi], ad);
            }
            #pragma unroll
            for (int nj = 0; nj < 4; nj++) {
                uint32_t bd = sA + 10240u
                    + (uint32_t)((wn + nj * 16 + ((lane >> 4) << 3) + (lane & 7)) * 80)
                    + (uint32_t)((kloc + ((lane >> 3) & 1) * 8) * 2);
                ldm4(bh[nj], bd);
                ldm4(bl[nj], bd + 10240u);
            }
            #pragma unroll
            for (int mi = 0; mi < 4; mi++)
                #pragma unroll
                for (int ns = 0; ns < 8; ns++) {
                    const uint32_t* bhp = &bh[ns >> 1][(ns & 1) * 2];
                    const uint32_t* blp = &bl[ns >> 1][(ns & 1) * 2];
                    mma16816(acc[mi][ns], ah[mi], bhp);
                    mma16816(acc[mi][ns], ah[mi], blp);
                }
        }
        // prefetch s+2 AFTER compute(s): buffer (s+2)%3 == (s-1)%3; barrier at
        // top of iter s guarantees all warps finished compute(s-1).
        if (s + 2 < nst) load_stage(s + 2); else CP_COMMIT();
    }

    // ---- epilogue ----
    const int g = lane >> 2, cc = (lane & 3) * 2;
    const bool dohl = (Chi != nullptr) && (bn < ldhl);
    #pragma unroll
    for (int mi = 0; mi < 4; mi++) {
        #pragma unroll
        for (int r = 0; r < 2; r++) {
            const int m = bm + wm + mi * 16 + g + r * 8;
            #pragma unroll
            for (int ns = 0; ns < 8; ns++) {
                const int ncol = wn + ns * 8 + cc;
                const int n = bn + ncol;
                float v0 = acc[mi][ns][r * 2 + 0] + sbias[ncol];
                float v1 = acc[mi][ns][r * 2 + 1] + sbias[ncol + 1];
                if (addend) {
                    float2 a = *(const float2*)(addend + (size_t)m * ldadd + n);
                    v0 += a.x; v1 += a.y;
                }
                if (act == 1) {
                    v0 = fmaxf(v0, 0.f) + log1pf(__expf(-fabsf(v0)));
                    v1 = fmaxf(v1, 0.f) + log1pf(__expf(-fabsf(v1)));
                }
                if (C && n < nvalid) *(float2*)(C + (size_t)m * ldc + n) = make_float2(v0, v1);
                if (dohl) {
                    *(__half2*)(Chi + (size_t)m * ldhl + n) =
                        __halves2half2(__float2half_rn(v0), __float2half_rn(v1));
                }
            }
        }
    }
}

// ===================== weight transpose + fp16 hi/lo split =================
__global__ __launch_bounds__(256) void wconv_kernel(
    const float* __restrict__ W, __half* __restrict__ H,
    __half* __restrict__ L, int K, int N)
{
    __shared__ float s[32][33];
    const int tx = threadIdx.x, ty = threadIdx.y;
    const int n0 = blockIdx.x * 32, k0 = blockIdx.y * 32;
    #pragma unroll
    for (int j = 0; j < 4; j++)
        s[ty + j * 8][tx] = W[(size_t)(k0 + ty + j * 8) * N + n0 + tx];
    __syncthreads();
    #pragma unroll
    for (int j = 0; j < 4; j++) {
        float v = s[tx][ty + j * 8];
        __half h = __float2half_rn(v);
        size_t o = (size_t)(n0 + ty + j * 8) * K + k0 + tx;
        H[o] = h;
        L[o] = __float2half_rn(v - __half2float(h));
    }
}

// ===================== pack W_B|W_C -> wt_bc rows 0..31 ====================
__global__ __launch_bounds__(256) void bcconv_kernel(
    const float* __restrict__ WB, const float* __restrict__ WC,
    __half* __restrict__ H, __half* __restrict__ L)
{
    int id = blockIdx.x * 256 + threadIdx.x;   // 32768 total
    int n = id & 31, k = id >> 5;
    float v = (n < 16) ? WB[k * 16 + n] : WC[k * 16 + (n - 16)];
    __half h = __float2half_rn(v);
    H[(size_t)n * 1024 + k] = h;
    L[(size_t)n * 1024 + k] = __float2half_rn(v - __half2float(h));
}

// ===================== embeds: [B,T]->[T,B] gather + fp16 ==================
__global__ __launch_bounds__(256) void aconv_kernel(
    const float* __restrict__ X, __half* __restrict__ H)
{
    const int p = blockIdx.x;
    const int src = (p & 7) * NT + (p >> 3);
    const int c = threadIdx.x * 4;
    float4 v = *(const float4*)(X + (size_t)src * 1024 + c);
    ((__half2*)(H + (size_t)p * 1024 + c))[0] =
        __halves2half2(__float2half_rn(v.x), __float2half_rn(v.y));
    ((__half2*)(H + (size_t)p * 1024 + c))[1] =
        __halves2half2(__float2half_rn(v.z), __float2half_rn(v.w));
}

// ===================== stage 0: lnsilu(actions @ W_pre + b) -> fp32 ========
__global__ __launch_bounds__(256) void pre_kernel(
    const float* __restrict__ actions, const float* __restrict__ W_pre,
    const float* __restrict__ b_pre, const float* __restrict__ g_pre,
    const float* __restrict__ bb_pre, float* __restrict__ xout)
{
    int p = blockIdx.x;
    int t = p >> 3, b = p & 7;
    __shared__ float sa[32];
    __shared__ float red[2][8];
    int tid = threadIdx.x;
    if (tid < 32) sa[tid] = actions[(size_t)(b * NT + t) * 32 + tid];
    __syncthreads();
    int c0 = tid * 4;
    float4 acc = *(const float4*)(b_pre + c0);
    #pragma unroll 8
    for (int k = 0; k < 32; k++) {
        float a = sa[k];
        float4 wv = *(const float4*)(W_pre + (size_t)k * 1024 + c0);
        acc.x = fmaf(a, wv.x, acc.x); acc.y = fmaf(a, wv.y, acc.y);
        acc.z = fmaf(a, wv.z, acc.z); acc.w = fmaf(a, wv.w, acc.w);
    }
    float s  = acc.x + acc.y + acc.z + acc.w;
    float s2 = acc.x*acc.x + acc.y*acc.y + acc.z*acc.z + acc.w*acc.w;
    #pragma unroll
    for (int o = 16; o; o >>= 1) {
        s  += __shfl_xor_sync(0xffffffffu, s, o);
        s2 += __shfl_xor_sync(0xffffffffu, s2, o);
    }
    if ((tid & 31) == 0) { red[0][tid >> 5] = s; red[1][tid >> 5] = s2; }
    __syncthreads();
    if (tid == 0) {
        float a = 0.f, c = 0.f;
        for (int i = 0; i < 8; i++) { a += red[0][i]; c += red[1][i]; }
        red[0][0] = a; red[1][0] = c;
    }
    __syncthreads();
    float mean = red[0][0] * (1.f / 1024.f);
    float var  = red[1][0] * (1.f / 1024.f) - mean * mean;
    float inv  = rsqrtf(var + 1e-5f);
    float vv[4] = {acc.x, acc.y, acc.z, acc.w};
    #pragma unroll
    for (int j = 0; j < 4; j++) {
        int c = c0 + j;
        float xn = (vv[j] - mean) * inv * g_pre[c] + bb_pre[c];
        xn = xn * (1.f / (1.f + __expf(-xn)));
        xout[(size_t)p * 1024 + c] = xn;
    }
}

// ===================== LayerNorm (+opt silu) -> fp32 and/or fp16 ===========
__global__ __launch_bounds__(256) void ln_kernel(
    const float* __restrict__ X,
    const float* __restrict__ gma, const float* __restrict__ bta,
    float* __restrict__ Y, int ldy,
    __half* __restrict__ H, int dosilu)
{
    int p = blockIdx.x;
    int tid = threadIdx.x;
    int c0 = tid * 4;
    __shared__ float red[2][8];
    float4 v = *(const float4*)(X + (size_t)p * 1024 + c0);
    float s  = v.x + v.y + v.z + v.w;
    float s2 = v.x*v.x + v.y*v.y + v.z*v.z + v.w*v.w;
    #pragma unroll
    for (int o = 16; o; o >>= 1) {
        s  += __shfl_xor_sync(0xffffffffu, s, o);
        s2 += __shfl_xor_sync(0xffffffffu, s2, o);
    }
    if ((tid & 31) == 0) { red[0][tid >> 5] = s; red[1][tid >> 5] = s2; }
    __syncthreads();
    if (tid == 0) {
        float a = 0.f, c = 0.f;
        for (int i = 0; i < 8; i++) { a += red[0][i]; c += red[1][i]; }
        red[0][0] = a; red[1][0] = c;
    }
    __syncthreads();
    float mean = red[0][0] * (1.f / 1024.f);
    float var  = red[1][0] * (1.f / 1024.f) - mean * mean;
    float inv  = rsqrtf(var + 1e-5f);
    float vv[4] = {v.x, v.y, v.z, v.w};
    float xn[4];
    #pragma unroll
    for (int j = 0; j < 4; j++) {
        int c = c0 + j;
        float x = (vv[j] - mean) * inv * gma[c] + bta[c];
        if (dosilu) x = x * (1.f / (1.f + __expf(-x)));
        xn[j] = x;
    }
    if (Y) {
        #pragma unroll
        for (int j = 0; j < 4; j++) Y[(size_t)p * ldy + c0 + j] = xn[j];
    }
    if (H) {
        ((__half2*)(H + (size_t)p * 1024 + c0))[0] =
            __halves2half2(__float2half_rn(xn[0]), __float2half_rn(xn[1]));
        ((__half2*)(H + (size_t)p * 1024 + c0))[1] =
            __halves2half2(__float2half_rn(xn[2]), __float2half_rn(xn[3]));
    }
}

// ===================== SSM scan ============================================
__global__ __launch_bounds__(256) void scan_kernel(
    const float* __restrict__ xz, const float* __restrict__ dt,
    const float* __restrict__ bc, const float* __restrict__ A_log,
    const float* __restrict__ Dp, float* __restrict__ y)
{
    int pair = blockIdx.x * 16 + (threadIdx.x >> 4);
    int n = threadIdx.x & 15;
    int b = pair >> 10;
    int d = pair & 1023;
    float A  = -__expf(A_log[d * 16 + n]);
    float Dd = Dp[d];
    float h = 0.f;
    #pragma unroll 2
    for (int t = 0; t < NT; t++) {
        int p = t * NB + b;
        float dtv = dt[(size_t)p * 1024 + d];
        float xs  = xz[(size_t)p * 2048 + d];
        float gate = xz[(size_t)p * 2048 + 1024 + d];
        float bv = bc[(size_t)p * 32 + n];
        float cv = bc[(size_t)p * 32 + 16 + n];
        float g = __expf(dtv * A);
        h = fmaf(g, h, dtv * xs * bv);
        float c = h * cv;
        c += __shfl_xor_sync(0xffffffffu, c, 8, 16);
        c += __shfl_xor_sync(0xffffffffu, c, 4, 16);
        c += __shfl_xor_sync(0xffffffffu, c, 2, 16);
        c += __shfl_xor_sync(0xffffffffu, c, 1, 16);
        if (n == 0) {
            y[(size_t)p * 1024 + d] =
                (c + Dd * xs) * gate * (1.f / (1.f + __expf(-gate)));
        }
    }
}

// ===================== softmax + unimix + log ==============================
__global__ __launch_bounds__(256) void softmax_kernel(
    const float* __restrict__ post, float* __restrict__ out)
{
    int idx  = blockIdx.x * 8 + (threadIdx.x >> 5);
    int lane = threadIdx.x & 31;
    int p = idx >> 5, s = idx & 31;
    float v = post[(size_t)p * 1024 + s * 32 + lane];
    float m = v;
    #pragma unroll
    for (int o = 16; o; o >>= 1) m = fmaxf(m, __shfl_xor_sync(0xffffffffu, m, o));
    float e = __expf(v - m);
    float sum = e;
    #pragma unroll
    for (int o = 16; o; o >>= 1) sum += __shfl_xor_sync(0xffffffffu, sum, o);
    float prob = e / sum;
    out[(size_t)p * 3072 + 2048 + s * 32 + lane] =
        logf(0.99f * prob + 0.01f / 32.f + 1e-8f);
}

// ===========================================================================
extern "C" void kernel_launch(void* const* d_in, const int* in_sizes, int n_in,
                              void* d_out, int out_size)
{
    const float* actions = (const float*)d_in[0];
    const float* embeds  = (const float*)d_in[1];
    const float* W_pre   = (const float*)d_in[2];
    const float* b_pre   = (const float*)d_in[3];
    const float* g_pre   = (const float*)d_in[4];
    const float* bb_pre  = (const float*)d_in[5];
    const float* W_emb   = (const float*)d_in[6];
    const float* W_in    = (const float*)d_in[7];
    const float* b_in    = (const float*)d_in[8];
    const float* W_dt    = (const float*)d_in[9];
    const float* b_dt    = (const float*)d_in[10];
    const float* W_B     = (const float*)d_in[11];
    const float* W_C     = (const float*)d_in[12];
    const float* A_log   = (const float*)d_in[13];
    const float* Dp      = (const float*)d_in[14];
    const float* g_out   = (const float*)d_in[15];
    const float* b_out   = (const float*)d_in[16];
    const float* W_pr1   = (const float*)d_in[17];
    const float* b_pr1   = (const float*)d_in[18];
    const float* g_pr    = (const float*)d_in[19];
    const float* bb_pr   = (const float*)d_in[20];
    const float* W_pr2   = (const float*)d_in[21];
    const float* b_pr2   = (const float*)d_in[22];
    const float* W_po1   = (const float*)d_in[23];
    const float* b_po1   = (const float*)d_in[24];
    const float* g_po    = (const float*)d_in[25];
    const float* bb_po   = (const float*)d_in[26];
    const float* W_po2   = (const float*)d_in[27];
    const float* b_po2   = (const float*)d_in[28];
    float* out = (float*)d_out;

    float *ptmp, *pxz, *pdt, *pbc, *py;
    cudaGetSymbolAddress((void**)&ptmp, g_tmp);
    cudaGetSymbolAddress((void**)&pxz,  g_xz);
    cudaGetSymbolAddress((void**)&pdt,  g_dt);
    cudaGetSymbolAddress((void**)&pbc,  g_bc);
    cudaGetSymbolAddress((void**)&py,   g_y);
    __half *pemb, *px, *pss, *pde, *ph1;
    cudaGetSymbolAddress((void**)&pemb, a_emb);
    cudaGetSymbolAddress((void**)&px,  a_x);
    cudaGetSymbolAddress((void**)&pss, a_ssm);
    cudaGetSymbolAddress((void**)&pde, a_det);
    cudaGetSymbolAddress((void**)&ph1, a_h1);
    __half *wEh,*wEl,*wIh,*wIl,*wDh,*wDl,*wP1h,*wP1l,*wP2h,*wP2l,*wO1h,*wO1l,*wO2h,*wO2l,*wBCh,*wBCl;
    cudaGetSymbolAddress((void**)&wEh, wt_emb_h);  cudaGetSymbolAddress((void**)&wEl, wt_emb_l);
    cudaGetSymbolAddress((void**)&wIh, wt_in_h);   cudaGetSymbolAddress((void**)&wIl, wt_in_l);
    cudaGetSymbolAddress((void**)&wDh, wt_dt_h);   cudaGetSymbolAddress((void**)&wDl, wt_dt_l);
    cudaGetSymbolAddress((void**)&wP1h, wt_pr1_h); cudaGetSymbolAddress((void**)&wP1l, wt_pr1_l);
    cudaGetSymbolAddress((void**)&wP2h, wt_pr2_h); cudaGetSymbolAddress((void**)&wP2l, wt_pr2_l);
    cudaGetSymbolAddress((void**)&wO1h, wt_po1_h); cudaGetSymbolAddress((void**)&wO1l, wt_po1_l);
    cudaGetSymbolAddress((void**)&wO2h, wt_po2_h); cudaGetSymbolAddress((void**)&wO2l, wt_po2_l);
    cudaGetSymbolAddress((void**)&wBCh, wt_bc_h);  cudaGetSymbolAddress((void**)&wBCl, wt_bc_l);

    cudaFuncSetAttribute(gemm_tc, cudaFuncAttributeMaxDynamicSharedMemorySize, GEMM_SMEM);

    const int BIG = 1 << 30;
    dim3 blk(256);
    dim3 gblk(128);
    dim3 wb(32, 8);
    dim3 gN1(8, 32);    // N=1024 (tile 128x128)
    dim3 gN2(16, 32);   // N=2048

    // interleave so any capture in index range 3..7 hits a gemm_tc
    aconv_kernel<<<NTOK, blk>>>(embeds, pemb);                              // 0
    pre_kernel<<<NTOK, blk>>>(actions, W_pre, b_pre, g_pre, bb_pre, ptmp);  // 1
    wconv_kernel<<<dim3(32, 32), wb>>>(W_emb, wEh, wEl, 1024, 1024);        // 2
    // 3: x = emb @ W_emb + x_pre -> fp16
    gemm_tc<<<gN1, gblk, GEMM_SMEM>>>(pemb, 1024, pemb, wEh, wEl,
        nullptr, ptmp, 1024, nullptr, 0, BIG, px, 1024, 1024, 0);
    wconv_kernel<<<dim3(64, 32), wb>>>(W_in,  wIh, wIl, 1024, 2048);        // 4
    // 5: xz = x @ W_in + b_in -> fp32 + fp16 of first 1024 cols
    gemm_tc<<<gN2, gblk, GEMM_SMEM>>>(px, 1024, px, wIh, wIl,
        b_in, nullptr, 0, pxz, 2048, BIG, pss, 1024, 1024, 0);
    wconv_kernel<<<dim3(32, 32), wb>>>(W_dt,  wDh, wDl, 1024, 1024);        // 6
    // 7: dt = softplus(x_ssm @ W_dt + b_dt)
    gemm_tc<<<gN1, gblk, GEMM_SMEM>>>(pss, 1024, pss, wDh, wDl,
        b_dt, nullptr, 0, pdt, 1024, BIG, nullptr, 0, 1024, 1);
    bcconv_kernel<<<128, blk>>>(W_B, W_C, wBCh, wBCl);                      // 8
    // 9: Bp|Cp = x_ssm @ [W_B|W_C]  (N-tile 128, store first 32 cols)
    gemm_tc<<<dim3(1, 32), gblk, GEMM_SMEM>>>(pss, 1024, pss, wBCh, wBCl,
        nullptr, nullptr, 0, pbc, 32, 32, nullptr, 0, 1024, 0);
    // 10: scan
    scan_kernel<<<512, blk>>>(pxz, pdt, pbc, A_log, Dp, py);
    // 11: deter = LN(y) -> out[:,0:1024] + fp16
    ln_kernel<<<NTOK, blk>>>(py, g_out, b_out, out, 3072, pde, 0);

    wconv_kernel<<<dim3(32, 32), wb>>>(W_pr1, wP1h, wP1l, 1024, 1024);
    wconv_kernel<<<dim3(32, 32), wb>>>(W_pr2, wP2h, wP2l, 1024, 1024);
    wconv_kernel<<<dim3(32, 64), wb>>>(W_po1, wO1h, wO1l, 2048, 1024);
    wconv_kernel<<<dim3(32, 32), wb>>>(W_po2, wO2h, wO2l, 1024, 1024);

    // prior head
    gemm_tc<<<gN1, gblk, GEMM_SMEM>>>(pde, 1024, pde, wP1h, wP1l,
        b_pr1, nullptr, 0, ptmp, 1024, BIG, nullptr, 0, 1024, 0);
    ln_kernel<<<NTOK, blk>>>(ptmp, g_pr, bb_pr, nullptr, 0, ph1, 1);
    gemm_tc<<<gN1, gblk, GEMM_SMEM>>>(ph1, 1024, ph1, wP2h, wP2l,
        b_pr2, nullptr, 0, out + 1024, 3072, BIG, nullptr, 0, 1024, 0);

    // post head (K=2048: [deter | emb_t])
    gemm_tc<<<gN1, gblk, GEMM_SMEM>>>(pde, 1024, pemb, wO1h, wO1l,
        b_po1, nullptr, 0, ptmp, 1024, BIG, nullptr, 0, 2048, 0);
    ln_kernel<<<NTOK, blk>>>(ptmp, g_po, bb_po, nullptr, 0, ph1, 1);
    gemm_tc<<<gN1, gblk, GEMM_SMEM>>>(ph1, 1024, ph1, wO2h, wO2l,
        b_po2, nullptr, 0, ptmp, 1024, BIG, nullptr, 0, 1024, 0);

    // softmax -> out[:, 2048:3072]
    softmax_kernel<<<NTOK * 32 / 8, blk>>>(ptmp, out);
}

// round 9
// speedup vs baseline: 3.2152x; 1.2257x over previous
#include <cuda_runtime.h>
#include <cuda_fp16.h>
#include <math.h>
#include <stdint.h>

#define NB 8
#define NT 512
#define NTOK 4096

// ===================== helpers =============================================
__device__ __forceinline__ uint32_t smem_to_u32(const void* p) {
    uint32_t a;
    asm("{ .reg .u64 t; cvta.to.shared.u64 t, %1; cvt.u32.u64 %0, t; }" : "=r"(a) : "l"(p));
    return a;
}
__device__ __forceinline__ void cp16(uint32_t s, const void* g) {
    asm volatile("cp.async.cg.shared.global [%0], [%1], 16;" :: "r"(s), "l"(g));
}
#define CP_COMMIT() asm volatile("cp.async.commit_group;" ::: "memory")
#define CP_WAIT(n)  asm volatile("cp.async.wait_group %0;" :: "n"(n) : "memory")

__device__ __forceinline__ void ldm4(uint32_t* r, uint32_t addr) {
    asm volatile("ldmatrix.sync.aligned.m8n8.x4.shared.b16 {%0,%1,%2,%3}, [%4];"
        : "=r"(r[0]), "=r"(r[1]), "=r"(r[2]), "=r"(r[3]) : "r"(addr));
}
__device__ __forceinline__ void mma16816(float* c, const uint32_t* a, const uint32_t* b) {
    asm volatile("mma.sync.aligned.m16n8k16.row.col.f32.f16.f16.f32 "
        "{%0,%1,%2,%3}, {%4,%5,%6,%7}, {%8,%9}, {%0,%1,%2,%3};"
        : "+f"(c[0]), "+f"(c[1]), "+f"(c[2]), "+f"(c[3])
        : "r"(a[0]), "r"(a[1]), "r"(a[2]), "r"(a[3]), "r"(b[0]), "r"(b[1]));
}

// ===================== device scratch ======================================
__device__ float g_tmp[NTOK * 1024];
__device__ float g_xz [NTOK * 2048];   // [x_ssm | silu(gate)]
__device__ float g_dt [NTOK * 1024];
__device__ float g_bc [NTOK * 32];
__device__ float g_y  [NTOK * 1024];

__device__ __half a_emb[NTOK*1024];
__device__ __half a_x  [NTOK*1024];
__device__ __half a_ssm[NTOK*1024];
__device__ __half a_det[NTOK*1024];
__device__ __half a_h1 [NTOK*1024];

__device__ __half wt_emb_h[1024*1024], wt_emb_l[1024*1024];
__device__ __half wt_in_h [2048*1024], wt_in_l [2048*1024];
__device__ __half wt_dt_h [1024*1024], wt_dt_l [1024*1024];
__device__ __half wt_pr1_h[1024*1024], wt_pr1_l[1024*1024];
__device__ __half wt_pr2_h[1024*1024], wt_pr2_l[1024*1024];
__device__ __half wt_po1_h[1024*2048], wt_po1_l[1024*2048];
__device__ __half wt_po2_h[1024*1024], wt_po2_l[1024*1024];
// B|C packed [128,1024]; rows 32-127 stay zero (static zero-init)
__device__ __half wt_bc_h[128*1024], wt_bc_l[128*1024];

// ===================== HMMA GEMM ===========================================
// C[4096,N] = act( [A0|A1] @ Wt^T + bias ) (+addend), 2-pass fp16 W-split.
// Tile 128(M)x128(N), 8 warps (warp tile 64x32), BK=32, 3 stages, 2 CTAs/SM.
// act: 0 none, 1 softplus (all cols), 2 silu on global cols >= 1024 only.
// Stage layout (80B-padded rows): A 128x80 @ +0, Bh @ +10240, Bl @ +20480.
#define STG_BYTES 30720
#define GEMM_SMEM (3*STG_BYTES + 512)

__global__ __launch_bounds__(256, 2) void gemm_tc(
    const __half* __restrict__ A0, int K0,
    const __half* __restrict__ A1,
    const __half* __restrict__ Bh, const __half* __restrict__ Bl,
    const float* __restrict__ bias,
    const float* __restrict__ addend, int ldadd,
    float* __restrict__ C, int ldc, int nvalid,
    __half* __restrict__ Chi, int ldhl,
    int K, int act)
{
    extern __shared__ char smem[];
    const uint32_t sb = smem_to_u32(smem);
    const int tid = threadIdx.x;
    const int lane = tid & 31, w = tid >> 5;
    const int bm = blockIdx.y * 128;
    const int bn = blockIdx.x * 128;
    const int wm = (w & 1) * 64;
    const int wn = (w >> 1) * 32;
    float* sbias = (float*)(smem + 3 * STG_BYTES);
    if (tid < 128) sbias[tid] = bias ? bias[bn + tid] : 0.f;

    const int nst = K >> 5;

    auto load_stage = [&](int s) {
        const uint32_t dst = sb + (uint32_t)(s % 3) * STG_BYTES;
        const int kglob = s << 5;
        #pragma unroll
        for (int j = 0; j < 6; j++) {
            int q = tid + (j << 8);
            int op = q >> 9;                 // 0:A 1:Bh 2:Bl
            int row = (q >> 2) & 127;
            int kc = q & 3;
            uint32_t d = dst + (uint32_t)op * 10240u + (uint32_t)(row * 80 + kc * 16);
            const __half* src;
            if (op == 0) {
                int col = kglob + kc * 8;
                const __half* base = A0;
                if (col >= K0) { base = A1; col -= K0; }
                src = base + (size_t)(bm + row) * 1024 + col;
            } else {
                src = ((op == 1) ? Bh : Bl) + (size_t)(bn + row) * K + kglob + kc * 8;
            }
            cp16(d, src);
        }
        CP_COMMIT();
    };

    load_stage(0); load_stage(1);

    float acc[4][4][4] = {};

    for (int s = 0; s < nst; s++) {
        CP_WAIT(1);
        __syncthreads();
        const uint32_t sA = sb + (uint32_t)(s % 3) * STG_BYTES;
        #pragma unroll
        for (int kk = 0; kk < 2; kk++) {
            const int kloc = kk * 16;
            uint32_t ah[4][4], bh[2][4], bl[2][4];
            #pragma unroll
            for (int mi = 0; mi < 4; mi++) {
                uint32_t ad = sA
                    + (uint32_t)((wm + mi * 16 + (lane & 15)) * 80)
                    + (uint32_t)((kloc + ((lane >> 4) << 3)) * 2);
                ldm4(ah[mi], ad);
            }
            #pragma unroll
            for (int nj = 0; nj < 2; nj++) {
                uint32_t bd = sA + 10240u
                    + (uint32_t)((wn + nj * 16 + ((lane >> 4) << 3) + (lane & 7)) * 80)
                    + (uint32_t)((kloc + ((lane >> 3) & 1) * 8) * 2);
                ldm4(bh[nj], bd);
                ldm4(bl[nj], bd + 10240u);
            }
            #pragma unroll
            for (int mi = 0; mi < 4; mi++)
                #pragma unroll
                for (int ns = 0; ns < 4; ns++) {
                    const uint32_t* bhp = &bh[ns >> 1][(ns & 1) * 2];
                    const uint32_t* blp = &bl[ns >> 1][(ns & 1) * 2];
                    mma16816(acc[mi][ns], ah[mi], bhp);
                    mma16816(acc[mi][ns], ah[mi], blp);
                }
        }
        // prefetch s+2 AFTER compute(s): buffer (s+2)%3 == (s-1)%3; the barrier
        // at top of iter s guarantees all warps finished compute(s-1).
        if (s + 2 < nst) load_stage(s + 2); else CP_COMMIT();
    }

    // ---- epilogue ----
    const int g = lane >> 2, cc = (lane & 3) * 2;
    const bool dohl = (Chi != nullptr) && (bn < ldhl);
    #pragma unroll
    for (int mi = 0; mi < 4; mi++) {
        #pragma unroll
        for (int r = 0; r < 2; r++) {
            const int m = bm + wm + mi * 16 + g + r * 8;
            #pragma unroll
            for (int ns = 0; ns < 4; ns++) {
                const int ncol = wn + ns * 8 + cc;
                const int n = bn + ncol;
                float v0 = acc[mi][ns][r * 2 + 0] + sbias[ncol];
                float v1 = acc[mi][ns][r * 2 + 1] + sbias[ncol + 1];
                if (addend) {
                    float2 a = *(const float2*)(addend + (size_t)m * ldadd + n);
                    v0 += a.x; v1 += a.y;
                }
                if (act == 1) {
                    v0 = fmaxf(v0, 0.f) + log1pf(__expf(-fabsf(v0)));
                    v1 = fmaxf(v1, 0.f) + log1pf(__expf(-fabsf(v1)));
                } else if (act == 2 && n >= 1024) {
                    v0 = v0 * (1.f / (1.f + __expf(-v0)));
                    v1 = v1 * (1.f / (1.f + __expf(-v1)));
                }
                if (C && n < nvalid) *(float2*)(C + (size_t)m * ldc + n) = make_float2(v0, v1);
                if (dohl) {
                    *(__half2*)(Chi + (size_t)m * ldhl + n) =
                        __halves2half2(__float2half_rn(v0), __float2half_rn(v1));
                }
            }
        }
    }
}

// ===================== weight transpose + fp16 hi/lo split =================
__global__ __launch_bounds__(256) void wconv_kernel(
    const float* __restrict__ W, __half* __restrict__ H,
    __half* __restrict__ L, int K, int N)
{
    __shared__ float s[32][33];
    const int tx = threadIdx.x, ty = threadIdx.y;
    const int n0 = blockIdx.x * 32, k0 = blockIdx.y * 32;
    #pragma unroll
    for (int j = 0; j < 4; j++)
        s[ty + j * 8][tx] = W[(size_t)(k0 + ty + j * 8) * N + n0 + tx];
    __syncthreads();
    #pragma unroll
    for (int j = 0; j < 4; j++) {
        float v = s[tx][ty + j * 8];
        __half h = __float2half_rn(v);
        size_t o = (size_t)(n0 + ty + j * 8) * K + k0 + tx;
        H[o] = h;
        L[o] = __float2half_rn(v - __half2float(h));
    }
}

// Batched variant: five 1024x1024 weights in one launch (blockIdx.z selects)
struct WSet { const float* W; __half* H; __half* L; };
struct WSets { WSet s[5]; };
__global__ __launch_bounds__(256) void wconv_multi(WSets ws)
{
    __shared__ float s[32][33];
    const WSet seg = ws.s[blockIdx.z];
    const int tx = threadIdx.x, ty = threadIdx.y;
    const int n0 = blockIdx.x * 32, k0 = blockIdx.y * 32;
    #pragma unroll
    for (int j = 0; j < 4; j++)
        s[ty + j * 8][tx] = seg.W[(size_t)(k0 + ty + j * 8) * 1024 + n0 + tx];
    __syncthreads();
    #pragma unroll
    for (int j = 0; j < 4; j++) {
        float v = s[tx][ty + j * 8];
        __half h = __float2half_rn(v);
        size_t o = (size_t)(n0 + ty + j * 8) * 1024 + k0 + tx;
        seg.H[o] = h;
        seg.L[o] = __float2half_rn(v - __half2float(h));
    }
}

// ===================== pack W_B|W_C -> wt_bc rows 0..31 ====================
__global__ __launch_bounds__(256) void bcconv_kernel(
    const float* __restrict__ WB, const float* __restrict__ WC,
    __half* __restrict__ H, __half* __restrict__ L)
{
    int id = blockIdx.x * 256 + threadIdx.x;   // 32768 total
    int n = id & 31, k = id >> 5;
    float v = (n < 16) ? WB[k * 16 + n] : WC[k * 16 + (n - 16)];
    __half h = __float2half_rn(v);
    H[(size_t)n * 1024 + k] = h;
    L[(size_t)n * 1024 + k] = __float2half_rn(v - __half2float(h));
}

// ===================== embeds: [B,T]->[T,B] gather + fp16 ==================
__global__ __launch_bounds__(256) void aconv_kernel(
    const float* __restrict__ X, __half* __restrict__ H)
{
    const int p = blockIdx.x;
    const int src = (p & 7) * NT + (p >> 3);
    const int c = threadIdx.x * 4;
    float4 v = *(const float4*)(X + (size_t)src * 1024 + c);
    ((__half2*)(H + (size_t)p * 1024 + c))[0] =
        __halves2half2(__float2half_rn(v.x), __float2half_rn(v.y));
    ((__half2*)(H + (size_t)p * 1024 + c))[1] =
        __halves2half2(__float2half_rn(v.z), __float2half_rn(v.w));
}

// ===================== stage 0: lnsilu(actions @ W_pre + b) -> fp32 ========
__global__ __launch_bounds__(256) void pre_kernel(
    const float* __restrict__ actions, const float* __restrict__ W_pre,
    const float* __restrict__ b_pre, const float* __restrict__ g_pre,
    const float* __restrict__ bb_pre, float* __restrict__ xout)
{
    int p = blockIdx.x;
    int t = p >> 3, b = p & 7;
    __shared__ float sa[32];
    __shared__ float red[2][8];
    int tid = threadIdx.x;
    if (tid < 32) sa[tid] = actions[(size_t)(b * NT + t) * 32 + tid];
    __syncthreads();
    int c0 = tid * 4;
    float4 acc = *(const float4*)(b_pre + c0);
    #pragma unroll 8
    for (int k = 0; k < 32; k++) {
        float a = sa[k];
        float4 wv = *(const float4*)(W_pre + (size_t)k * 1024 + c0);
        acc.x = fmaf(a, wv.x, acc.x); acc.y = fmaf(a, wv.y, acc.y);
        acc.z = fmaf(a, wv.z, acc.z); acc.w = fmaf(a, wv.w, acc.w);
    }
    float s  = acc.x + acc.y + acc.z + acc.w;
    float s2 = acc.x*acc.x + acc.y*acc.y + acc.z*acc.z + acc.w*acc.w;
    #pragma unroll
    for (int o = 16; o; o >>= 1) {
        s  += __shfl_xor_sync(0xffffffffu, s, o);
        s2 += __shfl_xor_sync(0xffffffffu, s2, o);
    }
    if ((tid & 31) == 0) { red[0][tid >> 5] = s; red[1][tid >> 5] = s2; }
    __syncthreads();
    if (tid == 0) {
        float a = 0.f, c = 0.f;
        for (int i = 0; i < 8; i++) { a += red[0][i]; c += red[1][i]; }
        red[0][0] = a; red[1][0] = c;
    }
    __syncthreads();
    float mean = red[0][0] * (1.f / 1024.f);
    float var  = red[1][0] * (1.f / 1024.f) - mean * mean;
    float inv  = rsqrtf(var + 1e-5f);
    float vv[4] = {acc.x, acc.y, acc.z, acc.w};
    #pragma unroll
    for (int j = 0; j < 4; j++) {
        int c = c0 + j;
        float xn = (vv[j] - mean) * inv * g_pre[c] + bb_pre[c];
        xn = xn * (1.f / (1.f + __expf(-xn)));
        xout[(size_t)p * 1024 + c] = xn;
    }
}

// ===================== LayerNorm (+opt silu) -> fp32 and/or fp16 ===========
__global__ __launch_bounds__(256) void ln_kernel(
    const float* __restrict__ X,
    const float* __restrict__ gma, const float* __restrict__ bta,
    float* __restrict__ Y, int ldy,
    __half* __restrict__ H, int dosilu)
{
    int p = blockIdx.x;
    int tid = threadIdx.x;
    int c0 = tid * 4;
    __shared__ float red[2][8];
    float4 v = *(const float4*)(X + (size_t)p * 1024 + c0);
    float s  = v.x + v.y + v.z + v.w;
    float s2 = v.x*v.x + v.y*v.y + v.z*v.z + v.w*v.w;
    #pragma unroll
    for (int o = 16; o; o >>= 1) {
        s  += __shfl_xor_sync(0xffffffffu, s, o);
        s2 += __shfl_xor_sync(0xffffffffu, s2, o);
    }
    if ((tid & 31) == 0) { red[0][tid >> 5] = s; red[1][tid >> 5] = s2; }
    __syncthreads();
    if (tid == 0) {
        float a = 0.f, c = 0.f;
        for (int i = 0; i < 8; i++) { a += red[0][i]; c += red[1][i]; }
        red[0][0] = a; red[1][0] = c;
    }
    __syncthreads();
    float mean = red[0][0] * (1.f / 1024.f);
    float var  = red[1][0] * (1.f / 1024.f) - mean * mean;
    float inv  = rsqrtf(var + 1e-5f);
    float vv[4] = {v.x, v.y, v.z, v.w};
    float xn[4];
    #pragma unroll
    for (int j = 0; j < 4; j++) {
        int c = c0 + j;
        float x = (vv[j] - mean) * inv * gma[c] + bta[c];
        if (dosilu) x = x * (1.f / (1.f + __expf(-x)));
        xn[j] = x;
    }
    if (Y) {
        #pragma unroll
        for (int j = 0; j < 4; j++) Y[(size_t)p * ldy + c0 + j] = xn[j];
    }
    if (H) {
        ((__half2*)(H + (size_t)p * 1024 + c0))[0] =
            __halves2half2(__float2half_rn(xn[0]), __float2half_rn(xn[1]));
        ((__half2*)(H + (size_t)p * 1024 + c0))[1] =
            __halves2half2(__float2half_rn(xn[2]), __float2half_rn(xn[3]));
    }
}

// ===================== SSM scan (gate pre-silu'd) ==========================
__global__ __launch_bounds__(256) void scan_kernel(
    const float* __restrict__ xz, const float* __restrict__ dt,
    const float* __restrict__ bc, const float* __restrict__ A_log,
    const float* __restrict__ Dp, float* __restrict__ y)
{
    int pair = blockIdx.x * 16 + (threadIdx.x >> 4);
    int n = threadIdx.x & 15;
    int b = pair >> 10;
    int d = pair & 1023;
    float A  = -__expf(A_log[d * 16 + n]);
    float Dd = Dp[d];
    float h = 0.f;
    #pragma unroll 2
    for (int t = 0; t < NT; t++) {
        int p = t * NB + b;
        float dtv = dt[(size_t)p * 1024 + d];
        float xs  = xz[(size_t)p * 2048 + d];
        float gate = xz[(size_t)p * 2048 + 1024 + d];   // silu already applied
        float bv = bc[(size_t)p * 32 + n];
        float cv = bc[(size_t)p * 32 + 16 + n];
        float g = __expf(dtv * A);
        h = fmaf(g, h, dtv * xs * bv);
        float c = h * cv;
        c += __shfl_xor_sync(0xffffffffu, c, 8, 16);
        c += __shfl_xor_sync(0xffffffffu, c, 4, 16);
        c += __shfl_xor_sync(0xffffffffu, c, 2, 16);
        c += __shfl_xor_sync(0xffffffffu, c, 1, 16);
        if (n == 0) {
            y[(size_t)p * 1024 + d] = (c + Dd * xs) * gate;
        }
    }
}

// ===================== softmax + unimix + log ==============================
__global__ __launch_bounds__(256) void softmax_kernel(
    const float* __restrict__ post, float* __restrict__ out)
{
    int idx  = blockIdx.x * 8 + (threadIdx.x >> 5);
    int lane = threadIdx.x & 31;
    int p = idx >> 5, s = idx & 31;
    float v = post[(size_t)p * 1024 + s * 32 + lane];
    float m = v;
    #pragma unroll
    for (int o = 16; o; o >>= 1) m = fmaxf(m, __shfl_xor_sync(0xffffffffu, m, o));
    float e = __expf(v - m);
    float sum = e;
    #pragma unroll
    for (int o = 16; o; o >>= 1) sum += __shfl_xor_sync(0xffffffffu, sum, o);
    float prob = e / sum;
    out[(size_t)p * 3072 + 2048 + s * 32 + lane] =
        logf(0.99f * prob + 0.01f / 32.f + 1e-8f);
}

// ===========================================================================
extern "C" void kernel_launch(void* const* d_in, const int* in_sizes, int n_in,
                              void* d_out, int out_size)
{
    const float* actions = (const float*)d_in[0];
    const float* embeds  = (const float*)d_in[1];
    const float* W_pre   = (const float*)d_in[2];
    const float* b_pre   = (const float*)d_in[3];
    const float* g_pre   = (const float*)d_in[4];
    const float* bb_pre  = (const float*)d_in[5];
    const float* W_emb   = (const float*)d_in[6];
    const float* W_in    = (const float*)d_in[7];
    const float* b_in    = (const float*)d_in[8];
    const float* W_dt    = (const float*)d_in[9];
    const float* b_dt    = (const float*)d_in[10];
    const float* W_B     = (const float*)d_in[11];
    const float* W_C     = (const float*)d_in[12];
    const float* A_log   = (const float*)d_in[13];
    const float* Dp      = (const float*)d_in[14];
    const float* g_out   = (const float*)d_in[15];
    const float* b_out   = (const float*)d_in[16];
    const float* W_pr1   = (const float*)d_in[17];
    const float* b_pr1   = (const float*)d_in[18];
    const float* g_pr    = (const float*)d_in[19];
    const float* bb_pr   = (const float*)d_in[20];
    const float* W_pr2   = (const float*)d_in[21];
    const float* b_pr2   = (const float*)d_in[22];
    const float* W_po1   = (const float*)d_in[23];
    const float* b_po1   = (const float*)d_in[24];
    const float* g_po    = (const float*)d_in[25];
    const float* bb_po   = (const float*)d_in[26];
    const float* W_po2   = (const float*)d_in[27];
    const float* b_po2   = (const float*)d_in[28];
    float* out = (float*)d_out;

    float *ptmp, *pxz, *pdt, *pbc, *py;
    cudaGetSymbolAddress((void**)&ptmp, g_tmp);
    cudaGetSymbolAddress((void**)&pxz,  g_xz);
    cudaGetSymbolAddress((void**)&pdt,  g_dt);
    cudaGetSymbolAddress((void**)&pbc,  g_bc);
    cudaGetSymbolAddress((void**)&py,   g_y);
    __half *pemb, *px, *pss, *pde, *ph1;
    cudaGetSymbolAddress((void**)&pemb, a_emb);
    cudaGetSymbolAddress((void**)&px,  a_x);
    cudaGetSymbolAddress((void**)&pss, a_ssm);
    cudaGetSymbolAddress((void**)&pde, a_det);
    cudaGetSymbolAddress((void**)&ph1, a_h1);
    __half *wEh,*wEl,*wIh,*wIl,*wDh,*wDl,*wP1h,*wP1l,*wP2h,*wP2l,*wO1h,*wO1l,*wO2h,*wO2l,*wBCh,*wBCl;
    cudaGetSymbolAddress((void**)&wEh, wt_emb_h);  cudaGetSymbolAddress((void**)&wEl, wt_emb_l);
    cudaGetSymbolAddress((void**)&wIh, wt_in_h);   cudaGetSymbolAddress((void**)&wIl, wt_in_l);
    cudaGetSymbolAddress((void**)&wDh, wt_dt_h);   cudaGetSymbolAddress((void**)&wDl, wt_dt_l);
    cudaGetSymbolAddress((void**)&wP1h, wt_pr1_h); cudaGetSymbolAddress((void**)&wP1l, wt_pr1_l);
    cudaGetSymbolAddress((void**)&wP2h, wt_pr2_h); cudaGetSymbolAddress((void**)&wP2l, wt_pr2_l);
    cudaGetSymbolAddress((void**)&wO1h, wt_po1_h); cudaGetSymbolAddress((void**)&wO1l, wt_po1_l);
    cudaGetSymbolAddress((void**)&wO2h, wt_po2_h); cudaGetSymbolAddress((void**)&wO2l, wt_po2_l);
    cudaGetSymbolAddress((void**)&wBCh, wt_bc_h);  cudaGetSymbolAddress((void**)&wBCl, wt_bc_l);

    cudaFuncSetAttribute(gemm_tc, cudaFuncAttributeMaxDynamicSharedMemorySize, GEMM_SMEM);

    const int BIG = 1 << 30;
    dim3 blk(256);
    dim3 gblk(256);
    dim3 wb(32, 8);
    dim3 gN1(8, 32);    // N=1024 (tile 128x128)
    dim3 gN2(16, 32);   // N=2048

    WSets ws;
    ws.s[0] = {W_emb, wEh, wEl};
    ws.s[1] = {W_dt,  wDh, wDl};
    ws.s[2] = {W_pr1, wP1h, wP1l};
    ws.s[3] = {W_pr2, wP2h, wP2l};
    ws.s[4] = {W_po2, wO2h, wO2l};

    aconv_kernel<<<NTOK, blk>>>(embeds, pemb);                              // 0
    pre_kernel<<<NTOK, blk>>>(actions, W_pre, b_pre, g_pre, bb_pre, ptmp);  // 1
    wconv_multi<<<dim3(32, 32, 5), wb>>>(ws);                               // 2
    wconv_kernel<<<dim3(64, 32), wb>>>(W_in, wIh, wIl, 1024, 2048);         // 3
    // 4: x = emb @ W_emb + x_pre -> fp16
    gemm_tc<<<gN1, gblk, GEMM_SMEM>>>(pemb, 1024, pemb, wEh, wEl,
        nullptr, ptmp, 1024, nullptr, 0, BIG, px, 1024, 1024, 0);
    // 5: xz = x @ W_in + b_in -> fp32 [x_ssm | silu(gate)] + fp16 x_ssm
    gemm_tc<<<gN2, gblk, GEMM_SMEM>>>(px, 1024, px, wIh, wIl,
        b_in, nullptr, 0, pxz, 2048, BIG, pss, 1024, 1024, 2);
    // 6: dt = softplus(x_ssm @ W_dt + b_dt)
    gemm_tc<<<gN1, gblk, GEMM_SMEM>>>(pss, 1024, pss, wDh, wDl,
        b_dt, nullptr, 0, pdt, 1024, BIG, nullptr, 0, 1024, 1);
    bcconv_kernel<<<128, blk>>>(W_B, W_C, wBCh, wBCl);                      // 7
    // 8: Bp|Cp = x_ssm @ [W_B|W_C]  (N-tile 128, store first 32 cols)
    gemm_tc<<<dim3(1, 32), gblk, GEMM_SMEM>>>(pss, 1024, pss, wBCh, wBCl,
        nullptr, nullptr, 0, pbc, 32, 32, nullptr, 0, 1024, 0);
    // 9: scan
    scan_kernel<<<512, blk>>>(pxz, pdt, pbc, A_log, Dp, py);
    // 10: deter = LN(y) -> out[:,0:1024] + fp16
    ln_kernel<<<NTOK, blk>>>(py, g_out, b_out, out, 3072, pde, 0);
    wconv_kernel<<<dim3(32, 64), wb>>>(W_po1, wO1h, wO1l, 2048, 1024);      // 11

    // prior head
    gemm_tc<<<gN1, gblk, GEMM_SMEM>>>(pde, 1024, pde, wP1h, wP1l,
        b_pr1, nullptr, 0, ptmp, 1024, BIG, nullptr, 0, 1024, 0);
    ln_kernel<<<NTOK, blk>>>(ptmp, g_pr, bb_pr, nullptr, 0, ph1, 1);
    gemm_tc<<<gN1, gblk, GEMM_SMEM>>>(ph1, 1024, ph1, wP2h, wP2l,
        b_pr2, nullptr, 0, out + 1024, 3072, BIG, nullptr, 0, 1024, 0);

    // post head (K=2048: [deter | emb_t])
    gemm_tc<<<gN1, gblk, GEMM_SMEM>>>(pde, 1024, pemb, wO1h, wO1l,
        b_po1, nullptr, 0, ptmp, 1024, BIG, nullptr, 0, 2048, 0);
    ln_kernel<<<NTOK, blk>>>(ptmp, g_po, bb_po, nullptr, 0, ph1, 1);
    gemm_tc<<<gN1, gblk, GEMM_SMEM>>>(ph1, 1024, ph1, wO2h, wO2l,
        b_po2, nullptr, 0, ptmp, 1024, BIG, nullptr, 0, 1024, 0);

    // softmax -> out[:, 2048:3072]
    softmax_kernel<<<NTOK * 32 / 8, blk>>>(ptmp, out);
}

// round 11
// speedup vs baseline: 3.3858x; 1.0531x over previous
#include <cuda_runtime.h>
#include <cuda_fp16.h>
#include <math.h>
#include <stdint.h>

#define NB 8
#define NT 512
#define NTOK 4096

// ===================== helpers =============================================
__device__ __forceinline__ uint32_t smem_to_u32(const void* p) {
    uint32_t a;
    asm("{ .reg .u64 t; cvta.to.shared.u64 t, %1; cvt.u32.u64 %0, t; }" : "=r"(a) : "l"(p));
    return a;
}
__device__ __forceinline__ void cp16(uint32_t s, const void* g) {
    asm volatile("cp.async.cg.shared.global [%0], [%1], 16;" :: "r"(s), "l"(g));
}
#define CP_COMMIT() asm volatile("cp.async.commit_group;" ::: "memory")
#define CP_WAIT(n)  asm volatile("cp.async.wait_group %0;" :: "n"(n) : "memory")

__device__ __forceinline__ void ldm4(uint32_t* r, uint32_t addr) {
    asm volatile("ldmatrix.sync.aligned.m8n8.x4.shared.b16 {%0,%1,%2,%3}, [%4];"
        : "=r"(r[0]), "=r"(r[1]), "=r"(r[2]), "=r"(r[3]) : "r"(addr));
}
__device__ __forceinline__ void mma16816(float* c, const uint32_t* a, const uint32_t* b) {
    asm volatile("mma.sync.aligned.m16n8k16.row.col.f32.f16.f16.f32 "
        "{%0,%1,%2,%3}, {%4,%5,%6,%7}, {%8,%9}, {%0,%1,%2,%3};"
        : "+f"(c[0]), "+f"(c[1]), "+f"(c[2]), "+f"(c[3])
        : "r"(a[0]), "r"(a[1]), "r"(a[2]), "r"(a[3]), "r"(b[0]), "r"(b[1]));
}

// ===================== device scratch ======================================
__device__ float g_tmp[NTOK * 1024];
__device__ float g_xz [NTOK * 2048];   // [x_ssm | silu(gate)]
__device__ float g_dt [NTOK * 1024];
__device__ float g_bc [NTOK * 32];     // interleaved: (B_n, C_n) pairs
__device__ float g_y  [NTOK * 1024];

__device__ __half a_emb[NTOK*1024];
__device__ __half a_x  [NTOK*1024];
__device__ __half a_ssm[NTOK*1024];
__device__ __half a_det[NTOK*1024];
__device__ __half a_h1 [NTOK*2048];    // [pr1 hidden | po1 hidden]
__device__ __half a_h2 [NTOK*2048];    // after lnsilu

__device__ __half wt_emb_h[1024*1024],  wt_emb_l[1024*1024];
__device__ __half wt_in_h [2048*1024],  wt_in_l [2048*1024];
__device__ __half wt_dtbc_h[1152*1024], wt_dtbc_l[1152*1024];  // dt rows 0-1023, B/C 1024-1055, zeros above
__device__ __half wt_pr1_h[1024*1024],  wt_pr1_l[1024*1024];
__device__ __half wt_pr2_h[1024*1024],  wt_pr2_l[1024*1024];
__device__ __half wt_po1_h[1024*2048],  wt_po1_l[1024*2048];   // [N=1024, K=2048]
__device__ __half wt_po2_h[1024*1024],  wt_po2_l[1024*1024];

// ===================== HMMA GEMM ===========================================
// Tile 128(M)x128(N), 8 warps (warp tile 64x32), BK=32, 3 stages, 2 CTAs/SM.
// act: 0 none, 1 softplus, 2 silu on global cols>=1024, 3 dt|bc split mode.
#define STG_BYTES 30720
#define GEMM_SMEM (3*STG_BYTES + 512)

struct GemmArgs {
    const __half* A0; int K0;          // A cols [0,K0) from A0, rest from A1
    const __half* A1;
    int lda;
    const __half* Bh; const __half* Bl;
    const float* bias; int biasN;
    const float* addend; int ldadd;
    float* C; int ldc; int nvalid;
    __half* Chi; int ldhl;
    float* bc;                          // act==3 target for cols 1024-1055
    int K; int act;
};

__device__ __forceinline__ void gemm_impl(const GemmArgs a, char* smem)
{
    const uint32_t sb = smem_to_u32(smem);
    const int tid = threadIdx.x;
    const int lane = tid & 31, w = tid >> 5;
    const int bm = blockIdx.y * 128;
    const int bn = blockIdx.x * 128;
    const int wm = (w & 1) * 64;
    const int wn = (w >> 1) * 32;
    float* sbias = (float*)(smem + 3 * STG_BYTES);
    if (tid < 128) sbias[tid] = (a.bias && bn + tid < a.biasN) ? a.bias[bn + tid] : 0.f;

    const int nst = a.K >> 5;

    auto load_stage = [&](int s) {
        const uint32_t dst = sb + (uint32_t)(s % 3) * STG_BYTES;
        const int kglob = s << 5;
        #pragma unroll
        for (int j = 0; j < 6; j++) {
            int q = tid + (j << 8);
            int op = q >> 9;                 // 0:A 1:Bh 2:Bl
            int row = (q >> 2) & 127;
            int kc = q & 3;
            uint32_t d = dst + (uint32_t)op * 10240u + (uint32_t)(row * 80 + kc * 16);
            const __half* src;
            if (op == 0) {
                int col = kglob + kc * 8;
                const __half* base = a.A0;
                if (col >= a.K0) { base = a.A1; col -= a.K0; }
                src = base + (size_t)(bm + row) * a.lda + col;
            } else {
                src = ((op == 1) ? a.Bh : a.Bl) + (size_t)(bn + row) * a.K + kglob + kc * 8;
            }
            cp16(d, src);
        }
        CP_COMMIT();
    };

    load_stage(0); load_stage(1);

    float acc[4][4][4] = {};

    for (int s = 0; s < nst; s++) {
        CP_WAIT(1);
        __syncthreads();
        const uint32_t sA = sb + (uint32_t)(s % 3) * STG_BYTES;
        #pragma unroll
        for (int kk = 0; kk < 2; kk++) {
            const int kloc = kk * 16;
            uint32_t ah[4][4], bh[2][4], bl[2][4];
            #pragma unroll
            for (int mi = 0; mi < 4; mi++) {
                uint32_t ad = sA
                    + (uint32_t)((wm + mi * 16 + (lane & 15)) * 80)
                    + (uint32_t)((kloc + ((lane >> 4) << 3)) * 2);
                ldm4(ah[mi], ad);
            }
            #pragma unroll
            for (int nj = 0; nj < 2; nj++) {
                uint32_t bd = sA + 10240u
                    + (uint32_t)((wn + nj * 16 + ((lane >> 4) << 3) + (lane & 7)) * 80)
                    + (uint32_t)((kloc + ((lane >> 3) & 1) * 8) * 2);
                ldm4(bh[nj], bd);
                ldm4(bl[nj], bd + 10240u);
            }
            #pragma unroll
            for (int mi = 0; mi < 4; mi++)
                #pragma unroll
                for (int ns = 0; ns < 4; ns++) {
                    const uint32_t* bhp = &bh[ns >> 1][(ns & 1) * 2];
                    const uint32_t* blp = &bl[ns >> 1][(ns & 1) * 2];
                    mma16816(acc[mi][ns], ah[mi], bhp);
                    mma16816(acc[mi][ns], ah[mi], blp);
                }
        }
        // prefetch s+2 AFTER compute(s): buffer (s+2)%3 == (s-1)%3; the barrier
        // at top of iter s guarantees all warps finished compute(s-1).
        if (s + 2 < nst) load_stage(s + 2); else CP_COMMIT();
    }

    // ---- epilogue ----
    const int g = lane >> 2, cc = (lane & 3) * 2;
    const bool dohl = (a.Chi != nullptr) && (bn < a.ldhl);
    #pragma unroll
    for (int mi = 0; mi < 4; mi++) {
        #pragma unroll
        for (int r = 0; r < 2; r++) {
            const int m = bm + wm + mi * 16 + g + r * 8;
            #pragma unroll
            for (int ns = 0; ns < 4; ns++) {
                const int ncol = wn + ns * 8 + cc;
                const int n = bn + ncol;
                float v0 = acc[mi][ns][r * 2 + 0] + sbias[ncol];
                float v1 = acc[mi][ns][r * 2 + 1] + sbias[ncol + 1];
                if (a.act == 3) {
                    if (n < 1024) {
                        v0 = fmaxf(v0, 0.f) + log1pf(__expf(-fabsf(v0)));
                        v1 = fmaxf(v1, 0.f) + log1pf(__expf(-fabsf(v1)));
                        *(float2*)(a.C + (size_t)m * a.ldc + n) = make_float2(v0, v1);
                    } else if (n < 1056) {
                        *(float2*)(a.bc + (size_t)m * 32 + (n - 1024)) = make_float2(v0, v1);
                    }
                    continue;
                }
                if (a.addend) {
                    float2 ad = *(const float2*)(a.addend + (size_t)m * a.ldadd + n);
                    v0 += ad.x; v1 += ad.y;
                }
                if (a.act == 1) {
                    v0 = fmaxf(v0, 0.f) + log1pf(__expf(-fabsf(v0)));
                    v1 = fmaxf(v1, 0.f) + log1pf(__expf(-fabsf(v1)));
                } else if (a.act == 2 && n >= 1024) {
                    v0 = v0 * (1.f / (1.f + __expf(-v0)));
                    v1 = v1 * (1.f / (1.f + __expf(-v1)));
                }
                if (a.C && n < a.nvalid)
                    *(float2*)(a.C + (size_t)m * a.ldc + n) = make_float2(v0, v1);
                if (dohl) {
                    *(__half2*)(a.Chi + (size_t)m * a.ldhl + n) =
                        __halves2half2(__float2half_rn(v0), __float2half_rn(v1));
                }
            }
        }
    }
}

__global__ __launch_bounds__(256, 2) void gemm_one(GemmArgs a) {
    extern __shared__ char smem[];
    gemm_impl(a, smem);
}
__global__ __launch_bounds__(256, 2) void gemm_dual(GemmArgs a0, GemmArgs a1) {
    extern __shared__ char smem[];
    gemm_impl(blockIdx.z ? a1 : a0, smem);
}

// ===================== batched weight transpose + fp16 split ===============
// Transposes a 1024(K-range) x 1024(N-range) block of W[srcK?,srcN] into
// Wt[N, dstK] at column offset koff. Read: W[(k0+r)*srcN + n], k local.
struct WSeg { const float* W; __half* H; __half* L; int srcN; int dstK; int koff; };
struct WSegs { WSeg s[9]; };
__global__ __launch_bounds__(256) void wconv_multi(WSegs ws)
{
    __shared__ float s[32][33];
    const WSeg seg = ws.s[blockIdx.z];
    const int tx = threadIdx.x, ty = threadIdx.y;
    const int n0 = blockIdx.x * 32, k0 = blockIdx.y * 32;
    #pragma unroll
    for (int j = 0; j < 4; j++)
        s[ty + j * 8][tx] = seg.W[(size_t)(k0 + ty + j * 8) * seg.srcN + n0 + tx];
    __syncthreads();
    #pragma unroll
    for (int j = 0; j < 4; j++) {
        float v = s[tx][ty + j * 8];
        __half h = __float2half_rn(v);
        size_t o = (size_t)(n0 + ty + j * 8) * seg.dstK + seg.koff + k0 + tx;
        seg.H[o] = h;
        seg.L[o] = __float2half_rn(v - __half2float(h));
    }
}

// ===================== pack W_B|W_C interleaved into wt_dtbc rows 1024+ ====
__global__ __launch_bounds__(256) void bcconv_kernel(
    const float* __restrict__ WB, const float* __restrict__ WC,
    __half* __restrict__ H, __half* __restrict__ L)
{
    int id = blockIdx.x * 256 + threadIdx.x;   // 32768 total
    int j = id & 31, k = id >> 5;
    float v = (j & 1) ? WC[k * 16 + (j >> 1)] : WB[k * 16 + (j >> 1)];
    __half h = __float2half_rn(v);
    size_t o = (size_t)(1024 + j) * 1024 + k;
    H[o] = h;
    L[o] = __float2half_rn(v - __half2float(h));
}

// ===================== embeds: [B,T]->[T,B] gather + fp16 ==================
__global__ __launch_bounds__(256) void aconv_kernel(
    const float* __restrict__ X, __half* __restrict__ H)
{
    const int p = blockIdx.x;
    const int src = (p & 7) * NT + (p >> 3);
    const int c = threadIdx.x * 4;
    float4 v = *(const float4*)(X + (size_t)src * 1024 + c);
    ((__half2*)(H + (size_t)p * 1024 + c))[0] =
        __halves2half2(__float2half_rn(v.x), __float2half_rn(v.y));
    ((__half2*)(H + (size_t)p * 1024 + c))[1] =
        __halves2half2(__float2half_rn(v.z), __float2half_rn(v.w));
}

// ===================== stage 0: lnsilu(actions @ W_pre + b) -> fp32 ========
__global__ __launch_bounds__(256) void pre_kernel(
    const float* __restrict__ actions, const float* __restrict__ W_pre,
    const float* __restrict__ b_pre, const float* __restrict__ g_pre,
    const float* __restrict__ bb_pre, float* __restrict__ xout)
{
    int p = blockIdx.x;
    int t = p >> 3, b = p & 7;
    __shared__ float sa[32];
    __shared__ float red[2][8];
    int tid = threadIdx.x;
    if (tid < 32) sa[tid] = actions[(size_t)(b * NT + t) * 32 + tid];
    __syncthreads();
    int c0 = tid * 4;
    float4 acc = *(const float4*)(b_pre + c0);
    #pragma unroll 8
    for (int k = 0; k < 32; k++) {
        float aa = sa[k];
        float4 wv = *(const float4*)(W_pre + (size_t)k * 1024 + c0);
        acc.x = fmaf(aa, wv.x, acc.x); acc.y = fmaf(aa, wv.y, acc.y);
        acc.z = fmaf(aa, wv.z, acc.z); acc.w = fmaf(aa, wv.w, acc.w);
    }
    float s  = acc.x + acc.y + acc.z + acc.w;
    float s2 = acc.x*acc.x + acc.y*acc.y + acc.z*acc.z + acc.w*acc.w;
    #pragma unroll
    for (int o = 16; o; o >>= 1) {
        s  += __shfl_xor_sync(0xffffffffu, s, o);
        s2 += __shfl_xor_sync(0xffffffffu, s2, o);
    }
    if ((tid & 31) == 0) { red[0][tid >> 5] = s; red[1][tid >> 5] = s2; }
    __syncthreads();
    if (tid == 0) {
        float aa = 0.f, c = 0.f;
        for (int i = 0; i < 8; i++) { aa += red[0][i]; c += red[1][i]; }
        red[0][0] = aa; red[1][0] = c;
    }
    __syncthreads();
    float mean = red[0][0] * (1.f / 1024.f);
    float var  = red[1][0] * (1.f / 1024.f) - mean * mean;
    float inv  = rsqrtf(var + 1e-5f);
    float vv[4] = {acc.x, acc.y, acc.z, acc.w};
    #pragma unroll
    for (int j = 0; j < 4; j++) {
        int c = c0 + j;
        float xn = (vv[j] - mean) * inv * g_pre[c] + bb_pre[c];
        xn = xn * (1.f / (1.f + __expf(-xn)));
        xout[(size_t)p * 1024 + c] = xn;
    }
}

// ===================== LayerNorm fp32-in -> fp32 + fp16 ====================
__global__ __launch_bounds__(256) void ln_kernel(
    const float* __restrict__ X,
    const float* __restrict__ gma, const float* __restrict__ bta,
    float* __restrict__ Y, int ldy,
    __half* __restrict__ H, int dosilu)
{
    int p = blockIdx.x;
    int tid = threadIdx.x;
    int c0 = tid * 4;
    __shared__ float red[2][8];
    float4 v = *(const float4*)(X + (size_t)p * 1024 + c0);
    float s  = v.x + v.y + v.z + v.w;
    float s2 = v.x*v.x + v.y*v.y + v.z*v.z + v.w*v.w;
    #pragma unroll
    for (int o = 16; o; o >>= 1) {
        s  += __shfl_xor_sync(0xffffffffu, s, o);
        s2 += __shfl_xor_sync(0xffffffffu, s2, o);
    }
    if ((tid & 31) == 0) { red[0][tid >> 5] = s; red[1][tid >> 5] = s2; }
    __syncthreads();
    if (tid == 0) {
        float aa = 0.f, c = 0.f;
        for (int i = 0; i < 8; i++) { aa += red[0][i]; c += red[1][i]; }
        red[0][0] = aa; red[1][0] = c;
    }
    __syncthreads();
    float mean = red[0][0] * (1.f / 1024.f);
    float var  = red[1][0] * (1.f / 1024.f) - mean * mean;
    float inv  = rsqrtf(var + 1e-5f);
    float vv[4] = {v.x, v.y, v.z, v.w};
    float xn[4];
    #pragma unroll
    for (int j = 0; j < 4; j++) {
        int c = c0 + j;
        float x = (vv[j] - mean) * inv * gma[c] + bta[c];
        if (dosilu) x = x * (1.f / (1.f + __expf(-x)));
        xn[j] = x;
    }
    if (Y) {
        #pragma unroll
        for (int j = 0; j < 4; j++) Y[(size_t)p * ldy + c0 + j] = xn[j];
    }
    if (H) {
        ((__half2*)(H + (size_t)p * 1024 + c0))[0] =
            __halves2half2(__float2half_rn(xn[0]), __float2half_rn(xn[1]));
        ((__half2*)(H + (size_t)p * 1024 + c0))[1] =
            __halves2half2(__float2half_rn(xn[2]), __float2half_rn(xn[3]));
    }
}

// ===================== batched head LN: fp16 in/out, +silu =================
__global__ __launch_bounds__(256) void ln16_kernel(
    const __half* __restrict__ Xin,
    const float* __restrict__ g0, const float* __restrict__ b0,
    const float* __restrict__ g1, const float* __restrict__ b1,
    __half* __restrict__ Yout)
{
    int p = blockIdx.x;
    int tok = p & (NTOK - 1);
    int sel = p >> 12;
    const float* gma = sel ? g1 : g0;
    const float* bta = sel ? b1 : b0;
    size_t base = (size_t)tok * 2048 + sel * 1024;
    int tid = threadIdx.x;
    int c0 = tid * 4;
    __shared__ float red[2][8];
    __half2 h0 = ((const __half2*)(Xin + base + c0))[0];
    __half2 h1 = ((const __half2*)(Xin + base + c0))[1];
    float vv[4] = {__half2float(h0.x), __half2float(h0.y),
                   __half2float(h1.x), __half2float(h1.y)};
    float s = vv[0] + vv[1] + vv[2] + vv[3];
    float s2 = vv[0]*vv[0] + vv[1]*vv[1] + vv[2]*vv[2] + vv[3]*vv[3];
    #pragma unroll
    for (int o = 16; o; o >>= 1) {
        s  += __shfl_xor_sync(0xffffffffu, s, o);
        s2 += __shfl_xor_sync(0xffffffffu, s2, o);
    }
    if ((tid & 31) == 0) { red[0][tid >> 5] = s; red[1][tid >> 5] = s2; }
    __syncthreads();
    if (tid == 0) {
        float aa = 0.f, c = 0.f;
        for (int i = 0; i < 8; i++) { aa += red[0][i]; c += red[1][i]; }
        red[0][0] = aa; red[1][0] = c;
    }
    __syncthreads();
    float mean = red[0][0] * (1.f / 1024.f);
    float var  = red[1][0] * (1.f / 1024.f) - mean * mean;
    float inv  = rsqrtf(var + 1e-5f);
    float xn[4];
    #pragma unroll
    for (int j = 0; j < 4; j++) {
        int c = c0 + j;
        float x = (vv[j] - mean) * inv * gma[c] + bta[c];
        xn[j] = x * (1.f / (1.f + __expf(-x)));
    }
    ((__half2*)(Yout + base + c0))[0] =
        __halves2half2(__float2half_rn(xn[0]), __float2half_rn(xn[1]));
    ((__half2*)(Yout + base + c0))[1] =
        __halves2half2(__float2half_rn(xn[2]), __float2half_rn(xn[3]));
}

// ===================== SSM scan (gate pre-silu'd; bc interleaved) ==========
__global__ __launch_bounds__(256) void scan_kernel(
    const float* __restrict__ xz, const float* __restrict__ dt,
    const float* __restrict__ bc, const float* __restrict__ A_log,
    const float* __restrict__ Dp, float* __restrict__ y)
{
    int pair = blockIdx.x * 16 + (threadIdx.x >> 4);
    int n = threadIdx.x & 15;
    int b = pair >> 10;
    int d = pair & 1023;
    float A  = -__expf(A_log[d * 16 + n]);
    float Dd = Dp[d];
    float h = 0.f;
    #pragma unroll 2
    for (int t = 0; t < NT; t++) {
        int p = t * NB + b;
        float dtv = dt[(size_t)p * 1024 + d];
        float xs  = xz[(size_t)p * 2048 + d];
        float gate = 0.f;
        if (n == 0) gate = xz[(size_t)p * 2048 + 1024 + d];
        float2 bc2 = *(const float2*)(bc + (size_t)p * 32 + 2 * n);
        float g = __expf(dtv * A);
        h = fmaf(g, h, dtv * xs * bc2.x);
        float c = h * bc2.y;
        c += __shfl_xor_sync(0xffffffffu, c, 8, 16);
        c += __shfl_xor_sync(0xffffffffu, c, 4, 16);
        c += __shfl_xor_sync(0xffffffffu, c, 2, 16);
        c += __shfl_xor_sync(0xffffffffu, c, 1, 16);
        if (n == 0) {
            y[(size_t)p * 1024 + d] = (c + Dd * xs) * gate;
        }
    }
}

// ===================== softmax + unimix + log ==============================
__global__ __launch_bounds__(256) void softmax_kernel(
    const float* __restrict__ post, float* __restrict__ out)
{
    int idx  = blockIdx.x * 8 + (threadIdx.x >> 5);
    int lane = threadIdx.x & 31;
    int p = idx >> 5, s = idx & 31;
    float v = post[(size_t)p * 1024 + s * 32 + lane];
    float m = v;
    #pragma unroll
    for (int o = 16; o; o >>= 1) m = fmaxf(m, __shfl_xor_sync(0xffffffffu, m, o));
    float e = __expf(v - m);
    float sum = e;
    #pragma unroll
    for (int o = 16; o; o >>= 1) sum += __shfl_xor_sync(0xffffffffu, sum, o);
    float prob = e / sum;
    out[(size_t)p * 3072 + 2048 + s * 32 + lane] =
        logf(0.99f * prob + 0.01f / 32.f + 1e-8f);
}

// ===========================================================================
extern "C" void kernel_launch(void* const* d_in, const int* in_sizes, int n_in,
                              void* d_out, int out_size)
{
    const float* actions = (const float*)d_in[0];
    const float* embeds  = (const float*)d_in[1];
    const float* W_pre   = (const float*)d_in[2];
    const float* b_pre   = (const float*)d_in[3];
    const float* g_pre   = (const float*)d_in[4];
    const float* bb_pre  = (const float*)d_in[5];
    const float* W_emb   = (const float*)d_in[6];
    const float* W_in    = (const float*)d_in[7];
    const float* b_in    = (const float*)d_in[8];
    const float* W_dt    = (const float*)d_in[9];
    const float* b_dt    = (const float*)d_in[10];
    const float* W_B     = (const float*)d_in[11];
    const float* W_C     = (const float*)d_in[12];
    const float* A_log   = (const float*)d_in[13];
    const float* Dp      = (const float*)d_in[14];
    const float* g_out   = (const float*)d_in[15];
    const float* b_out   = (const float*)d_in[16];
    const float* W_pr1   = (const float*)d_in[17];
    const float* b_pr1   = (const float*)d_in[18];
    const float* g_pr    = (const float*)d_in[19];
    const float* bb_pr   = (const float*)d_in[20];
    const float* W_pr2   = (const float*)d_in[21];
    const float* b_pr2   = (const float*)d_in[22];
    const float* W_po1   = (const float*)d_in[23];
    const float* b_po1   = (const float*)d_in[24];
    const float* g_po    = (const float*)d_in[25];
    const float* bb_po   = (const float*)d_in[26];
    const float* W_po2   = (const float*)d_in[27];
    const float* b_po2   = (const float*)d_in[28];
    float* out = (float*)d_out;

    float *ptmp, *pxz, *pdt, *pbc, *py;
    cudaGetSymbolAddress((void**)&ptmp, g_tmp);
    cudaGetSymbolAddress((void**)&pxz,  g_xz);
    cudaGetSymbolAddress((void**)&pdt,  g_dt);
    cudaGetSymbolAddress((void**)&pbc,  g_bc);
    cudaGetSymbolAddress((void**)&py,   g_y);
    __half *pemb, *px, *pss, *pde, *ph1, *ph2;
    cudaGetSymbolAddress((void**)&pemb, a_emb);
    cudaGetSymbolAddress((void**)&px,  a_x);
    cudaGetSymbolAddress((void**)&pss, a_ssm);
    cudaGetSymbolAddress((void**)&pde, a_det);
    cudaGetSymbolAddress((void**)&ph1, a_h1);
    cudaGetSymbolAddress((void**)&ph2, a_h2);
    __half *wEh,*wEl,*wIh,*wIl,*wDh,*wDl,*wP1h,*wP1l,*wP2h,*wP2l,*wO1h,*wO1l,*wO2h,*wO2l;
    cudaGetSymbolAddress((void**)&wEh, wt_emb_h);   cudaGetSymbolAddress((void**)&wEl, wt_emb_l);
    cudaGetSymbolAddress((void**)&wIh, wt_in_h);    cudaGetSymbolAddress((void**)&wIl, wt_in_l);
    cudaGetSymbolAddress((void**)&wDh, wt_dtbc_h);  cudaGetSymbolAddress((void**)&wDl, wt_dtbc_l);
    cudaGetSymbolAddress((void**)&wP1h, wt_pr1_h);  cudaGetSymbolAddress((void**)&wP1l, wt_pr1_l);
    cudaGetSymbolAddress((void**)&wP2h, wt_pr2_h);  cudaGetSymbolAddress((void**)&wP2l, wt_pr2_l);
    cudaGetSymbolAddress((void**)&wO1h, wt_po1_h);  cudaGetSymbolAddress((void**)&wO1l, wt_po1_l);
    cudaGetSymbolAddress((void**)&wO2h, wt_po2_h);  cudaGetSymbolAddress((void**)&wO2l, wt_po2_l);

    cudaFuncSetAttribute(gemm_one,  cudaFuncAttributeMaxDynamicSharedMemorySize, GEMM_SMEM);
    cudaFuncSetAttribute(gemm_dual, cudaFuncAttributeMaxDynamicSharedMemorySize, GEMM_SMEM);

    const int BIG = 1 << 30;
    dim3 blk(256);
    dim3 gblk(256);
    dim3 wb(32, 8);

    // WSeg: {W, H, L, srcN, dstK, koff}; each segment converts a 1024x1024 block.
    WSegs ws;
    ws.s[0] = {W_emb,               wEh,              wEl,              1024, 1024, 0};
    ws.s[1] = {W_dt,                wDh,              wDl,              1024, 1024, 0};
    ws.s[2] = {W_pr1,               wP1h,             wP1l,             1024, 1024, 0};
    ws.s[3] = {W_pr2,               wP2h,             wP2l,             1024, 1024, 0};
    ws.s[4] = {W_po2,               wO2h,             wO2l,             1024, 1024, 0};
    // W_in [K=1024, N=2048] -> Wt [2048, 1024]: split along N (rows of Wt)
    ws.s[5] = {W_in,                wIh,              wIl,              2048, 1024, 0};
    ws.s[6] = {W_in + 1024,         wIh + 1024*1024,  wIl + 1024*1024,  2048, 1024, 0};
    // W_po1 [K=2048, N=1024] -> Wt [1024, 2048]: split along K (cols of Wt)
    ws.s[7] = {W_po1,               wO1h,             wO1l,             1024, 2048, 0};
    ws.s[8] = {W_po1 + 1024*1024,   wO1h,             wO1l,             1024, 2048, 1024};

    // 0,1,2 then gemm at capture index 3
    aconv_kernel<<<NTOK, blk>>>(embeds, pemb);                              // 0
    pre_kernel<<<NTOK, blk>>>(actions, W_pre, b_pre, g_pre, bb_pre, ptmp);  // 1
    wconv_multi<<<dim3(32, 32, 9), wb>>>(ws);                               // 2

    // 3: x = emb @ W_emb + x_pre -> fp16
    GemmArgs ax = {pemb, 1024, pemb, 1024, wEh, wEl, nullptr, 0,
                   ptmp, 1024, nullptr, 0, 0, px, 1024, nullptr, 1024, 0};
    gemm_one<<<dim3(8, 32), gblk, GEMM_SMEM>>>(ax);

    bcconv_kernel<<<128, blk>>>(W_B, W_C, wDh, wDl);                        // 4

    // 5: xz = x @ W_in + b_in -> fp32 [x_ssm | silu(gate)] + fp16 x_ssm
    GemmArgs axz = {px, BIG, px, 1024, wIh, wIl, b_in, 2048,
                    nullptr, 0, pxz, 2048, BIG, pss, 1024, nullptr, 1024, 2};
    gemm_one<<<dim3(16, 32), gblk, GEMM_SMEM>>>(axz);

    // 6: dt|bc = x_ssm @ [W_dt | W_B,W_C interleaved]  (N=1152)
    GemmArgs adt = {pss, BIG, pss, 1024, wDh, wDl, b_dt, 1024,
                    nullptr, 0, pdt, 1024, 1024, nullptr, 0, pbc, 1024, 3};
    gemm_one<<<dim3(9, 32), gblk, GEMM_SMEM>>>(adt);

    // 7: scan
    scan_kernel<<<512, blk>>>(pxz, pdt, pbc, A_log, Dp, py);
    // 8: deter = LN(y) -> out[:,0:1024] + fp16
    ln_kernel<<<NTOK, blk>>>(py, g_out, b_out, out, 3072, pde, 0);

    // 9: dual pr1 / po1 -> a_h1 fp16 [4096,2048]
    GemmArgs ap1 = {pde, BIG, pde, 1024, wP1h, wP1l, b_pr1, 1024,
                    nullptr, 0, nullptr, 0, 0, ph1, 2048, nullptr, 1024, 0};
    GemmArgs ao1 = {pde, 1024, pemb, 1024, wO1h, wO1l, b_po1, 1024,
                    nullptr, 0, nullptr, 0, 0, ph1 + 1024, 2048, nullptr, 2048, 0};
    gemm_dual<<<dim3(8, 32, 2), gblk, GEMM_SMEM>>>(ap1, ao1);

    // 10: batched head lnsilu (fp16 in/out)
    ln16_kernel<<<2 * NTOK, blk>>>(ph1, g_pr, bb_pr, g_po, bb_po, ph2);

    // 11: dual pr2 -> out[:,1024:2048], po2 -> ptmp
    GemmArgs ap2 = {ph2, BIG, ph2, 2048, wP2h, wP2l, b_pr2, 1024,
                    nullptr, 0, out + 1024, 3072, BIG, nullptr, 0, nullptr, 1024, 0};
    GemmArgs ao2 = {ph2 + 1024, BIG, ph2 + 1024, 2048, wO2h, wO2l, b_po2, 1024,
                    nullptr, 0, ptmp, 1024, BIG, nullptr, 0, nullptr, 1024, 0};
    gemm_dual<<<dim3(8, 32, 2), gblk, GEMM_SMEM>>>(ap2, ao2);

    // 12: softmax -> out[:, 2048:3072]
    softmax_kernel<<<NTOK * 32 / 8, blk>>>(ptmp, out);
}

// round 12
// speedup vs baseline: 4.1546x; 1.2271x over previous
#include <cuda_runtime.h>
#include <cuda_fp16.h>
#include <math.h>
#include <stdint.h>

#define NB 8
#define NT 512
#define NTOK 4096

// ===================== helpers =============================================
__device__ __forceinline__ uint32_t smem_to_u32(const void* p) {
    uint32_t a;
    asm("{ .reg .u64 t; cvta.to.shared.u64 t, %1; cvt.u32.u64 %0, t; }" : "=r"(a) : "l"(p));
    return a;
}
__device__ __forceinline__ void cp16(uint32_t s, const void* g) {
    asm volatile("cp.async.cg.shared.global [%0], [%1], 16;" :: "r"(s), "l"(g));
}
#define CP_COMMIT() asm volatile("cp.async.commit_group;" ::: "memory")
#define CP_WAIT(n)  asm volatile("cp.async.wait_group %0;" :: "n"(n) : "memory")

__device__ __forceinline__ void ldm4(uint32_t* r, uint32_t addr) {
    asm volatile("ldmatrix.sync.aligned.m8n8.x4.shared.b16 {%0,%1,%2,%3}, [%4];"
        : "=r"(r[0]), "=r"(r[1]), "=r"(r[2]), "=r"(r[3]) : "r"(addr));
}
__device__ __forceinline__ void mma16816(float* c, const uint32_t* a, const uint32_t* b) {
    asm volatile("mma.sync.aligned.m16n8k16.row.col.f32.f16.f16.f32 "
        "{%0,%1,%2,%3}, {%4,%5,%6,%7}, {%8,%9}, {%0,%1,%2,%3};"
        : "+f"(c[0]), "+f"(c[1]), "+f"(c[2]), "+f"(c[3])
        : "r"(a[0]), "r"(a[1]), "r"(a[2]), "r"(a[3]), "r"(b[0]), "r"(b[1]));
}

// ===================== device scratch ======================================
__device__ float g_tmp[NTOK * 1024];
__device__ float g_xz [NTOK * 2048];   // [x_ssm | silu(gate)]
__device__ float g_dt [NTOK * 1024];
__device__ float g_bc [NTOK * 32];     // interleaved: (B_n, C_n) pairs
__device__ float g_y  [NTOK * 1024];

__device__ __half a_emb[NTOK*1024];
__device__ __half a_x  [NTOK*1024];
__device__ __half a_ssm[NTOK*1024];
__device__ __half a_det[NTOK*1024];
__device__ __half a_h1 [NTOK*2048];    // [pr1 hidden | po1 hidden]
__device__ __half a_h2 [NTOK*2048];    // after lnsilu

// Weights: single fp16, transposed [N,K]
__device__ __half wt_emb [1024*1024];
__device__ __half wt_in  [2048*1024];
__device__ __half wt_dtbc[1152*1024];  // dt rows 0-1023, B/C 1024-1055, zeros above
__device__ __half wt_pr1 [1024*1024];
__device__ __half wt_pr2 [1024*1024];
__device__ __half wt_po1 [1024*2048];  // [N=1024, K=2048]
__device__ __half wt_po2 [1024*1024];

// ===================== HMMA GEMM (single-pass fp16) ========================
// Tile 128(M)x128(N), 4 warps (warp tile 64x64), BK=32, 3 stages, 2 CTAs/SM.
// act: 0 none, 1 softplus, 2 silu on global cols>=1024, 3 dt|bc split mode.
// Stage layout (80B-padded rows): A 128x80 @ +0, B 128x80 @ +10240.
#define STG_BYTES 20480
#define GEMM_SMEM (3*STG_BYTES + 512)

struct GemmArgs {
    const __half* A0; int K0;          // A cols [0,K0) from A0, rest from A1
    const __half* A1;
    int lda;
    const __half* B;
    const float* bias; int biasN;
    const float* addend; int ldadd;
    float* C; int ldc; int nvalid;
    __half* Chi; int ldhl;
    float* bc;                          // act==3 target for cols 1024-1055
    int K; int act;
};

__device__ __forceinline__ void gemm_impl(const GemmArgs a, char* smem)
{
    const uint32_t sb = smem_to_u32(smem);
    const int tid = threadIdx.x;
    const int lane = tid & 31, w = tid >> 5;
    const int bm = blockIdx.y * 128;
    const int bn = blockIdx.x * 128;
    const int wm = (w & 1) * 64;
    const int wn = (w >> 1) * 64;
    float* sbias = (float*)(smem + 3 * STG_BYTES);
    if (tid < 128) sbias[tid] = (a.bias && bn + tid < a.biasN) ? a.bias[bn + tid] : 0.f;

    const int nst = a.K >> 5;

    auto load_stage = [&](int s) {
        const uint32_t dst = sb + (uint32_t)(s % 3) * STG_BYTES;
        const int kglob = s << 5;
        #pragma unroll
        for (int j = 0; j < 8; j++) {
            int q = tid + (j << 7);
            int op = q >> 9;                 // 0:A 1:B
            int row = (q >> 2) & 127;
            int kc = q & 3;
            uint32_t d = dst + (uint32_t)op * 10240u + (uint32_t)(row * 80 + kc * 16);
            const __half* src;
            if (op == 0) {
                int col = kglob + kc * 8;
                const __half* base = a.A0;
                if (col >= a.K0) { base = a.A1; col -= a.K0; }
                src = base + (size_t)(bm + row) * a.lda + col;
            } else {
                src = a.B + (size_t)(bn + row) * a.K + kglob + kc * 8;
            }
            cp16(d, src);
        }
        CP_COMMIT();
    };

    load_stage(0); load_stage(1);

    float acc[4][8][4] = {};

    for (int s = 0; s < nst; s++) {
        CP_WAIT(1);
        __syncthreads();
        const uint32_t sA = sb + (uint32_t)(s % 3) * STG_BYTES;
        #pragma unroll
        for (int kk = 0; kk < 2; kk++) {
            const int kloc = kk * 16;
            uint32_t ah[4][4], bb[4][4];
            #pragma unroll
            for (int mi = 0; mi < 4; mi++) {
                uint32_t ad = sA
                    + (uint32_t)((wm + mi * 16 + (lane & 15)) * 80)
                    + (uint32_t)((kloc + ((lane >> 4) << 3)) * 2);
                ldm4(ah[mi], ad);
            }
            #pragma unroll
            for (int nj = 0; nj < 4; nj++) {
                uint32_t bd = sA + 10240u
                    + (uint32_t)((wn + nj * 16 + ((lane >> 4) << 3) + (lane & 7)) * 80)
                    + (uint32_t)((kloc + ((lane >> 3) & 1) * 8) * 2);
                ldm4(bb[nj], bd);
            }
            #pragma unroll
            for (int mi = 0; mi < 4; mi++)
                #pragma unroll
                for (int ns = 0; ns < 8; ns++)
                    mma16816(acc[mi][ns], ah[mi], &bb[ns >> 1][(ns & 1) * 2]);
        }
        // prefetch s+2 AFTER compute(s): buffer (s+2)%3 == (s-1)%3; the barrier
        // at top of iter s guarantees all warps finished compute(s-1).
        if (s + 2 < nst) load_stage(s + 2); else CP_COMMIT();
    }

    // ---- epilogue ----
    const int g = lane >> 2, cc = (lane & 3) * 2;
    const bool dohl = (a.Chi != nullptr) && (bn < a.ldhl);
    #pragma unroll
    for (int mi = 0; mi < 4; mi++) {
        #pragma unroll
        for (int r = 0; r < 2; r++) {
            const int m = bm + wm + mi * 16 + g + r * 8;
            #pragma unroll
            for (int ns = 0; ns < 8; ns++) {
                const int ncol = wn + ns * 8 + cc;
                const int n = bn + ncol;
                float v0 = acc[mi][ns][r * 2 + 0] + sbias[ncol];
                float v1 = acc[mi][ns][r * 2 + 1] + sbias[ncol + 1];
                if (a.act == 3) {
                    if (n < 1024) {
                        v0 = fmaxf(v0, 0.f) + log1pf(__expf(-fabsf(v0)));
                        v1 = fmaxf(v1, 0.f) + log1pf(__expf(-fabsf(v1)));
                        *(float2*)(a.C + (size_t)m * a.ldc + n) = make_float2(v0, v1);
                    } else if (n < 1056) {
                        *(float2*)(a.bc + (size_t)m * 32 + (n - 1024)) = make_float2(v0, v1);
                    }
                    continue;
                }
                if (a.addend) {
                    float2 ad = *(const float2*)(a.addend + (size_t)m * a.ldadd + n);
                    v0 += ad.x; v1 += ad.y;
                }
                if (a.act == 1) {
                    v0 = fmaxf(v0, 0.f) + log1pf(__expf(-fabsf(v0)));
                    v1 = fmaxf(v1, 0.f) + log1pf(__expf(-fabsf(v1)));
                } else if (a.act == 2 && n >= 1024) {
                    v0 = v0 * (1.f / (1.f + __expf(-v0)));
                    v1 = v1 * (1.f / (1.f + __expf(-v1)));
                }
                if (a.C && n < a.nvalid)
                    *(float2*)(a.C + (size_t)m * a.ldc + n) = make_float2(v0, v1);
                if (dohl) {
                    *(__half2*)(a.Chi + (size_t)m * a.ldhl + n) =
                        __halves2half2(__float2half_rn(v0), __float2half_rn(v1));
                }
            }
        }
    }
}

__global__ __launch_bounds__(128, 2) void gemm_one(GemmArgs a) {
    extern __shared__ char smem[];
    gemm_impl(a, smem);
}
__global__ __launch_bounds__(128, 2) void gemm_dual(GemmArgs a0, GemmArgs a1) {
    extern __shared__ char smem[];
    gemm_impl(blockIdx.z ? a1 : a0, smem);
}

// ===================== batched weight transpose -> fp16 ====================
// Transposes a 1024(K) x 1024(N) block of W[.., srcN] into Wt[N, dstK]+koff.
struct WSeg { const float* W; __half* H; int srcN; int dstK; int koff; };
struct WSegs { WSeg s[9]; };
__global__ __launch_bounds__(256) void wconv_multi(WSegs ws)
{
    __shared__ float s[32][33];
    const WSeg seg = ws.s[blockIdx.z];
    const int tx = threadIdx.x, ty = threadIdx.y;
    const int n0 = blockIdx.x * 32, k0 = blockIdx.y * 32;
    #pragma unroll
    for (int j = 0; j < 4; j++)
        s[ty + j * 8][tx] = seg.W[(size_t)(k0 + ty + j * 8) * seg.srcN + n0 + tx];
    __syncthreads();
    #pragma unroll
    for (int j = 0; j < 4; j++) {
        float v = s[tx][ty + j * 8];
        size_t o = (size_t)(n0 + ty + j * 8) * seg.dstK + seg.koff + k0 + tx;
        seg.H[o] = __float2half_rn(v);
    }
}

// ===================== pack W_B|W_C interleaved into wt_dtbc rows 1024+ ====
__global__ __launch_bounds__(256) void bcconv_kernel(
    const float* __restrict__ WB, const float* __restrict__ WC,
    __half* __restrict__ H)
{
    int id = blockIdx.x * 256 + threadIdx.x;   // 32768 total
    int j = id & 31, k = id >> 5;
    float v = (j & 1) ? WC[k * 16 + (j >> 1)] : WB[k * 16 + (j >> 1)];
    H[(size_t)(1024 + j) * 1024 + k] = __float2half_rn(v);
}

// ===================== embeds: [B,T]->[T,B] gather + fp16 ==================
__global__ __launch_bounds__(256) void aconv_kernel(
    const float* __restrict__ X, __half* __restrict__ H)
{
    const int p = blockIdx.x;
    const int src = (p & 7) * NT + (p >> 3);
    const int c = threadIdx.x * 4;
    float4 v = *(const float4*)(X + (size_t)src * 1024 + c);
    ((__half2*)(H + (size_t)p * 1024 + c))[0] =
        __halves2half2(__float2half_rn(v.x), __float2half_rn(v.y));
    ((__half2*)(H + (size_t)p * 1024 + c))[1] =
        __halves2half2(__float2half_rn(v.z), __float2half_rn(v.w));
}

// ===================== stage 0: lnsilu(actions @ W_pre + b) -> fp32 ========
__global__ __launch_bounds__(256) void pre_kernel(
    const float* __restrict__ actions, const float* __restrict__ W_pre,
    const float* __restrict__ b_pre, const float* __restrict__ g_pre,
    const float* __restrict__ bb_pre, float* __restrict__ xout)
{
    int p = blockIdx.x;
    int t = p >> 3, b = p & 7;
    __shared__ float sa[32];
    __shared__ float red[2][8];
    int tid = threadIdx.x;
    if (tid < 32) sa[tid] = actions[(size_t)(b * NT + t) * 32 + tid];
    __syncthreads();
    int c0 = tid * 4;
    float4 acc = *(const float4*)(b_pre + c0);
    #pragma unroll 8
    for (int k = 0; k < 32; k++) {
        float aa = sa[k];
        float4 wv = *(const float4*)(W_pre + (size_t)k * 1024 + c0);
        acc.x = fmaf(aa, wv.x, acc.x); acc.y = fmaf(aa, wv.y, acc.y);
        acc.z = fmaf(aa, wv.z, acc.z); acc.w = fmaf(aa, wv.w, acc.w);
    }
    float s  = acc.x + acc.y + acc.z + acc.w;
    float s2 = acc.x*acc.x + acc.y*acc.y + acc.z*acc.z + acc.w*acc.w;
    #pragma unroll
    for (int o = 16; o; o >>= 1) {
        s  += __shfl_xor_sync(0xffffffffu, s, o);
        s2 += __shfl_xor_sync(0xffffffffu, s2, o);
    }
    if ((tid & 31) == 0) { red[0][tid >> 5] = s; red[1][tid >> 5] = s2; }
    __syncthreads();
    if (tid == 0) {
        float aa = 0.f, c = 0.f;
        for (int i = 0; i < 8; i++) { aa += red[0][i]; c += red[1][i]; }
        red[0][0] = aa; red[1][0] = c;
    }
    __syncthreads();
    float mean = red[0][0] * (1.f / 1024.f);
    float var  = red[1][0] * (1.f / 1024.f) - mean * mean;
    float inv  = rsqrtf(var + 1e-5f);
    float vv[4] = {acc.x, acc.y, acc.z, acc.w};
    #pragma unroll
    for (int j = 0; j < 4; j++) {
        int c = c0 + j;
        float xn = (vv[j] - mean) * inv * g_pre[c] + bb_pre[c];
        xn = xn * (1.f / (1.f + __expf(-xn)));
        xout[(size_t)p * 1024 + c] = xn;
    }
}

// ===================== LayerNorm fp32-in -> fp32 + fp16 ====================
__global__ __launch_bounds__(256) void ln_kernel(
    const float* __restrict__ X,
    const float* __restrict__ gma, const float* __restrict__ bta,
    float* __restrict__ Y, int ldy,
    __half* __restrict__ H, int dosilu)
{
    int p = blockIdx.x;
    int tid = threadIdx.x;
    int c0 = tid * 4;
    __shared__ float red[2][8];
    float4 v = *(const float4*)(X + (size_t)p * 1024 + c0);
    float s  = v.x + v.y + v.z + v.w;
    float s2 = v.x*v.x + v.y*v.y + v.z*v.z + v.w*v.w;
    #pragma unroll
    for (int o = 16; o; o >>= 1) {
        s  += __shfl_xor_sync(0xffffffffu, s, o);
        s2 += __shfl_xor_sync(0xffffffffu, s2, o);
    }
    if ((tid & 31) == 0) { red[0][tid >> 5] = s; red[1][tid >> 5] = s2; }
    __syncthreads();
    if (tid == 0) {
        float aa = 0.f, c = 0.f;
        for (int i = 0; i < 8; i++) { aa += red[0][i]; c += red[1][i]; }
        red[0][0] = aa; red[1][0] = c;
    }
    __syncthreads();
    float mean = red[0][0] * (1.f / 1024.f);
    float var  = red[1][0] * (1.f / 1024.f) - mean * mean;
    float inv  = rsqrtf(var + 1e-5f);
    float vv[4] = {v.x, v.y, v.z, v.w};
    float xn[4];
    #pragma unroll
    for (int j = 0; j < 4; j++) {
        int c = c0 + j;
        float x = (vv[j] - mean) * inv * gma[c] + bta[c];
        if (dosilu) x = x * (1.f / (1.f + __expf(-x)));
        xn[j] = x;
    }
    if (Y) {
        #pragma unroll
        for (int j = 0; j < 4; j++) Y[(size_t)p * ldy + c0 + j] = xn[j];
    }
    if (H) {
        ((__half2*)(H + (size_t)p * 1024 + c0))[0] =
            __halves2half2(__float2half_rn(xn[0]), __float2half_rn(xn[1]));
        ((__half2*)(H + (size_t)p * 1024 + c0))[1] =
            __halves2half2(__float2half_rn(xn[2]), __float2half_rn(xn[3]));
    }
}

// ===================== batched head LN: fp16 in/out, +silu =================
__global__ __launch_bounds__(256) void ln16_kernel(
    const __half* __restrict__ Xin,
    const float* __restrict__ g0, const float* __restrict__ b0,
    const float* __restrict__ g1, const float* __restrict__ b1,
    __half* __restrict__ Yout)
{
    int p = blockIdx.x;
    int tok = p & (NTOK - 1);
    int sel = p >> 12;
    const float* gma = sel ? g1 : g0;
    const float* bta = sel ? b1 : b0;
    size_t base = (size_t)tok * 2048 + sel * 1024;
    int tid = threadIdx.x;
    int c0 = tid * 4;
    __shared__ float red[2][8];
    __half2 h0 = ((const __half2*)(Xin + base + c0))[0];
    __half2 h1 = ((const __half2*)(Xin + base + c0))[1];
    float vv[4] = {__half2float(h0.x), __half2float(h0.y),
                   __half2float(h1.x), __half2float(h1.y)};
    float s = vv[0] + vv[1] + vv[2] + vv[3];
    float s2 = vv[0]*vv[0] + vv[1]*vv[1] + vv[2]*vv[2] + vv[3]*vv[3];
    #pragma unroll
    for (int o = 16; o; o >>= 1) {
        s  += __shfl_xor_sync(0xffffffffu, s, o);
        s2 += __shfl_xor_sync(0xffffffffu, s2, o);
    }
    if ((tid & 31) == 0) { red[0][tid >> 5] = s; red[1][tid >> 5] = s2; }
    __syncthreads();
    if (tid == 0) {
        float aa = 0.f, c = 0.f;
        for (int i = 0; i < 8; i++) { aa += red[0][i]; c += red[1][i]; }
        red[0][0] = aa; red[1][0] = c;
    }
    __syncthreads();
    float mean = red[0][0] * (1.f / 1024.f);
    float var  = red[1][0] * (1.f / 1024.f) - mean * mean;
    float inv  = rsqrtf(var + 1e-5f);
    float xn[4];
    #pragma unroll
    for (int j = 0; j < 4; j++) {
        int c = c0 + j;
        float x = (vv[j] - mean) * inv * gma[c] + bta[c];
        xn[j] = x * (1.f / (1.f + __expf(-x)));
    }
    ((__half2*)(Yout + base + c0))[0] =
        __halves2half2(__float2half_rn(xn[0]), __float2half_rn(xn[1]));
    ((__half2*)(Yout + base + c0))[1] =
        __halves2half2(__float2half_rn(xn[2]), __float2half_rn(xn[3]));
}

// ===================== SSM scan (gate pre-silu'd; bc interleaved) ==========
__global__ __launch_bounds__(256) void scan_kernel(
    const float* __restrict__ xz, const float* __restrict__ dt,
    const float* __restrict__ bc, const float* __restrict__ A_log,
    const float* __restrict__ Dp, float* __restrict__ y)
{
    int pair = blockIdx.x * 16 + (threadIdx.x >> 4);
    int n = threadIdx.x & 15;
    int b = pair >> 10;
    int d = pair & 1023;
    float A  = -__expf(A_log[d * 16 + n]);
    float Dd = Dp[d];
    float h = 0.f;
    #pragma unroll 2
    for (int t = 0; t < NT; t++) {
        int p = t * NB + b;
        float dtv = dt[(size_t)p * 1024 + d];
        float xs  = xz[(size_t)p * 2048 + d];
        float gate = 0.f;
        if (n == 0) gate = xz[(size_t)p * 2048 + 1024 + d];
        float2 bc2 = *(const float2*)(bc + (size_t)p * 32 + 2 * n);
        float g = __expf(dtv * A);
        h = fmaf(g, h, dtv * xs * bc2.x);
        float c = h * bc2.y;
        c += __shfl_xor_sync(0xffffffffu, c, 8, 16);
        c += __shfl_xor_sync(0xffffffffu, c, 4, 16);
        c += __shfl_xor_sync(0xffffffffu, c, 2, 16);
        c += __shfl_xor_sync(0xffffffffu, c, 1, 16);
        if (n == 0) {
            y[(size_t)p * 1024 + d] = (c + Dd * xs) * gate;
        }
    }
}

// ===================== softmax + unimix + log ==============================
__global__ __launch_bounds__(256) void softmax_kernel(
    const float* __restrict__ post, float* __restrict__ out)
{
    int idx  = blockIdx.x * 8 + (threadIdx.x >> 5);
    int lane = threadIdx.x & 31;
    int p = idx >> 5, s = idx & 31;
    float v = post[(size_t)p * 1024 + s * 32 + lane];
    float m = v;
    #pragma unroll
    for (int o = 16; o; o >>= 1) m = fmaxf(m, __shfl_xor_sync(0xffffffffu, m, o));
    float e = __expf(v - m);
    float sum = e;
    #pragma unroll
    for (int o = 16; o; o >>= 1) sum += __shfl_xor_sync(0xffffffffu, sum, o);
    float prob = e / sum;
    out[(size_t)p * 3072 + 2048 + s * 32 + lane] =
        logf(0.99f * prob + 0.01f / 32.f + 1e-8f);
}

// ===========================================================================
extern "C" void kernel_launch(void* const* d_in, const int* in_sizes, int n_in,
                              void* d_out, int out_size)
{
    const float* actions = (const float*)d_in[0];
    const float* embeds  = (const float*)d_in[1];
    const float* W_pre   = (const float*)d_in[2];
    const float* b_pre   = (const float*)d_in[3];
    const float* g_pre   = (const float*)d_in[4];
    const float* bb_pre  = (const float*)d_in[5];
    const float* W_emb   = (const float*)d_in[6];
    const float* W_in    = (const float*)d_in[7];
    const float* b_in    = (const float*)d_in[8];
    const float* W_dt    = (const float*)d_in[9];
    const float* b_dt    = (const float*)d_in[10];
    const float* W_B     = (const float*)d_in[11];
    const float* W_C     = (const float*)d_in[12];
    const float* A_log   = (const float*)d_in[13];
    const float* Dp      = (const float*)d_in[14];
    const float* g_out   = (const float*)d_in[15];
    const float* b_out   = (const float*)d_in[16];
    const float* W_pr1   = (const float*)d_in[17];
    const float* b_pr1   = (const float*)d_in[18];
    const float* g_pr    = (const float*)d_in[19];
    const float* bb_pr   = (const float*)d_in[20];
    const float* W_pr2   = (const float*)d_in[21];
    const float* b_pr2   = (const float*)d_in[22];
    const float* W_po1   = (const float*)d_in[23];
    const float* b_po1   = (const float*)d_in[24];
    const float* g_po    = (const float*)d_in[25];
    const float* bb_po   = (const float*)d_in[26];
    const float* W_po2   = (const float*)d_in[27];
    const float* b_po2   = (const float*)d_in[28];
    float* out = (float*)d_out;

    float *ptmp, *pxz, *pdt, *pbc, *py;
    cudaGetSymbolAddress((void**)&ptmp, g_tmp);
    cudaGetSymbolAddress((void**)&pxz,  g_xz);
    cudaGetSymbolAddress((void**)&pdt,  g_dt);
    cudaGetSymbolAddress((void**)&pbc,  g_bc);
    cudaGetSymbolAddress((void**)&py,   g_y);
    __half *pemb, *px, *pss, *pde, *ph1, *ph2;
    cudaGetSymbolAddress((void**)&pemb, a_emb);
    cudaGetSymbolAddress((void**)&px,  a_x);
    cudaGetSymbolAddress((void**)&pss, a_ssm);
    cudaGetSymbolAddress((void**)&pde, a_det);
    cudaGetSymbolAddress((void**)&ph1, a_h1);
    cudaGetSymbolAddress((void**)&ph2, a_h2);
    __half *wE, *wI, *wD, *wP1, *wP2, *wO1, *wO2;
    cudaGetSymbolAddress((void**)&wE, wt_emb);
    cudaGetSymbolAddress((void**)&wI, wt_in);
    cudaGetSymbolAddress((void**)&wD, wt_dtbc);
    cudaGetSymbolAddress((void**)&wP1, wt_pr1);
    cudaGetSymbolAddress((void**)&wP2, wt_pr2);
    cudaGetSymbolAddress((void**)&wO1, wt_po1);
    cudaGetSymbolAddress((void**)&wO2, wt_po2);

    cudaFuncSetAttribute(gemm_one,  cudaFuncAttributeMaxDynamicSharedMemorySize, GEMM_SMEM);
    cudaFuncSetAttribute(gemm_dual, cudaFuncAttributeMaxDynamicSharedMemorySize, GEMM_SMEM);

    const int BIG = 1 << 30;
    dim3 blk(256);
    dim3 gblk(128);
    dim3 wb(32, 8);

    // WSeg: {W, H, srcN, dstK, koff}; each segment converts a 1024x1024 block.
    WSegs ws;
    ws.s[0] = {W_emb,             wE,              1024, 1024, 0};
    ws.s[1] = {W_dt,              wD,              1024, 1024, 0};
    ws.s[2] = {W_pr1,             wP1,             1024, 1024, 0};
    ws.s[3] = {W_pr2,             wP2,             1024, 1024, 0};
    ws.s[4] = {W_po2,             wO2,             1024, 1024, 0};
    // W_in [K=1024, N=2048] -> Wt [2048, 1024]: split along N (rows of Wt)
    ws.s[5] = {W_in,              wI,              2048, 1024, 0};
    ws.s[6] = {W_in + 1024,       wI + 1024*1024,  2048, 1024, 0};
    // W_po1 [K=2048, N=1024] -> Wt [1024, 2048]: split along K (cols of Wt)
    ws.s[7] = {W_po1,             wO1,             1024, 2048, 0};
    ws.s[8] = {W_po1 + 1024*1024, wO1,             1024, 2048, 1024};

    // 0,1,2 then gemm at capture index 3
    aconv_kernel<<<NTOK, blk>>>(embeds, pemb);                              // 0
    pre_kernel<<<NTOK, blk>>>(actions, W_pre, b_pre, g_pre, bb_pre, ptmp);  // 1
    wconv_multi<<<dim3(32, 32, 9), wb>>>(ws);                               // 2

    // 3: x = emb @ W_emb + x_pre -> fp16
    GemmArgs ax = {pemb, 1024, pemb, 1024, wE, nullptr, 0,
                   ptmp, 1024, nullptr, 0, 0, px, 1024, nullptr, 1024, 0};
    gemm_one<<<dim3(8, 32), gblk, GEMM_SMEM>>>(ax);

    bcconv_kernel<<<128, blk>>>(W_B, W_C, wD);                              // 4

    // 5: xz = x @ W_in + b_in -> fp32 [x_ssm | silu(gate)] + fp16 x_ssm
    GemmArgs axz = {px, BIG, px, 1024, wI, b_in, 2048,
                    nullptr, 0, pxz, 2048, BIG, pss, 1024, nullptr, 1024, 2};
    gemm_one<<<dim3(16, 32), gblk, GEMM_SMEM>>>(axz);

    // 6: dt|bc = x_ssm @ [W_dt | W_B,W_C interleaved]  (N=1152)
    GemmArgs adt = {pss, BIG, pss, 1024, wD, b_dt, 1024,
                    nullptr, 0, pdt, 1024, 1024, nullptr, 0, pbc, 1024, 3};
    gemm_one<<<dim3(9, 32), gblk, GEMM_SMEM>>>(adt);

    // 7: scan
    scan_kernel<<<512, blk>>>(pxz, pdt, pbc, A_log, Dp, py);
    // 8: deter = LN(y) -> out[:,0:1024] + fp16
    ln_kernel<<<NTOK, blk>>>(py, g_out, b_out, out, 3072, pde, 0);

    // 9: dual pr1 / po1 -> a_h1 fp16 [4096,2048]
    GemmArgs ap1 = {pde, BIG, pde, 1024, wP1, b_pr1, 1024,
                    nullptr, 0, nullptr, 0, 0, ph1, 2048, nullptr, 1024, 0};
    GemmArgs ao1 = {pde, 1024, pemb, 1024, wO1, b_po1, 1024,
                    nullptr, 0, nullptr, 0, 0, ph1 + 1024, 2048, nullptr, 2048, 0};
    gemm_dual<<<dim3(8, 32, 2), gblk, GEMM_SMEM>>>(ap1, ao1);

    // 10: batched head lnsilu (fp16 in/out)
    ln16_kernel<<<2 * NTOK, blk>>>(ph1, g_pr, bb_pr, g_po, bb_po, ph2);

    // 11: dual pr2 -> out[:,1024:2048], po2 -> ptmp
    GemmArgs ap2 = {ph2, BIG, ph2, 2048, wP2, b_pr2, 1024,
                    nullptr, 0, out + 1024, 3072, BIG, nullptr, 0, nullptr, 1024, 0};
    GemmArgs ao2 = {ph2 + 1024, BIG, ph2 + 1024, 2048, wO2, b_po2, 1024,
                    nullptr, 0, ptmp, 1024, BIG, nullptr, 0, nullptr, 1024, 0};
    gemm_dual<<<dim3(8, 32, 2), gblk, GEMM_SMEM>>>(ap2, ao2);

    // 12: softmax -> out[:, 2048:3072]
    softmax_kernel<<<NTOK * 32 / 8, blk>>>(ptmp, out);
}

// round 13
// speedup vs baseline: 4.1765x; 1.0053x over previous
#include <cuda_runtime.h>
#include <cuda_fp16.h>
#include <math.h>
#include <stdint.h>

#define NB 8
#define NT 512
#define NTOK 4096

// ===================== helpers =============================================
__device__ __forceinline__ uint32_t smem_to_u32(const void* p) {
    uint32_t a;
    asm("{ .reg .u64 t; cvta.to.shared.u64 t, %1; cvt.u32.u64 %0, t; }" : "=r"(a) : "l"(p));
    return a;
}
__device__ __forceinline__ void cp16(uint32_t s, const void* g) {
    asm volatile("cp.async.cg.shared.global [%0], [%1], 16;" :: "r"(s), "l"(g));
}
#define CP_COMMIT() asm volatile("cp.async.commit_group;" ::: "memory")
#define CP_WAIT(n)  asm volatile("cp.async.wait_group %0;" :: "n"(n) : "memory")

__device__ __forceinline__ void ldm4(uint32_t* r, uint32_t addr) {
    asm volatile("ldmatrix.sync.aligned.m8n8.x4.shared.b16 {%0,%1,%2,%3}, [%4];"
        : "=r"(r[0]), "=r"(r[1]), "=r"(r[2]), "=r"(r[3]) : "r"(addr));
}
__device__ __forceinline__ void mma16816(float* c, const uint32_t* a, const uint32_t* b) {
    asm volatile("mma.sync.aligned.m16n8k16.row.col.f32.f16.f16.f32 "
        "{%0,%1,%2,%3}, {%4,%5,%6,%7}, {%8,%9}, {%0,%1,%2,%3};"
        : "+f"(c[0]), "+f"(c[1]), "+f"(c[2]), "+f"(c[3])
        : "r"(a[0]), "r"(a[1]), "r"(a[2]), "r"(a[3]), "r"(b[0]), "r"(b[1]));
}

// ===================== device scratch ======================================
__device__ float g_tmp[NTOK * 1024];
__device__ float g_xz [NTOK * 2048];   // [x_ssm | silu(gate)]
__device__ float g_dt [NTOK * 1024];
__device__ float g_bc [NTOK * 32];     // interleaved: (B_n, C_n) pairs
__device__ float g_y  [NTOK * 1024];

__device__ __half a_emb[NTOK*1024];
__device__ __half a_x  [NTOK*1024];
__device__ __half a_ssm[NTOK*1024];
__device__ __half a_det[NTOK*1024];
__device__ __half a_h1 [NTOK*2048];    // [pr1 hidden | po1 hidden]
__device__ __half a_h2 [NTOK*2048];    // after lnsilu

// Weights: single fp16, transposed [N,K]
__device__ __half wt_emb [1024*1024];
__device__ __half wt_in  [2048*1024];
__device__ __half wt_dtbc[1152*1024];  // dt rows 0-1023, B/C 1024-1055, zeros above
__device__ __half wt_pr1 [1024*1024];
__device__ __half wt_pr2 [1024*1024];
__device__ __half wt_po1 [1024*2048];  // [N=1024, K=2048]
__device__ __half wt_po2 [1024*1024];

// ===================== HMMA GEMM (single-pass fp16) ========================
// Tile 128(M)x128(N), 4 warps (warp tile 64x64), BK=32, 4 stages, 2 CTAs/SM.
// Prefetch for stage s+3 issued BEFORE compute(s): 3 loads in flight during
// compute. act: 0 none, 1 softplus, 2 silu on cols>=1024, 3 dt|bc split.
// Stage layout (80B-padded rows): A 128x80 @ +0, B 128x80 @ +10240.
#define STG_BYTES 20480
#define GEMM_SMEM (4*STG_BYTES + 512)

struct GemmArgs {
    const __half* A0; int K0;          // A cols [0,K0) from A0, rest from A1
    const __half* A1;
    int lda;
    const __half* B;
    const float* bias; int biasN;
    const float* addend; int ldadd;
    float* C; int ldc; int nvalid;
    __half* Chi; int ldhl;
    float* bc;                          // act==3 target for cols 1024-1055
    int K; int act;
};

__device__ __forceinline__ void gemm_impl(const GemmArgs a, char* smem)
{
    const uint32_t sb = smem_to_u32(smem);
    const int tid = threadIdx.x;
    const int lane = tid & 31, w = tid >> 5;
    const int bm = blockIdx.y * 128;
    const int bn = blockIdx.x * 128;
    const int wm = (w & 1) * 64;
    const int wn = (w >> 1) * 64;
    float* sbias = (float*)(smem + 4 * STG_BYTES);
    if (tid < 128) sbias[tid] = (a.bias && bn + tid < a.biasN) ? a.bias[bn + tid] : 0.f;

    const int nst = a.K >> 5;

    auto load_stage = [&](int s) {
        const uint32_t dst = sb + (uint32_t)(s & 3) * STG_BYTES;
        const int kglob = s << 5;
        #pragma unroll
        for (int j = 0; j < 8; j++) {
            int q = tid + (j << 7);
            int op = q >> 9;                 // 0:A 1:B
            int row = (q >> 2) & 127;
            int kc = q & 3;
            uint32_t d = dst + (uint32_t)op * 10240u + (uint32_t)(row * 80 + kc * 16);
            const __half* src;
            if (op == 0) {
                int col = kglob + kc * 8;
                const __half* base = a.A0;
                if (col >= a.K0) { base = a.A1; col -= a.K0; }
                src = base + (size_t)(bm + row) * a.lda + col;
            } else {
                src = a.B + (size_t)(bn + row) * a.K + kglob + kc * 8;
            }
            cp16(d, src);
        }
        CP_COMMIT();
    };

    load_stage(0); load_stage(1); load_stage(2);

    float acc[4][8][4] = {};

    for (int s = 0; s < nst; s++) {
        CP_WAIT(2);            // stage s resident (s+1, s+2 may be pending)
        __syncthreads();
        // issue prefetch for s+3 BEFORE compute: buffer (s+3)&3 == (s-1)&3,
        // whose readers (compute(s-1)) all finished before the barrier above.
        if (s + 3 < nst) load_stage(s + 3); else CP_COMMIT();
        const uint32_t sA = sb + (uint32_t)(s & 3) * STG_BYTES;
        #pragma unroll
        for (int kk = 0; kk < 2; kk++) {
            const int kloc = kk * 16;
            uint32_t ah[4][4], bb[4][4];
            #pragma unroll
            for (int mi = 0; mi < 4; mi++) {
                uint32_t ad = sA
                    + (uint32_t)((wm + mi * 16 + (lane & 15)) * 80)
                    + (uint32_t)((kloc + ((lane >> 4) << 3)) * 2);
                ldm4(ah[mi], ad);
            }
            #pragma unroll
            for (int nj = 0; nj < 4; nj++) {
                uint32_t bd = sA + 10240u
                    + (uint32_t)((wn + nj * 16 + ((lane >> 4) << 3) + (lane & 7)) * 80)
                    + (uint32_t)((kloc + ((lane >> 3) & 1) * 8) * 2);
                ldm4(bb[nj], bd);
            }
            #pragma unroll
            for (int mi = 0; mi < 4; mi++)
                #pragma unroll
                for (int ns = 0; ns < 8; ns++)
                    mma16816(acc[mi][ns], ah[mi], &bb[ns >> 1][(ns & 1) * 2]);
        }
    }

    // ---- epilogue ----
    const int g = lane >> 2, cc = (lane & 3) * 2;
    const bool dohl = (a.Chi != nullptr) && (bn < a.ldhl);
    #pragma unroll
    for (int mi = 0; mi < 4; mi++) {
        #pragma unroll
        for (int r = 0; r < 2; r++) {
            const int m = bm + wm + mi * 16 + g + r * 8;
            #pragma unroll
            for (int ns = 0; ns < 8; ns++) {
                const int ncol = wn + ns * 8 + cc;
                const int n = bn + ncol;
                float v0 = acc[mi][ns][r * 2 + 0] + sbias[ncol];
                float v1 = acc[mi][ns][r * 2 + 1] + sbias[ncol + 1];
                if (a.act == 3) {
                    if (n < 1024) {
                        v0 = fmaxf(v0, 0.f) + log1pf(__expf(-fabsf(v0)));
                        v1 = fmaxf(v1, 0.f) + log1pf(__expf(-fabsf(v1)));
                        *(float2*)(a.C + (size_t)m * a.ldc + n) = make_float2(v0, v1);
                    } else if (n < 1056) {
                        *(float2*)(a.bc + (size_t)m * 32 + (n - 1024)) = make_float2(v0, v1);
                    }
                    continue;
                }
                if (a.addend) {
                    float2 ad = *(const float2*)(a.addend + (size_t)m * a.ldadd + n);
                    v0 += ad.x; v1 += ad.y;
                }
                if (a.act == 1) {
                    v0 = fmaxf(v0, 0.f) + log1pf(__expf(-fabsf(v0)));
                    v1 = fmaxf(v1, 0.f) + log1pf(__expf(-fabsf(v1)));
                } else if (a.act == 2 && n >= 1024) {
                    v0 = v0 * (1.f / (1.f + __expf(-v0)));
                    v1 = v1 * (1.f / (1.f + __expf(-v1)));
                }
                if (a.C && n < a.nvalid)
                    *(float2*)(a.C + (size_t)m * a.ldc + n) = make_float2(v0, v1);
                if (dohl) {
                    *(__half2*)(a.Chi + (size_t)m * a.ldhl + n) =
                        __halves2half2(__float2half_rn(v0), __float2half_rn(v1));
                }
            }
        }
    }
}

__global__ __launch_bounds__(128, 2) void gemm_one(GemmArgs a) {
    extern __shared__ char smem[];
    gemm_impl(a, smem);
}
__global__ __launch_bounds__(128, 2) void gemm_dual(GemmArgs a0, GemmArgs a1) {
    extern __shared__ char smem[];
    gemm_impl(blockIdx.z ? a1 : a0, smem);
}

// ===================== batched weight transpose -> fp16 ====================
// Transposes a 1024(K) x 1024(N) block of W[.., srcN] into Wt[N, dstK]+koff.
struct WSeg { const float* W; __half* H; int srcN; int dstK; int koff; };
struct WSegs { WSeg s[9]; };
__global__ __launch_bounds__(256) void wconv_multi(WSegs ws)
{
    __shared__ float s[32][33];
    const WSeg seg = ws.s[blockIdx.z];
    const int tx = threadIdx.x, ty = threadIdx.y;
    const int n0 = blockIdx.x * 32, k0 = blockIdx.y * 32;
    #pragma unroll
    for (int j = 0; j < 4; j++)
        s[ty + j * 8][tx] = seg.W[(size_t)(k0 + ty + j * 8) * seg.srcN + n0 + tx];
    __syncthreads();
    #pragma unroll
    for (int j = 0; j < 4; j++) {
        float v = s[tx][ty + j * 8];
        size_t o = (size_t)(n0 + ty + j * 8) * seg.dstK + seg.koff + k0 + tx;
        seg.H[o] = __float2half_rn(v);
    }
}

// ===================== pack W_B|W_C interleaved into wt_dtbc rows 1024+ ====
__global__ __launch_bounds__(256) void bcconv_kernel(
    const float* __restrict__ WB, const float* __restrict__ WC,
    __half* __restrict__ H)
{
    int id = blockIdx.x * 256 + threadIdx.x;   // 32768 total
    int j = id & 31, k = id >> 5;
    float v = (j & 1) ? WC[k * 16 + (j >> 1)] : WB[k * 16 + (j >> 1)];
    H[(size_t)(1024 + j) * 1024 + k] = __float2half_rn(v);
}

// ===================== embeds: [B,T]->[T,B] gather + fp16 ==================
__global__ __launch_bounds__(256) void aconv_kernel(
    const float* __restrict__ X, __half* __restrict__ H)
{
    const int p = blockIdx.x;
    const int src = (p & 7) * NT + (p >> 3);
    const int c = threadIdx.x * 4;
    float4 v = *(const float4*)(X + (size_t)src * 1024 + c);
    ((__half2*)(H + (size_t)p * 1024 + c))[0] =
        __halves2half2(__float2half_rn(v.x), __float2half_rn(v.y));
    ((__half2*)(H + (size_t)p * 1024 + c))[1] =
        __halves2half2(__float2half_rn(v.z), __float2half_rn(v.w));
}

// ===================== stage 0: lnsilu(actions @ W_pre + b) -> fp32 ========
__global__ __launch_bounds__(256) void pre_kernel(
    const float* __restrict__ actions, const float* __restrict__ W_pre,
    const float* __restrict__ b_pre, const float* __restrict__ g_pre,
    const float* __restrict__ bb_pre, float* __restrict__ xout)
{
    int p = blockIdx.x;
    int t = p >> 3, b = p & 7;
    __shared__ float sa[32];
    __shared__ float red[2][8];
    int tid = threadIdx.x;
    if (tid < 32) sa[tid] = actions[(size_t)(b * NT + t) * 32 + tid];
    __syncthreads();
    int c0 = tid * 4;
    float4 acc = *(const float4*)(b_pre + c0);
    #pragma unroll 8
    for (int k = 0; k < 32; k++) {
        float aa = sa[k];
        float4 wv = *(const float4*)(W_pre + (size_t)k * 1024 + c0);
        acc.x = fmaf(aa, wv.x, acc.x); acc.y = fmaf(aa, wv.y, acc.y);
        acc.z = fmaf(aa, wv.z, acc.z); acc.w = fmaf(aa, wv.w, acc.w);
    }
    float s  = acc.x + acc.y + acc.z + acc.w;
    float s2 = acc.x*acc.x + acc.y*acc.y + acc.z*acc.z + acc.w*acc.w;
    #pragma unroll
    for (int o = 16; o; o >>= 1) {
        s  += __shfl_xor_sync(0xffffffffu, s, o);
        s2 += __shfl_xor_sync(0xffffffffu, s2, o);
    }
    if ((tid & 31) == 0) { red[0][tid >> 5] = s; red[1][tid >> 5] = s2; }
    __syncthreads();
    if (tid == 0) {
        float aa = 0.f, c = 0.f;
        for (int i = 0; i < 8; i++) { aa += red[0][i]; c += red[1][i]; }
        red[0][0] = aa; red[1][0] = c;
    }
    __syncthreads();
    float mean = red[0][0] * (1.f / 1024.f);
    float var  = red[1][0] * (1.f / 1024.f) - mean * mean;
    float inv  = rsqrtf(var + 1e-5f);
    float vv[4] = {acc.x, acc.y, acc.z, acc.w};
    #pragma unroll
    for (int j = 0; j < 4; j++) {
        int c = c0 + j;
        float xn = (vv[j] - mean) * inv * g_pre[c] + bb_pre[c];
        xn = xn * (1.f / (1.f + __expf(-xn)));
        xout[(size_t)p * 1024 + c] = xn;
    }
}

// ===================== LayerNorm fp32-in -> fp32 + fp16 ====================
__global__ __launch_bounds__(256) void ln_kernel(
    const float* __restrict__ X,
    const float* __restrict__ gma, const float* __restrict__ bta,
    float* __restrict__ Y, int ldy,
    __half* __restrict__ H, int dosilu)
{
    int p = blockIdx.x;
    int tid = threadIdx.x;
    int c0 = tid * 4;
    __shared__ float red[2][8];
    float4 v = *(const float4*)(X + (size_t)p * 1024 + c0);
    float s  = v.x + v.y + v.z + v.w;
    float s2 = v.x*v.x + v.y*v.y + v.z*v.z + v.w*v.w;
    #pragma unroll
    for (int o = 16; o; o >>= 1) {
        s  += __shfl_xor_sync(0xffffffffu, s, o);
        s2 += __shfl_xor_sync(0xffffffffu, s2, o);
    }
    if ((tid & 31) == 0) { red[0][tid >> 5] = s; red[1][tid >> 5] = s2; }
    __syncthreads();
    if (tid == 0) {
        float aa = 0.f, c = 0.f;
        for (int i = 0; i < 8; i++) { aa += red[0][i]; c += red[1][i]; }
        red[0][0] = aa; red[1][0] = c;
    }
    __syncthreads();
    float mean = red[0][0] * (1.f / 1024.f);
    float var  = red[1][0] * (1.f / 1024.f) - mean * mean;
    float inv  = rsqrtf(var + 1e-5f);
    float vv[4] = {v.x, v.y, v.z, v.w};
    float xn[4];
    #pragma unroll
    for (int j = 0; j < 4; j++) {
        int c = c0 + j;
        float x = (vv[j] - mean) * inv * gma[c] + bta[c];
        if (dosilu) x = x * (1.f / (1.f + __expf(-x)));
        xn[j] = x;
    }
    if (Y) {
        #pragma unroll
        for (int j = 0; j < 4; j++) Y[(size_t)p * ldy + c0 + j] = xn[j];
    }
    if (H) {
        ((__half2*)(H + (size_t)p * 1024 + c0))[0] =
            __halves2half2(__float2half_rn(xn[0]), __float2half_rn(xn[1]));
        ((__half2*)(H + (size_t)p * 1024 + c0))[1] =
            __halves2half2(__float2half_rn(xn[2]), __float2half_rn(xn[3]));
    }
}

// ===================== batched head LN: fp16 in/out, +silu =================
__global__ __launch_bounds__(256) void ln16_kernel(
    const __half* __restrict__ Xin,
    const float* __restrict__ g0, const float* __restrict__ b0,
    const float* __restrict__ g1, const float* __restrict__ b1,
    __half* __restrict__ Yout)
{
    int p = blockIdx.x;
    int tok = p & (NTOK - 1);
    int sel = p >> 12;
    const float* gma = sel ? g1 : g0;
    const float* bta = sel ? b1 : b0;
    size_t base = (size_t)tok * 2048 + sel * 1024;
    int tid = threadIdx.x;
    int c0 = tid * 4;
    __shared__ float red[2][8];
    __half2 h0 = ((const __half2*)(Xin + base + c0))[0];
    __half2 h1 = ((const __half2*)(Xin + base + c0))[1];
    float vv[4] = {__half2float(h0.x), __half2float(h0.y),
                   __half2float(h1.x), __half2float(h1.y)};
    float s = vv[0] + vv[1] + vv[2] + vv[3];
    float s2 = vv[0]*vv[0] + vv[1]*vv[1] + vv[2]*vv[2] + vv[3]*vv[3];
    #pragma unroll
    for (int o = 16; o; o >>= 1) {
        s  += __shfl_xor_sync(0xffffffffu, s, o);
        s2 += __shfl_xor_sync(0xffffffffu, s2, o);
    }
    if ((tid & 31) == 0) { red[0][tid >> 5] = s; red[1][tid >> 5] = s2; }
    __syncthreads();
    if (tid == 0) {
        float aa = 0.f, c = 0.f;
        for (int i = 0; i < 8; i++) { aa += red[0][i]; c += red[1][i]; }
        red[0][0] = aa; red[1][0] = c;
    }
    __syncthreads();
    float mean = red[0][0] * (1.f / 1024.f);
    float var  = red[1][0] * (1.f / 1024.f) - mean * mean;
    float inv  = rsqrtf(var + 1e-5f);
    float xn[4];
    #pragma unroll
    for (int j = 0; j < 4; j++) {
        int c = c0 + j;
        float x = (vv[j] - mean) * inv * gma[c] + bta[c];
        xn[j] = x * (1.f / (1.f + __expf(-x)));
    }
    ((__half2*)(Yout + base + c0))[0] =
        __halves2half2(__float2half_rn(xn[0]), __float2half_rn(xn[1]));
    ((__half2*)(Yout + base + c0))[1] =
        __halves2half2(__float2half_rn(xn[2]), __float2half_rn(xn[3]));
}

// ===================== SSM scan (gate pre-silu'd; bc interleaved) ==========
__global__ __launch_bounds__(256) void scan_kernel(
    const float* __restrict__ xz, const float* __restrict__ dt,
    const float* __restrict__ bc, const float* __restrict__ A_log,
    const float* __restrict__ Dp, float* __restrict__ y)
{
    int pair = blockIdx.x * 16 + (threadIdx.x >> 4);
    int n = threadIdx.x & 15;
    int b = pair >> 10;
    int d = pair & 1023;
    float A  = -__expf(A_log[d * 16 + n]);
    float Dd = Dp[d];
    float h = 0.f;
    #pragma unroll 2
    for (int t = 0; t < NT; t++) {
        int p = t * NB + b;
        float dtv = dt[(size_t)p * 1024 + d];
        float xs  = xz[(size_t)p * 2048 + d];
        float gate = 0.f;
        if (n == 0) gate = xz[(size_t)p * 2048 + 1024 + d];
        float2 bc2 = *(const float2*)(bc + (size_t)p * 32 + 2 * n);
        float g = __expf(dtv * A);
        h = fmaf(g, h, dtv * xs * bc2.x);
        float c = h * bc2.y;
        c += __shfl_xor_sync(0xffffffffu, c, 8, 16);
        c += __shfl_xor_sync(0xffffffffu, c, 4, 16);
        c += __shfl_xor_sync(0xffffffffu, c, 2, 16);
        c += __shfl_xor_sync(0xffffffffu, c, 1, 16);
        if (n == 0) {
            y[(size_t)p * 1024 + d] = (c + Dd * xs) * gate;
        }
    }
}

// ===================== softmax + unimix + log ==============================
__global__ __launch_bounds__(256) void softmax_kernel(
    const float* __restrict__ post, float* __restrict__ out)
{
    int idx  = blockIdx.x * 8 + (threadIdx.x >> 5);
    int lane = threadIdx.x & 31;
    int p = idx >> 5, s = idx & 31;
    float v = post[(size_t)p * 1024 + s * 32 + lane];
    float m = v;
    #pragma unroll
    for (int o = 16; o; o >>= 1) m = fmaxf(m, __shfl_xor_sync(0xffffffffu, m, o));
    float e = __expf(v - m);
    float sum = e;
    #pragma unroll
    for (int o = 16; o; o >>= 1) sum += __shfl_xor_sync(0xffffffffu, sum, o);
    float prob = e / sum;
    out[(size_t)p * 3072 + 2048 + s * 32 + lane] =
        logf(0.99f * prob + 0.01f / 32.f + 1e-8f);
}

// ===========================================================================
extern "C" void kernel_launch(void* const* d_in, const int* in_sizes, int n_in,
                              void* d_out, int out_size)
{
    const float* actions = (const float*)d_in[0];
    const float* embeds  = (const float*)d_in[1];
    const float* W_pre   = (const float*)d_in[2];
    const float* b_pre   = (const float*)d_in[3];
    const float* g_pre   = (const float*)d_in[4];
    const float* bb_pre  = (const float*)d_in[5];
    const float* W_emb   = (const float*)d_in[6];
    const float* W_in    = (const float*)d_in[7];
    const float* b_in    = (const float*)d_in[8];
    const float* W_dt    = (const float*)d_in[9];
    const float* b_dt    = (const float*)d_in[10];
    const float* W_B     = (const float*)d_in[11];
    const float* W_C     = (const float*)d_in[12];
    const float* A_log   = (const float*)d_in[13];
    const float* Dp      = (const float*)d_in[14];
    const float* g_out   = (const float*)d_in[15];
    const float* b_out   = (const float*)d_in[16];
    const float* W_pr1   = (const float*)d_in[17];
    const float* b_pr1   = (const float*)d_in[18];
    const float* g_pr    = (const float*)d_in[19];
    const float* bb_pr   = (const float*)d_in[20];
    const float* W_pr2   = (const float*)d_in[21];
    const float* b_pr2   = (const float*)d_in[22];
    const float* W_po1   = (const float*)d_in[23];
    const float* b_po1   = (const float*)d_in[24];
    const float* g_po    = (const float*)d_in[25];
    const float* bb_po   = (const float*)d_in[26];
    const float* W_po2   = (const float*)d_in[27];
    const float* b_po2   = (const float*)d_in[28];
    float* out = (float*)d_out;

    float *ptmp, *pxz, *pdt, *pbc, *py;
    cudaGetSymbolAddress((void**)&ptmp, g_tmp);
    cudaGetSymbolAddress((void**)&pxz,  g_xz);
    cudaGetSymbolAddress((void**)&pdt,  g_dt);
    cudaGetSymbolAddress((void**)&pbc,  g_bc);
    cudaGetSymbolAddress((void**)&py,   g_y);
    __half *pemb, *px, *pss, *pde, *ph1, *ph2;
    cudaGetSymbolAddress((void**)&pemb, a_emb);
    cudaGetSymbolAddress((void**)&px,  a_x);
    cudaGetSymbolAddress((void**)&pss, a_ssm);
    cudaGetSymbolAddress((void**)&pde, a_det);
    cudaGetSymbolAddress((void**)&ph1, a_h1);
    cudaGetSymbolAddress((void**)&ph2, a_h2);
    __half *wE, *wI, *wD, *wP1, *wP2, *wO1, *wO2;
    cudaGetSymbolAddress((void**)&wE, wt_emb);
    cudaGetSymbolAddress((void**)&wI, wt_in);
    cudaGetSymbolAddress((void**)&wD, wt_dtbc);
    cudaGetSymbolAddress((void**)&wP1, wt_pr1);
    cudaGetSymbolAddress((void**)&wP2, wt_pr2);
    cudaGetSymbolAddress((void**)&wO1, wt_po1);
    cudaGetSymbolAddress((void**)&wO2, wt_po2);

    cudaFuncSetAttribute(gemm_one,  cudaFuncAttributeMaxDynamicSharedMemorySize, GEMM_SMEM);
    cudaFuncSetAttribute(gemm_dual, cudaFuncAttributeMaxDynamicSharedMemorySize, GEMM_SMEM);

    const int BIG = 1 << 30;
    dim3 blk(256);
    dim3 gblk(128);
    dim3 wb(32, 8);

    // WSeg: {W, H, srcN, dstK, koff}; each segment converts a 1024x1024 block.
    WSegs ws;
    ws.s[0] = {W_emb,             wE,              1024, 1024, 0};
    ws.s[1] = {W_dt,              wD,              1024, 1024, 0};
    ws.s[2] = {W_pr1,             wP1,             1024, 1024, 0};
    ws.s[3] = {W_pr2,             wP2,             1024, 1024, 0};
    ws.s[4] = {W_po2,             wO2,             1024, 1024, 0};
    // W_in [K=1024, N=2048] -> Wt [2048, 1024]: split along N (rows of Wt)
    ws.s[5] = {W_in,              wI,              2048, 1024, 0};
    ws.s[6] = {W_in + 1024,       wI + 1024*1024,  2048, 1024, 0};
    // W_po1 [K=2048, N=1024] -> Wt [1024, 2048]: split along K (cols of Wt)
    ws.s[7] = {W_po1,             wO1,             1024, 2048, 0};
    ws.s[8] = {W_po1 + 1024*1024, wO1,             1024, 2048, 1024};

    // 0,1,2 then gemm at capture index 3
    aconv_kernel<<<NTOK, blk>>>(embeds, pemb);                              // 0
    pre_kernel<<<NTOK, blk>>>(actions, W_pre, b_pre, g_pre, bb_pre, ptmp);  // 1
    wconv_multi<<<dim3(32, 32, 9), wb>>>(ws);                               // 2

    // 3: x = emb @ W_emb + x_pre -> fp16
    GemmArgs ax = {pemb, 1024, pemb, 1024, wE, nullptr, 0,
                   ptmp, 1024, nullptr, 0, 0, px, 1024, nullptr, 1024, 0};
    gemm_one<<<dim3(8, 32), gblk, GEMM_SMEM>>>(ax);

    bcconv_kernel<<<128, blk>>>(W_B, W_C, wD);                              // 4

    // 5: xz = x @ W_in + b_in -> fp32 [x_ssm | silu(gate)] + fp16 x_ssm
    GemmArgs axz = {px, BIG, px, 1024, wI, b_in, 2048,
                    nullptr, 0, pxz, 2048, BIG, pss, 1024, nullptr, 1024, 2};
    gemm_one<<<dim3(16, 32), gblk, GEMM_SMEM>>>(axz);

    // 6: dt|bc = x_ssm @ [W_dt | W_B,W_C interleaved]  (N=1152)
    GemmArgs adt = {pss, BIG, pss, 1024, wD, b_dt, 1024,
                    nullptr, 0, pdt, 1024, 1024, nullptr, 0, pbc, 1024, 3};
    gemm_one<<<dim3(9, 32), gblk, GEMM_SMEM>>>(adt);

    // 7: scan
    scan_kernel<<<512, blk>>>(pxz, pdt, pbc, A_log, Dp, py);
    // 8: deter = LN(y) -> out[:,0:1024] + fp16
    ln_kernel<<<NTOK, blk>>>(py, g_out, b_out, out, 3072, pde, 0);

    // 9: dual pr1 / po1 -> a_h1 fp16 [4096,2048]
    GemmArgs ap1 = {pde, BIG, pde, 1024, wP1, b_pr1, 1024,
                    nullptr, 0, nullptr, 0, 0, ph1, 2048, nullptr, 1024, 0};
    GemmArgs ao1 = {pde, 1024, pemb, 1024, wO1, b_po1, 1024,
                    nullptr, 0, nullptr, 0, 0, ph1 + 1024, 2048, nullptr, 2048, 0};
    gemm_dual<<<dim3(8, 32, 2), gblk, GEMM_SMEM>>>(ap1, ao1);

    // 10: batched head lnsilu (fp16 in/out)
    ln16_kernel<<<2 * NTOK, blk>>>(ph1, g_pr, bb_pr, g_po, bb_po, ph2);

    // 11: dual pr2 -> out[:,1024:2048], po2 -> ptmp
    GemmArgs ap2 = {ph2, BIG, ph2, 2048, wP2, b_pr2, 1024,
                    nullptr, 0, out + 1024, 3072, BIG, nullptr, 0, nullptr, 1024, 0};
    GemmArgs ao2 = {ph2 + 1024, BIG, ph2 + 1024, 2048, wO2, b_po2, 1024,
                    nullptr, 0, ptmp, 1024, BIG, nullptr, 0, nullptr, 1024, 0};
    gemm_dual<<<dim3(8, 32, 2), gblk, GEMM_SMEM>>>(ap2, ao2);

    // 12: softmax -> out[:, 2048:3072]
    softmax_kernel<<<NTOK * 32 / 8, blk>>>(ptmp, out);
}